// round 6
// baseline (speedup 1.0000x reference)
#include <cuda_runtime.h>
#include <math.h>

#define BATCH 1024
#define TSTEPS 80
#define EDIM 100
#define UDIM 256
#define NG 1024       // 4 gates * U
#define VOCAB 10000
#define GRID_CTAS 128
#define NTHR 512

typedef unsigned long long u64;

// ---------------- persistent device scratch (no runtime allocation) ----------------
__device__ float g_W1h[UDIM * NG];                  // 256 x 1024 packed, n = u*4+g
__device__ float g_W1x[EDIM * NG];                  // 100 x 1024 packed
__device__ float g_W2 [2 * UDIM * NG];              // 512 x 1024 packed
__device__ float g_b1[NG];
__device__ float g_b2[NG];
__device__ float g_embW[(size_t)VOCAB * NG];        // 41 MB: emb @ W1x (per-vocab-word gates)
__device__ float g_h1[2][BATCH * UDIM];
__device__ float g_h2[2][BATCH * UDIM];
__device__ float g_c1[BATCH * UDIM];
__device__ float g_c2[BATCH * UDIM];
__device__ unsigned g_bar_count = 0;
__device__ volatile unsigned g_bar_gen = 0;

__device__ __forceinline__ float sigmoidf_(float x) { return 1.0f / (1.0f + expf(-x)); }

// packed f32x2 helpers (SASS FFMA2 path — only reachable via PTX fma.rn.f32x2)
__device__ __forceinline__ void ffma2(u64 &d, u64 a, u64 b) {
    asm("fma.rn.f32x2 %0, %1, %2, %0;" : "+l"(d) : "l"(a), "l"(b));
}
__device__ __forceinline__ u64 pack2(float lo, float hi) {
    u64 r; asm("mov.b64 %0, {%1, %2};" : "=l"(r) : "f"(lo), "f"(hi)); return r;
}
__device__ __forceinline__ u64 dup2(float v) {
    u64 r; asm("mov.b64 %0, {%1, %1};" : "=l"(r) : "f"(v)); return r;
}
__device__ __forceinline__ float lo32(u64 v) { return __uint_as_float((unsigned)v); }
__device__ __forceinline__ float hi32(u64 v) { return __uint_as_float((unsigned)(v >> 32)); }

// ---------------- software grid barrier (all GRID_CTAS co-resident) ----------------
__device__ __forceinline__ void grid_barrier() {
    __syncthreads();
    if (threadIdx.x == 0) {
        __threadfence();
        unsigned gen = g_bar_gen;
        if (atomicAdd(&g_bar_count, 1u) == GRID_CTAS - 1) {
            g_bar_count = 0;
            __threadfence();
            g_bar_gen = gen + 1;
        } else {
            while (g_bar_gen == gen) { }
            __threadfence();
        }
    }
    __syncthreads();
}

// ---------------- weight repack: n = u*4 + g, g in {f,i,c,o} ----------------
__global__ void pack_kernel(
    const float* wf1, const float* bf1, const float* wi1, const float* bi1,
    const float* wc1, const float* bc1, const float* wo1, const float* bo1,
    const float* wf2, const float* bf2, const float* wi2, const float* bi2,
    const float* wc2, const float* bc2, const float* wo2, const float* bo2)
{
    const int TOT_W = (UDIM + EDIM + 2 * UDIM) * NG;
    int id = blockIdx.x * blockDim.x + threadIdx.x;
    if (id < TOT_W) {
        int kk = id >> 10;
        int n  = id & 1023;
        int u  = n >> 2;
        int g  = n & 3;
        if (kk < UDIM) {
            const float* w = (g == 0) ? wf1 : (g == 1) ? wi1 : (g == 2) ? wc1 : wo1;
            g_W1h[kk * NG + n] = w[kk * UDIM + u];
        } else if (kk < UDIM + EDIM) {
            const float* w = (g == 0) ? wf1 : (g == 1) ? wi1 : (g == 2) ? wc1 : wo1;
            g_W1x[(kk - UDIM) * NG + n] = w[kk * UDIM + u];
        } else {
            int k2 = kk - (UDIM + EDIM);
            const float* w = (g == 0) ? wf2 : (g == 1) ? wi2 : (g == 2) ? wc2 : wo2;
            g_W2[k2 * NG + n] = w[k2 * UDIM + u];
        }
    } else if (id < TOT_W + 2 * NG) {
        int j = id - TOT_W;
        int n = j & 1023;
        int u = n >> 2;
        int g = n & 3;
        if (j < NG) g_b1[n] = ((g == 0) ? bf1 : (g == 1) ? bi1 : (g == 2) ? bc1 : bo1)[u];
        else        g_b2[n] = ((g == 0) ? bf2 : (g == 1) ? bi2 : (g == 2) ? bc2 : bo2)[u];
    }
}

__global__ void zero_kernel()
{
    int id = blockIdx.x * blockDim.x + threadIdx.x;
    if (id < BATCH * UDIM) {
        g_h1[0][id] = 0.0f;
        g_h2[0][id] = 0.0f;
        g_c1[id]    = 0.0f;
        g_c2[id]    = 0.0f;
    }
}

// ---------------- embW = emb @ W1x  (M=10000, N=1024, K=100 pad 128) ----------------
__global__ __launch_bounds__(256) void embw_kernel(const float* __restrict__ emb)
{
    __shared__ __align__(16) float As[32][64];
    __shared__ __align__(16) float Bs[32][64];

    const int tid = threadIdx.x;
    const int m0  = blockIdx.y * 64;
    const int n0  = blockIdx.x * 64;
    const int tm  = tid >> 4;
    const int tn  = tid & 15;

    float acc[4][4] = {};

    for (int k0 = 0; k0 < 128; k0 += 32) {
        #pragma unroll
        for (int i = 0; i < 2; i++) {
            int f4 = tid + i * 256;
            int m  = f4 >> 3;
            int kq = f4 & 7;
            int k  = k0 + kq * 4;
            float4 v = make_float4(0.f, 0.f, 0.f, 0.f);
            int row = m0 + m;
            if (k < EDIM && row < VOCAB)
                v = *(const float4*)&emb[(size_t)row * EDIM + k];
            As[kq * 4 + 0][m] = v.x;
            As[kq * 4 + 1][m] = v.y;
            As[kq * 4 + 2][m] = v.z;
            As[kq * 4 + 3][m] = v.w;
        }
        #pragma unroll
        for (int i = 0; i < 2; i++) {
            int f4 = tid + i * 256;
            int kk = f4 >> 4;
            int c4 = f4 & 15;
            int k  = k0 + kk;
            float4 v = make_float4(0.f, 0.f, 0.f, 0.f);
            if (k < EDIM) v = *(const float4*)&g_W1x[k * NG + n0 + c4 * 4];
            *(float4*)&Bs[kk][c4 * 4] = v;
        }
        __syncthreads();

        #pragma unroll
        for (int k = 0; k < 32; k++) {
            float4 b = *(const float4*)&Bs[k][tn * 4];
            float4 a = *(const float4*)&As[k][tm * 4];
            float ar[4] = {a.x, a.y, a.z, a.w};
            float br[4] = {b.x, b.y, b.z, b.w};
            #pragma unroll
            for (int r = 0; r < 4; r++)
                #pragma unroll
                for (int c = 0; c < 4; c++)
                    acc[r][c] += ar[r] * br[c];
        }
        __syncthreads();
    }

    #pragma unroll
    for (int r = 0; r < 4; r++) {
        int row = m0 + tm * 4 + r;
        if (row < VOCAB)
            *(float4*)&g_embW[(size_t)row * NG + n0 + tn * 4] =
                make_float4(acc[r][0], acc[r][1], acc[r][2], acc[r][3]);
    }
}

// ---------------- one layer phase: 128x64 tile GEMM (f32x2) + fused LSTM epilogue ----------------
template <bool LAYER2>
__device__ __forceinline__ void phase(int t, int p, int m0, int n0, int tm, int tn,
                                      float (*As)[128], float (*Bs)[64],
                                      const int* __restrict__ tokens)
{
    const int tid = threadIdx.x;
    constexpr int K = LAYER2 ? 2 * UDIM : UDIM;
    const float* __restrict__ W = LAYER2 ? g_W2 : g_W1h;

    u64 acc[2][4];
    #pragma unroll
    for (int r = 0; r < 2; r++)
        #pragma unroll
        for (int c = 0; c < 4; c++) acc[r][c] = 0ull;

    for (int k0 = 0; k0 < K; k0 += 32) {
        // A tile: 128 rows x 32 k of hidden state (4096 floats / 512 thr = 2 float4 each)
        #pragma unroll
        for (int i = 0; i < 2; i++) {
            int f4 = tid + i * NTHR;         // 0..1023
            int m  = f4 >> 3;                // 0..127
            int kq = f4 & 7;
            int k  = k0 + kq * 4;
            const float* src;
            if (!LAYER2) {
                src = &g_h1[p][(m0 + m) * UDIM + k];
            } else {
                src = (k < UDIM) ? &g_h2[p][(m0 + m) * UDIM + k]
                                 : &g_h1[1 - p][(m0 + m) * UDIM + (k - UDIM)];
            }
            float4 v = *(const float4*)src;
            As[kq * 4 + 0][m] = v.x;
            As[kq * 4 + 1][m] = v.y;
            As[kq * 4 + 2][m] = v.z;
            As[kq * 4 + 3][m] = v.w;
        }
        // B tile: 32 k x 64 n (2048 floats / 512 thr = 1 float4 each)
        {
            int kk = tid >> 4;               // 0..31
            int c4 = tid & 15;               // 0..15
            *(float4*)&Bs[kk][c4 * 4] = *(const float4*)&W[(k0 + kk) * NG + n0 + c4 * 4];
        }
        __syncthreads();

        #pragma unroll
        for (int k = 0; k < 32; k++) {
            float4 Af = *(const float4*)&As[k][tm * 4];
            float4 Bf = *(const float4*)&Bs[k][tn * 4];
            u64 a0 = pack2(Af.x, Af.y);
            u64 a1 = pack2(Af.z, Af.w);
            u64 b0 = dup2(Bf.x), b1 = dup2(Bf.y), b2 = dup2(Bf.z), b3 = dup2(Bf.w);
            ffma2(acc[0][0], a0, b0); ffma2(acc[0][1], a0, b1);
            ffma2(acc[0][2], a0, b2); ffma2(acc[0][3], a0, b3);
            ffma2(acc[1][0], a1, b0); ffma2(acc[1][1], a1, b1);
            ffma2(acc[1][2], a1, b2); ffma2(acc[1][3], a1, b3);
        }
        __syncthreads();
    }

    // fused LSTM epilogue: this thread owns 4 batch rows x unit u
    const float* __restrict__ bias = LAYER2 ? g_b2 : g_b1;
    float* __restrict__ cs   = LAYER2 ? g_c2 : g_c1;
    float* __restrict__ hout = LAYER2 ? g_h2[1 - p] : g_h1[1 - p];

    const int n = n0 + tn * 4;
    const int u = n >> 2;
    float4 bv = *(const float4*)&bias[n];

    #pragma unroll
    for (int r = 0; r < 4; r++) {
        int bb = m0 + tm * 4 + r;
        int rp = r >> 1;
        float pf = ((r & 1) ? hi32(acc[rp][0]) : lo32(acc[rp][0])) + bv.x;
        float pi = ((r & 1) ? hi32(acc[rp][1]) : lo32(acc[rp][1])) + bv.y;
        float pc = ((r & 1) ? hi32(acc[rp][2]) : lo32(acc[rp][2])) + bv.z;
        float po = ((r & 1) ? hi32(acc[rp][3]) : lo32(acc[rp][3])) + bv.w;
        if (!LAYER2) {
            int row = tokens[bb * TSTEPS + t];
            float4 x = *(const float4*)&g_embW[(size_t)row * NG + n];
            pf += x.x; pi += x.y; pc += x.z; po += x.w;
        }
        float gf = sigmoidf_(pf);
        float gi = sigmoidf_(pi);
        float ct = tanhf(pc);
        float go = sigmoidf_(po);
        float c  = cs[bb * UDIM + u];
        c = gf * c + gi * ct;
        cs[bb * UDIM + u] = c;
        hout[bb * UDIM + u] = go * tanhf(c);
    }
}

// ---------------- persistent all-timesteps kernel ----------------
__global__ __launch_bounds__(NTHR, 1) void lstm_persistent(
    const int* __restrict__ tokens,
    const float* __restrict__ w_out, const float* __restrict__ b_out,
    float* __restrict__ out)
{
    __shared__ __align__(16) float As[32][128];
    __shared__ __align__(16) float Bs[32][64];

    const int cta = blockIdx.x;
    const int n0  = (cta & 15) * 64;
    const int m0  = (cta >> 4) * 128;
    const int tm  = threadIdx.x >> 4;    // 0..31
    const int tn  = threadIdx.x & 15;    // 0..15

    for (int t = 0; t < TSTEPS; t++) {
        int p = t & 1;
        phase<false>(t, p, m0, n0, tm, tn, As, Bs, tokens);
        grid_barrier();
        phase<true >(t, p, m0, n0, tm, tn, As, Bs, tokens);
        grid_barrier();
    }

    // final dense + sigmoid: 8 batches per CTA (warps 0-7)
    int warp = threadIdx.x >> 5;
    int lane = threadIdx.x & 31;
    if (warp < 8) {
        int bb = cta * 8 + warp;
        const float* h = g_h2[0];        // t=79 (p=1) wrote buffer 0
        float s = 0.0f;
        #pragma unroll
        for (int i = 0; i < 8; i++)
            s += h[bb * UDIM + lane + i * 32] * w_out[lane + i * 32];
        #pragma unroll
        for (int o = 16; o; o >>= 1) s += __shfl_xor_sync(0xFFFFFFFFu, s, o);
        if (lane == 0) out[bb] = sigmoidf_(s + b_out[0]);
    }
}

// ---------------- launch ----------------
extern "C" void kernel_launch(void* const* d_in, const int* in_sizes, int n_in,
                              void* d_out, int out_size)
{
    const int*   tokens = (const int*)  d_in[0];
    const float* emb    = (const float*)d_in[1];
    const float* wf1 = (const float*)d_in[2];  const float* bf1 = (const float*)d_in[3];
    const float* wi1 = (const float*)d_in[4];  const float* bi1 = (const float*)d_in[5];
    const float* wc1 = (const float*)d_in[6];  const float* bc1 = (const float*)d_in[7];
    const float* wo1 = (const float*)d_in[8];  const float* bo1 = (const float*)d_in[9];
    const float* wf2 = (const float*)d_in[10]; const float* bf2 = (const float*)d_in[11];
    const float* wi2 = (const float*)d_in[12]; const float* bi2 = (const float*)d_in[13];
    const float* wc2 = (const float*)d_in[14]; const float* bc2 = (const float*)d_in[15];
    const float* wo2 = (const float*)d_in[16]; const float* bo2 = (const float*)d_in[17];
    const float* w_out = (const float*)d_in[18];
    const float* b_out = (const float*)d_in[19];
    float* out = (float*)d_out;

    const int TOT = (UDIM + EDIM + 2 * UDIM) * NG + 2 * NG;
    pack_kernel<<<(TOT + 255) / 256, 256>>>(wf1, bf1, wi1, bi1, wc1, bc1, wo1, bo1,
                                            wf2, bf2, wi2, bi2, wc2, bc2, wo2, bo2);
    zero_kernel<<<(BATCH * UDIM + 255) / 256, 256>>>();

    // embW = emb @ W1x  (V=10000 rows -> replaces the 81920-row xg GEMM)
    embw_kernel<<<dim3(NG / 64, (VOCAB + 63) / 64), 256>>>(emb);

    lstm_persistent<<<GRID_CTAS, NTHR>>>(tokens, w_out, b_out, out);
}

// round 7
// speedup vs baseline: 1.2185x; 1.2185x over previous
#include <cuda_runtime.h>
#include <math.h>
#include <stdint.h>

#define BATCH 1024
#define TSTEPS 80
#define EDIM 100
#define UDIM 256
#define NG 1024       // 4 gates * U
#define VOCAB 10000
#define GRID_CTAS 128
#define NTHR 128
#define KC 32

typedef unsigned long long u64;

// ---------------- persistent device scratch ----------------
__device__ float g_W1h[UDIM * NG];                  // [k][n], n = u*4+g
__device__ float g_W1x[EDIM * NG];
__device__ float g_W2 [2 * UDIM * NG];
__device__ float g_b1[NG];
__device__ float g_b2[NG];
__device__ float g_embW[(size_t)VOCAB * NG];        // emb @ W1x, [vocab][n]
// hidden/cell states TRANSPOSED: [unit][batch]
__device__ float g_h1[2][UDIM * BATCH];
__device__ float g_h2[2][UDIM * BATCH];
__device__ float g_c1[UDIM * BATCH];
__device__ float g_c2[UDIM * BATCH];
__device__ unsigned g_bar_count = 0;
__device__ volatile unsigned g_bar_gen = 0;

__device__ __forceinline__ float sigmoidf_(float x) { return 1.0f / (1.0f + expf(-x)); }

// packed f32x2 (SASS FFMA2)
__device__ __forceinline__ void ffma2(u64 &d, u64 a, u64 b) {
    asm("fma.rn.f32x2 %0, %1, %2, %0;" : "+l"(d) : "l"(a), "l"(b));
}
__device__ __forceinline__ u64 dup2(float v) {
    u64 r; asm("mov.b64 %0, {%1, %1};" : "=l"(r) : "f"(v)); return r;
}
__device__ __forceinline__ float lo32(u64 v) { return __uint_as_float((unsigned)v); }
__device__ __forceinline__ float hi32(u64 v) { return __uint_as_float((unsigned)(v >> 32)); }

__device__ __forceinline__ uint32_t smem_u32(const void* p) {
    uint32_t a;
    asm("{ .reg .u64 t; cvta.to.shared.u64 t, %1; cvt.u32.u64 %0, t; }" : "=r"(a) : "l"(p));
    return a;
}
__device__ __forceinline__ void cp16(uint32_t dst, const void* src) {
    asm volatile("cp.async.cg.shared.global [%0], [%1], 16;" :: "r"(dst), "l"(src));
}
__device__ __forceinline__ void cp_commit() { asm volatile("cp.async.commit_group;"); }
__device__ __forceinline__ void cp_wait1()  { asm volatile("cp.async.wait_group 1;"); }
__device__ __forceinline__ void cp_wait0()  { asm volatile("cp.async.wait_group 0;"); }

// ---------------- software grid barrier ----------------
__device__ __forceinline__ void grid_barrier() {
    __syncthreads();
    if (threadIdx.x == 0) {
        __threadfence();
        unsigned gen = g_bar_gen;
        if (atomicAdd(&g_bar_count, 1u) == GRID_CTAS - 1) {
            g_bar_count = 0;
            __threadfence();
            g_bar_gen = gen + 1;
        } else {
            while (g_bar_gen == gen) { }
            __threadfence();
        }
    }
    __syncthreads();
}

// ---------------- weight repack: n = u*4 + g ----------------
__global__ void pack_kernel(
    const float* wf1, const float* bf1, const float* wi1, const float* bi1,
    const float* wc1, const float* bc1, const float* wo1, const float* bo1,
    const float* wf2, const float* bf2, const float* wi2, const float* bi2,
    const float* wc2, const float* bc2, const float* wo2, const float* bo2)
{
    const int TOT_W = (UDIM + EDIM + 2 * UDIM) * NG;
    int id = blockIdx.x * blockDim.x + threadIdx.x;
    if (id < TOT_W) {
        int kk = id >> 10;
        int n  = id & 1023;
        int u  = n >> 2;
        int g  = n & 3;
        if (kk < UDIM) {
            const float* w = (g == 0) ? wf1 : (g == 1) ? wi1 : (g == 2) ? wc1 : wo1;
            g_W1h[kk * NG + n] = w[kk * UDIM + u];
        } else if (kk < UDIM + EDIM) {
            const float* w = (g == 0) ? wf1 : (g == 1) ? wi1 : (g == 2) ? wc1 : wo1;
            g_W1x[(kk - UDIM) * NG + n] = w[kk * UDIM + u];
        } else {
            int k2 = kk - (UDIM + EDIM);
            const float* w = (g == 0) ? wf2 : (g == 1) ? wi2 : (g == 2) ? wc2 : wo2;
            g_W2[k2 * NG + n] = w[k2 * UDIM + u];
        }
    } else if (id < TOT_W + 2 * NG) {
        int j = id - TOT_W;
        int n = j & 1023;
        int u = n >> 2;
        int g = n & 3;
        if (j < NG) g_b1[n] = ((g == 0) ? bf1 : (g == 1) ? bi1 : (g == 2) ? bc1 : bo1)[u];
        else        g_b2[n] = ((g == 0) ? bf2 : (g == 1) ? bi2 : (g == 2) ? bc2 : bo2)[u];
    }
}

__global__ void zero_kernel()
{
    int id = blockIdx.x * blockDim.x + threadIdx.x;
    if (id < UDIM * BATCH) {
        g_h1[0][id] = 0.0f;
        g_h2[0][id] = 0.0f;
        g_c1[id]    = 0.0f;
        g_c2[id]    = 0.0f;
    }
}

// ---------------- embW = emb @ W1x  (M=10000, N=1024, K=100 pad 128) ----------------
__global__ __launch_bounds__(256) void embw_kernel(const float* __restrict__ emb)
{
    __shared__ __align__(16) float As[32][64];
    __shared__ __align__(16) float Bs[32][64];

    const int tid = threadIdx.x;
    const int m0  = blockIdx.y * 64;
    const int n0  = blockIdx.x * 64;
    const int tm  = tid >> 4;
    const int tn  = tid & 15;

    float acc[4][4] = {};

    for (int k0 = 0; k0 < 128; k0 += 32) {
        #pragma unroll
        for (int i = 0; i < 2; i++) {
            int f4 = tid + i * 256;
            int m  = f4 >> 3;
            int kq = f4 & 7;
            int k  = k0 + kq * 4;
            float4 v = make_float4(0.f, 0.f, 0.f, 0.f);
            int row = m0 + m;
            if (k < EDIM && row < VOCAB)
                v = *(const float4*)&emb[(size_t)row * EDIM + k];
            As[kq * 4 + 0][m] = v.x;
            As[kq * 4 + 1][m] = v.y;
            As[kq * 4 + 2][m] = v.z;
            As[kq * 4 + 3][m] = v.w;
        }
        #pragma unroll
        for (int i = 0; i < 2; i++) {
            int f4 = tid + i * 256;
            int kk = f4 >> 4;
            int c4 = f4 & 15;
            int k  = k0 + kk;
            float4 v = make_float4(0.f, 0.f, 0.f, 0.f);
            if (k < EDIM) v = *(const float4*)&g_W1x[k * NG + n0 + c4 * 4];
            *(float4*)&Bs[kk][c4 * 4] = v;
        }
        __syncthreads();

        #pragma unroll
        for (int k = 0; k < 32; k++) {
            float4 b = *(const float4*)&Bs[k][tn * 4];
            float4 a = *(const float4*)&As[k][tm * 4];
            float ar[4] = {a.x, a.y, a.z, a.w};
            float br[4] = {b.x, b.y, b.z, b.w};
            #pragma unroll
            for (int r = 0; r < 4; r++)
                #pragma unroll
                for (int c = 0; c < 4; c++)
                    acc[r][c] += ar[r] * br[c];
        }
        __syncthreads();
    }

    #pragma unroll
    for (int r = 0; r < 4; r++) {
        int row = m0 + tm * 4 + r;
        if (row < VOCAB)
            *(float4*)&g_embW[(size_t)row * NG + n0 + tn * 4] =
                make_float4(acc[r][0], acc[r][1], acc[r][2], acc[r][3]);
    }
}

// ---------------- persistent kernel ----------------
// Tile: 64 M (batch) x 128 N (gates). 128 threads, micro 8x8.
// Shared buffers (double): As[2][32][64] (8KB ea), Bs[2][32][128] (16KB ea) = 48KB exactly.

struct SmemT {
    float As[2][KC][64];
    float Bs[2][KC][128];
};

template <bool L2P>
__device__ __forceinline__ void stage_chunk(SmemT* sm, int k0, int buf, int p,
                                            int m0, int n0, int tid)
{
    // A: 32k x 64m = 2048 floats / 128 thr = 4 float4 each (row copies, transposed h)
    #pragma unroll
    for (int i = 0; i < 4; i++) {
        int f4 = tid + i * NTHR;       // 0..511
        int kq = f4 >> 4;              // 0..31
        int c4 = f4 & 15;              // 0..15
        int k  = k0 + kq;
        const float* src;
        if (!L2P) {
            src = &g_h1[p][k * BATCH + m0 + c4 * 4];
        } else {
            src = (k < UDIM) ? &g_h2[p][k * BATCH + m0 + c4 * 4]
                             : &g_h1[1 - p][(k - UDIM) * BATCH + m0 + c4 * 4];
        }
        cp16(smem_u32(&sm->As[buf][kq][c4 * 4]), src);
    }
    // B: 32k x 128n = 4096 floats / 128 thr = 8 float4 each
    const float* __restrict__ W = L2P ? g_W2 : g_W1h;
    #pragma unroll
    for (int i = 0; i < 8; i++) {
        int f4 = tid + i * NTHR;       // 0..1023
        int kk = f4 >> 5;              // 0..31
        int c4 = f4 & 31;              // 0..31
        cp16(smem_u32(&sm->Bs[buf][kk][c4 * 4]), &W[(k0 + kk) * NG + n0 + c4 * 4]);
    }
}

template <bool L2P>
__device__ __forceinline__ void phase(SmemT* sm, int t, int p, int m0, int n0,
                                      int tm, int tn, const int* __restrict__ tokens)
{
    const int tid = threadIdx.x;
    constexpr int K = L2P ? 2 * UDIM : UDIM;
    constexpr int C = K / KC;

    u64 acc[8][4];
    #pragma unroll
    for (int r = 0; r < 8; r++)
        #pragma unroll
        for (int c = 0; c < 4; c++) acc[r][c] = 0ull;

    stage_chunk<L2P>(sm, 0, 0, p, m0, n0, tid);
    cp_commit();

    for (int c = 0; c < C; c++) {
        int cur = c & 1;
        if (c + 1 < C) {
            stage_chunk<L2P>(sm, (c + 1) * KC, 1 - cur, p, m0, n0, tid);
            cp_commit();
            cp_wait1();
        } else {
            cp_wait0();
        }
        __syncthreads();

        #pragma unroll 8
        for (int k = 0; k < KC; k++) {
            float4 a0 = *(const float4*)&sm->As[cur][k][tm * 8];
            float4 a1 = *(const float4*)&sm->As[cur][k][tm * 8 + 4];
            ulonglong2 b0 = *(const ulonglong2*)&sm->Bs[cur][k][tn * 8];
            ulonglong2 b1 = *(const ulonglong2*)&sm->Bs[cur][k][tn * 8 + 4];
            u64 ad[8];
            ad[0] = dup2(a0.x); ad[1] = dup2(a0.y); ad[2] = dup2(a0.z); ad[3] = dup2(a0.w);
            ad[4] = dup2(a1.x); ad[5] = dup2(a1.y); ad[6] = dup2(a1.z); ad[7] = dup2(a1.w);
            #pragma unroll
            for (int r = 0; r < 8; r++) {
                ffma2(acc[r][0], ad[r], b0.x);
                ffma2(acc[r][1], ad[r], b0.y);
                ffma2(acc[r][2], ad[r], b1.x);
                ffma2(acc[r][3], ad[r], b1.y);
            }
        }
        __syncthreads();
    }

    // ---- fused LSTM epilogue: thread owns 8 batch rows x 2 units ----
    const float* __restrict__ bias = L2P ? g_b2 : g_b1;
    float* __restrict__ cs   = L2P ? g_c2 : g_c1;
    float* __restrict__ hout = L2P ? g_h2[1 - p] : g_h1[1 - p];

    const int n   = n0 + tn * 8;
    const int u0  = n >> 2;           // units u0, u0+1
    const int bb0 = m0 + tm * 8;

    float4 bv0 = *(const float4*)&bias[n];
    float4 bv1 = *(const float4*)&bias[n + 4];

    float c0[8], c1[8], h0v[8], h1v[8];
    *(float4*)&c0[0] = *(const float4*)&cs[(size_t)u0 * BATCH + bb0];
    *(float4*)&c0[4] = *(const float4*)&cs[(size_t)u0 * BATCH + bb0 + 4];
    *(float4*)&c1[0] = *(const float4*)&cs[(size_t)(u0 + 1) * BATCH + bb0];
    *(float4*)&c1[4] = *(const float4*)&cs[(size_t)(u0 + 1) * BATCH + bb0 + 4];

    #pragma unroll
    for (int r = 0; r < 8; r++) {
        float pf0 = lo32(acc[r][0]) + bv0.x;
        float pi0 = hi32(acc[r][0]) + bv0.y;
        float pc0 = lo32(acc[r][1]) + bv0.z;
        float po0 = hi32(acc[r][1]) + bv0.w;
        float pf1 = lo32(acc[r][2]) + bv1.x;
        float pi1 = hi32(acc[r][2]) + bv1.y;
        float pc1 = lo32(acc[r][3]) + bv1.z;
        float po1 = hi32(acc[r][3]) + bv1.w;
        if (!L2P) {
            int row = tokens[(bb0 + r) * TSTEPS + t];
            float4 x0 = *(const float4*)&g_embW[(size_t)row * NG + n];
            float4 x1 = *(const float4*)&g_embW[(size_t)row * NG + n + 4];
            pf0 += x0.x; pi0 += x0.y; pc0 += x0.z; po0 += x0.w;
            pf1 += x1.x; pi1 += x1.y; pc1 += x1.z; po1 += x1.w;
        }
        float cc0 = sigmoidf_(pf0) * c0[r] + sigmoidf_(pi0) * tanhf(pc0);
        float cc1 = sigmoidf_(pf1) * c1[r] + sigmoidf_(pi1) * tanhf(pc1);
        c0[r] = cc0;
        c1[r] = cc1;
        h0v[r] = sigmoidf_(po0) * tanhf(cc0);
        h1v[r] = sigmoidf_(po1) * tanhf(cc1);
    }

    *(float4*)&cs[(size_t)u0 * BATCH + bb0]           = *(const float4*)&c0[0];
    *(float4*)&cs[(size_t)u0 * BATCH + bb0 + 4]       = *(const float4*)&c0[4];
    *(float4*)&cs[(size_t)(u0 + 1) * BATCH + bb0]     = *(const float4*)&c1[0];
    *(float4*)&cs[(size_t)(u0 + 1) * BATCH + bb0 + 4] = *(const float4*)&c1[4];
    *(float4*)&hout[(size_t)u0 * BATCH + bb0]           = *(const float4*)&h0v[0];
    *(float4*)&hout[(size_t)u0 * BATCH + bb0 + 4]       = *(const float4*)&h0v[4];
    *(float4*)&hout[(size_t)(u0 + 1) * BATCH + bb0]     = *(const float4*)&h1v[0];
    *(float4*)&hout[(size_t)(u0 + 1) * BATCH + bb0 + 4] = *(const float4*)&h1v[4];
}

__global__ __launch_bounds__(NTHR, 1) void lstm_persistent(
    const int* __restrict__ tokens,
    const float* __restrict__ w_out, const float* __restrict__ b_out,
    float* __restrict__ out)
{
    __shared__ __align__(16) SmemT sm;

    const int cta = blockIdx.x;
    const int n0  = (cta & 7) * 128;     // 8 n-tiles
    const int m0  = (cta >> 3) * 64;     // 16 m-tiles
    const int tm  = threadIdx.x >> 4;    // 0..7
    const int tn  = threadIdx.x & 15;    // 0..15

    for (int t = 0; t < TSTEPS; t++) {
        int p = t & 1;
        phase<false>(&sm, t, p, m0, n0, tm, tn, tokens);
        grid_barrier();
        phase<true >(&sm, t, p, m0, n0, tm, tn, tokens);
        grid_barrier();
    }

    // final dense + sigmoid (h2 final is in buffer 0, transposed [u][b])
    int gw   = cta * (NTHR / 32) + (threadIdx.x >> 5);  // global warp id, 0..511
    int lane = threadIdx.x & 31;
    if (gw < BATCH / 32) {
        int bb = gw * 32 + lane;
        float s = 0.0f;
        const float* h = g_h2[0];
        #pragma unroll 8
        for (int u = 0; u < UDIM; u++)
            s += h[(size_t)u * BATCH + bb] * w_out[u];
        out[bb] = sigmoidf_(s + b_out[0]);
    }
}

// ---------------- launch ----------------
extern "C" void kernel_launch(void* const* d_in, const int* in_sizes, int n_in,
                              void* d_out, int out_size)
{
    const int*   tokens = (const int*)  d_in[0];
    const float* emb    = (const float*)d_in[1];
    const float* wf1 = (const float*)d_in[2];  const float* bf1 = (const float*)d_in[3];
    const float* wi1 = (const float*)d_in[4];  const float* bi1 = (const float*)d_in[5];
    const float* wc1 = (const float*)d_in[6];  const float* bc1 = (const float*)d_in[7];
    const float* wo1 = (const float*)d_in[8];  const float* bo1 = (const float*)d_in[9];
    const float* wf2 = (const float*)d_in[10]; const float* bf2 = (const float*)d_in[11];
    const float* wi2 = (const float*)d_in[12]; const float* bi2 = (const float*)d_in[13];
    const float* wc2 = (const float*)d_in[14]; const float* bc2 = (const float*)d_in[15];
    const float* wo2 = (const float*)d_in[16]; const float* bo2 = (const float*)d_in[17];
    const float* w_out = (const float*)d_in[18];
    const float* b_out = (const float*)d_in[19];
    float* out = (float*)d_out;

    const int TOT = (UDIM + EDIM + 2 * UDIM) * NG + 2 * NG;
    pack_kernel<<<(TOT + 255) / 256, 256>>>(wf1, bf1, wi1, bi1, wc1, bc1, wo1, bo1,
                                            wf2, bf2, wi2, bi2, wc2, bc2, wo2, bo2);
    zero_kernel<<<(UDIM * BATCH + 255) / 256, 256>>>();

    embw_kernel<<<dim3(NG / 64, (VOCAB + 63) / 64), 256>>>(emb);

    lstm_persistent<<<GRID_CTAS, NTHR>>>(tokens, w_out, b_out, out);
}

// round 8
// speedup vs baseline: 2.3650x; 1.9409x over previous
#include <cuda_runtime.h>
#include <math.h>
#include <stdint.h>

#define BATCH 1024
#define TSTEPS 80
#define EDIM 100
#define UDIM 256
#define NG 1024       // 4 gates * U, packed n = u*4 + g
#define VOCAB 10000
#define GRID_CTAS 128
#define NTHR 128
#define KC 32

// ---------------- persistent device scratch ----------------
__device__ __align__(16) float g_W1h[UDIM * NG];           // tf32-rounded, [k][n]
__device__ __align__(16) float g_W1x[EDIM * NG];           // fp32 (exact), [k][n]
__device__ __align__(16) float g_W2 [2 * UDIM * NG];       // tf32-rounded, [k][n]
__device__ __align__(16) float g_b1[NG];
__device__ __align__(16) float g_b2[NG];
__device__ __align__(16) float g_embW[(size_t)VOCAB * NG]; // fp32 exact: emb@W1x + b1
// states transposed [unit][batch]; h values tf32-rounded at write
__device__ __align__(16) float g_h1[2][UDIM * BATCH];
__device__ __align__(16) float g_h2[2][UDIM * BATCH];
__device__ __align__(16) float g_c1[UDIM * BATCH];
__device__ __align__(16) float g_c2[UDIM * BATCH];
__device__ unsigned g_bar_count = 0;
__device__ volatile unsigned g_bar_gen = 0;

__device__ __forceinline__ float sigmoidf_(float x) { return 1.0f / (1.0f + expf(-x)); }

__device__ __forceinline__ uint32_t cvt_tf32(float f) {
    uint32_t r; asm("cvt.rna.tf32.f32 %0, %1;" : "=r"(r) : "f"(f)); return r;
}
__device__ __forceinline__ float tf32r(float f) { return __uint_as_float(cvt_tf32(f)); }

__device__ __forceinline__ uint32_t smem_u32(const void* p) {
    uint32_t a;
    asm("{ .reg .u64 t; cvta.to.shared.u64 t, %1; cvt.u32.u64 %0, t; }" : "=r"(a) : "l"(p));
    return a;
}
__device__ __forceinline__ void cp16(uint32_t dst, const void* src) {
    asm volatile("cp.async.cg.shared.global [%0], [%1], 16;" :: "r"(dst), "l"(src));
}
__device__ __forceinline__ void cp_commit() { asm volatile("cp.async.commit_group;"); }
__device__ __forceinline__ void cp_wait1()  { asm volatile("cp.async.wait_group 1;"); }
__device__ __forceinline__ void cp_wait0()  { asm volatile("cp.async.wait_group 0;"); }

// m16n8k8 tf32 MMA, acc fp32
__device__ __forceinline__ void mma_tf32(float* c, const uint32_t* a, const uint32_t* b) {
    asm volatile(
        "mma.sync.aligned.m16n8k8.row.col.f32.tf32.tf32.f32 "
        "{%0,%1,%2,%3}, {%4,%5,%6,%7}, {%8,%9}, {%0,%1,%2,%3};"
        : "+f"(c[0]), "+f"(c[1]), "+f"(c[2]), "+f"(c[3])
        : "r"(a[0]), "r"(a[1]), "r"(a[2]), "r"(a[3]), "r"(b[0]), "r"(b[1]));
}

// ---------------- software grid barrier ----------------
__device__ __forceinline__ void grid_barrier() {
    __syncthreads();
    if (threadIdx.x == 0) {
        __threadfence();
        unsigned gen = g_bar_gen;
        if (atomicAdd(&g_bar_count, 1u) == GRID_CTAS - 1) {
            g_bar_count = 0;
            __threadfence();
            g_bar_gen = gen + 1;
        } else {
            while (g_bar_gen == gen) { }
            __threadfence();
        }
    }
    __syncthreads();
}

// ---------------- weight repack: n = u*4 + g; W1h/W2 rounded to tf32 ----------------
__global__ void pack_kernel(
    const float* wf1, const float* bf1, const float* wi1, const float* bi1,
    const float* wc1, const float* bc1, const float* wo1, const float* bo1,
    const float* wf2, const float* bf2, const float* wi2, const float* bi2,
    const float* wc2, const float* bc2, const float* wo2, const float* bo2)
{
    const int TOT_W = (UDIM + EDIM + 2 * UDIM) * NG;
    int id = blockIdx.x * blockDim.x + threadIdx.x;
    if (id < TOT_W) {
        int kk = id >> 10;
        int n  = id & 1023;
        int u  = n >> 2;
        int g  = n & 3;
        if (kk < UDIM) {
            const float* w = (g == 0) ? wf1 : (g == 1) ? wi1 : (g == 2) ? wc1 : wo1;
            g_W1h[kk * NG + n] = tf32r(w[kk * UDIM + u]);
        } else if (kk < UDIM + EDIM) {
            const float* w = (g == 0) ? wf1 : (g == 1) ? wi1 : (g == 2) ? wc1 : wo1;
            g_W1x[(kk - UDIM) * NG + n] = w[kk * UDIM + u];   // exact fp32
        } else {
            int k2 = kk - (UDIM + EDIM);
            const float* w = (g == 0) ? wf2 : (g == 1) ? wi2 : (g == 2) ? wc2 : wo2;
            g_W2[k2 * NG + n] = tf32r(w[k2 * UDIM + u]);
        }
    } else if (id < TOT_W + 2 * NG) {
        int j = id - TOT_W;
        int n = j & 1023;
        int u = n >> 2;
        int g = n & 3;
        if (j < NG) g_b1[n] = ((g == 0) ? bf1 : (g == 1) ? bi1 : (g == 2) ? bc1 : bo1)[u];
        else        g_b2[n] = ((g == 0) ? bf2 : (g == 1) ? bi2 : (g == 2) ? bc2 : bo2)[u];
    }
}

__global__ void zero_kernel()
{
    int id = blockIdx.x * blockDim.x + threadIdx.x;
    if (id < UDIM * BATCH) {
        g_h1[0][id] = 0.0f;
        g_h2[0][id] = 0.0f;
        g_c1[id]    = 0.0f;
        g_c2[id]    = 0.0f;
    }
}

// ---------------- embW = emb @ W1x + b1 (fp32 exact; M=10000, N=1024, K=100) ----------------
__global__ __launch_bounds__(256) void embw_kernel(const float* __restrict__ emb)
{
    __shared__ __align__(16) float As[32][64];
    __shared__ __align__(16) float Bs[32][64];

    const int tid = threadIdx.x;
    const int m0  = blockIdx.y * 64;
    const int n0  = blockIdx.x * 64;
    const int tm  = tid >> 4;
    const int tn  = tid & 15;

    float acc[4][4] = {};

    for (int k0 = 0; k0 < 128; k0 += 32) {
        #pragma unroll
        for (int i = 0; i < 2; i++) {
            int f4 = tid + i * 256;
            int m  = f4 >> 3;
            int kq = f4 & 7;
            int k  = k0 + kq * 4;
            float4 v = make_float4(0.f, 0.f, 0.f, 0.f);
            int row = m0 + m;
            if (k < EDIM && row < VOCAB)
                v = *(const float4*)&emb[(size_t)row * EDIM + k];
            As[kq * 4 + 0][m] = v.x;
            As[kq * 4 + 1][m] = v.y;
            As[kq * 4 + 2][m] = v.z;
            As[kq * 4 + 3][m] = v.w;
        }
        #pragma unroll
        for (int i = 0; i < 2; i++) {
            int f4 = tid + i * 256;
            int kk = f4 >> 4;
            int c4 = f4 & 15;
            int k  = k0 + kk;
            float4 v = make_float4(0.f, 0.f, 0.f, 0.f);
            if (k < EDIM) v = *(const float4*)&g_W1x[k * NG + n0 + c4 * 4];
            *(float4*)&Bs[kk][c4 * 4] = v;
        }
        __syncthreads();

        #pragma unroll
        for (int k = 0; k < 32; k++) {
            float4 b = *(const float4*)&Bs[k][tn * 4];
            float4 a = *(const float4*)&As[k][tm * 4];
            float ar[4] = {a.x, a.y, a.z, a.w};
            float br[4] = {b.x, b.y, b.z, b.w};
            #pragma unroll
            for (int r = 0; r < 4; r++)
                #pragma unroll
                for (int c = 0; c < 4; c++)
                    acc[r][c] += ar[r] * br[c];
        }
        __syncthreads();
    }

    float4 bb = *(const float4*)&g_b1[n0 + tn * 4];
    #pragma unroll
    for (int r = 0; r < 4; r++) {
        int row = m0 + tm * 4 + r;
        if (row < VOCAB)
            *(float4*)&g_embW[(size_t)row * NG + n0 + tn * 4] =
                make_float4(acc[r][0] + bb.x, acc[r][1] + bb.y,
                            acc[r][2] + bb.z, acc[r][3] + bb.w);
    }
}

// ---------------- persistent kernel: tf32 MMA phases ----------------
// CTA tile 64M x 128N; 4 warps, warp tile 64M x 32N; mma m16n8k8 (4 mt x 4 nt).
// smem XOR swizzle: col' = col ^ ((k&3)*8) -> conflict-free frag LDS.

struct SmemT {
    float As[2][KC][64];    // [k][m] swizzled
    float Bs[2][KC][128];   // [k][n] swizzled
};

template <bool DUAL>
__device__ __forceinline__ void stage(SmemT* sm, int buf, int k0,
    const float* __restrict__ A0, const float* __restrict__ A1,
    const float* __restrict__ W, int m0, int n0, int tid)
{
    #pragma unroll
    for (int i = 0; i < 4; i++) {
        int f4 = tid + i * NTHR;     // 0..511
        int kq = f4 >> 4;            // 0..31
        int c4 = f4 & 15;            // 0..15
        int k  = k0 + kq;
        const float* src;
        if (DUAL)
            src = (k < UDIM) ? A0 + (size_t)k * BATCH + m0 + c4 * 4
                             : A1 + (size_t)(k - UDIM) * BATCH + m0 + c4 * 4;
        else
            src = A0 + (size_t)k * BATCH + m0 + c4 * 4;
        cp16(smem_u32(&sm->As[buf][kq][(c4 * 4) ^ ((kq & 3) * 8)]), src);
    }
    #pragma unroll
    for (int i = 0; i < 8; i++) {
        int f4 = tid + i * NTHR;     // 0..1023
        int kk = f4 >> 5;            // 0..31
        int c4 = f4 & 31;            // 0..31
        cp16(smem_u32(&sm->Bs[buf][kk][(c4 * 4) ^ ((kk & 3) * 8)]),
             &W[(size_t)(k0 + kk) * NG + n0 + c4 * 4]);
    }
}

template <bool L1P, bool DUAL>
__device__ __forceinline__ void gemm_phase(SmemT* sm,
    const float* __restrict__ A0, const float* __restrict__ A1,
    const float* __restrict__ W, int K,
    float* __restrict__ cs, float* __restrict__ hout,
    const int* __restrict__ tokens, int t, int m0, int n0)
{
    const int tid  = threadIdx.x;
    const int lane = tid & 31;
    const int wid  = tid >> 5;
    const int s    = lane & 3;       // threadID in group (k / col-pair select)
    const int g    = lane >> 2;      // group id (row / col select)
    const int nw   = wid * 32;       // warp's local n offset within the 128-wide tile

    float acc[4][4][4];
    #pragma unroll
    for (int a = 0; a < 4; a++)
        #pragma unroll
        for (int b = 0; b < 4; b++)
            #pragma unroll
            for (int c = 0; c < 4; c++) acc[a][b][c] = 0.0f;

    stage<DUAL>(sm, 0, 0, A0, A1, W, m0, n0, tid);
    cp_commit();

    const int C = K / KC;
    for (int c = 0; c < C; c++) {
        int cur = c & 1;
        if (c + 1 < C) {
            stage<DUAL>(sm, 1 - cur, (c + 1) * KC, A0, A1, W, m0, n0, tid);
            cp_commit();
            cp_wait1();
        } else {
            cp_wait0();
        }
        __syncthreads();

        #pragma unroll
        for (int k8 = 0; k8 < KC / 8; k8++) {
            const int kr0 = k8 * 8 + s;
            const int kr1 = kr0 + 4;          // (kr1 & 3) == (kr0 & 3) -> same swizzle
            const int sw  = s * 8;

            uint32_t bf[4][2];
            #pragma unroll
            for (int nt = 0; nt < 4; nt++) {
                int col = nw + nt * 8 + g;
                bf[nt][0] = *(const uint32_t*)&sm->Bs[cur][kr0][col ^ sw];
                bf[nt][1] = *(const uint32_t*)&sm->Bs[cur][kr1][col ^ sw];
            }
            #pragma unroll
            for (int mt = 0; mt < 4; mt++) {
                uint32_t af[4];
                int r0 = mt * 16 + g;
                af[0] = *(const uint32_t*)&sm->As[cur][kr0][r0 ^ sw];
                af[1] = *(const uint32_t*)&sm->As[cur][kr0][(r0 + 8) ^ sw];
                af[2] = *(const uint32_t*)&sm->As[cur][kr1][r0 ^ sw];
                af[3] = *(const uint32_t*)&sm->As[cur][kr1][(r0 + 8) ^ sw];
                #pragma unroll
                for (int nt = 0; nt < 4; nt++)
                    mma_tf32(acc[mt][nt], af, bf[nt]);
            }
        }
        __syncthreads();
    }

    // ---- fused LSTM epilogue ----
    // acc[mt][nt]: c0=(row g, col 2s), c1=(g,2s+1), c2=(g+8,2s), c3=(g+8,2s+1)
    // even s-pair lane holds (f,i), odd holds (ctilde,o) of the same unit.
    // shfl-xor-1 exchange: even lane finishes row g, odd lane row g+8.
    #pragma unroll
    for (int mt = 0; mt < 4; mt++) {
        const int m = m0 + mt * 16 + g + ((lane & 1) << 3);
        int tok = 0;
        if (L1P) tok = tokens[m * TSTEPS + t];
        #pragma unroll
        for (int nt = 0; nt < 4; nt++) {
            float* a = acc[mt][nt];
            float v1 = __shfl_xor_sync(0xFFFFFFFFu, (lane & 1) ? a[0] : a[2], 1);
            float v2 = __shfl_xor_sync(0xFFFFFFFFu, (lane & 1) ? a[1] : a[3], 1);
            float pf, pi, pc, po;
            if (lane & 1) { pc = a[2]; po = a[3]; pf = v1; pi = v2; }
            else          { pf = a[0]; pi = a[1]; pc = v1; po = v2; }

            const int u = ((n0 + nw + nt * 8) >> 2) + (s >> 1);
            if (L1P) {
                float4 x = *(const float4*)&g_embW[(size_t)tok * NG + u * 4];
                pf += x.x; pi += x.y; pc += x.z; po += x.w;
            } else {
                float4 bv = *(const float4*)&g_b2[u * 4];
                pf += bv.x; pi += bv.y; pc += bv.z; po += bv.w;
            }
            float cold = cs[(size_t)u * BATCH + m];
            float cn = sigmoidf_(pf) * cold + sigmoidf_(pi) * tanhf(pc);
            cs[(size_t)u * BATCH + m] = cn;
            hout[(size_t)u * BATCH + m] = tf32r(sigmoidf_(po) * tanhf(cn));
        }
    }
    __syncthreads();
}

__global__ __launch_bounds__(NTHR, 1) void lstm_persistent(
    const int* __restrict__ tokens,
    const float* __restrict__ w_out, const float* __restrict__ b_out,
    float* __restrict__ out)
{
    __shared__ __align__(16) SmemT sm;

    const int cta = blockIdx.x;
    const int n0  = (cta & 7) * 128;     // 8 n-tiles
    const int m0  = (cta >> 3) * 64;     // 16 m-tiles

    // prologue: layer1 at t=0 (h1_init = zeros in g_h1[0]) -> h1(0) into g_h1[1]
    gemm_phase<true, false>(&sm, g_h1[0], g_h1[0], g_W1h, UDIM,
                            g_c1, g_h1[1], tokens, 0, m0, n0);
    grid_barrier();

    for (int t = 0; t < TSTEPS; t++) {
        // layer2(t): A = [h2(t-1) | h1(t)]
        gemm_phase<false, true>(&sm, g_h2[t & 1], g_h1[(t + 1) & 1], g_W2, 2 * UDIM,
                                g_c2, g_h2[(t + 1) & 1], tokens, t, m0, n0);
        // layer1(t+1): A = h1(t)  (independent of layer2(t) -> same phase)
        if (t < TSTEPS - 1)
            gemm_phase<true, false>(&sm, g_h1[(t + 1) & 1], g_h1[0], g_W1h, UDIM,
                                    g_c1, g_h1[t & 1], tokens, t + 1, m0, n0);
        grid_barrier();
    }

    // final dense + sigmoid; h2(79) lives in g_h2[0]
    int gw   = cta * (NTHR / 32) + (threadIdx.x >> 5);
    int lane = threadIdx.x & 31;
    if (gw < BATCH / 32) {
        int bb = gw * 32 + lane;
        float s = 0.0f;
        const float* h = g_h2[0];
        #pragma unroll 8
        for (int u = 0; u < UDIM; u++)
            s += h[(size_t)u * BATCH + bb] * w_out[u];
        out[bb] = sigmoidf_(s + b_out[0]);
    }
}

// ---------------- launch ----------------
extern "C" void kernel_launch(void* const* d_in, const int* in_sizes, int n_in,
                              void* d_out, int out_size)
{
    const int*   tokens = (const int*)  d_in[0];
    const float* emb    = (const float*)d_in[1];
    const float* wf1 = (const float*)d_in[2];  const float* bf1 = (const float*)d_in[3];
    const float* wi1 = (const float*)d_in[4];  const float* bi1 = (const float*)d_in[5];
    const float* wc1 = (const float*)d_in[6];  const float* bc1 = (const float*)d_in[7];
    const float* wo1 = (const float*)d_in[8];  const float* bo1 = (const float*)d_in[9];
    const float* wf2 = (const float*)d_in[10]; const float* bf2 = (const float*)d_in[11];
    const float* wi2 = (const float*)d_in[12]; const float* bi2 = (const float*)d_in[13];
    const float* wc2 = (const float*)d_in[14]; const float* bc2 = (const float*)d_in[15];
    const float* wo2 = (const float*)d_in[16]; const float* bo2 = (const float*)d_in[17];
    const float* w_out = (const float*)d_in[18];
    const float* b_out = (const float*)d_in[19];
    float* out = (float*)d_out;

    const int TOT = (UDIM + EDIM + 2 * UDIM) * NG + 2 * NG;
    pack_kernel<<<(TOT + 255) / 256, 256>>>(wf1, bf1, wi1, bi1, wc1, bc1, wo1, bo1,
                                            wf2, bf2, wi2, bi2, wc2, bc2, wo2, bo2);
    zero_kernel<<<(UDIM * BATCH + 255) / 256, 256>>>();

    embw_kernel<<<dim3(NG / 64, (VOCAB + 63) / 64), 256>>>(emb);

    lstm_persistent<<<GRID_CTAS, NTHR>>>(tokens, w_out, b_out, out);
}

// round 9
// speedup vs baseline: 3.3312x; 1.4085x over previous
#include <cuda_runtime.h>
#include <math.h>
#include <stdint.h>

#define BATCH 1024
#define TSTEPS 80
#define EDIM 100
#define UDIM 256
#define NG 1024       // 4 gates * U, packed n = u*4 + g
#define VOCAB 10000
#define GRID_CTAS 128
#define NTHR 256
#define KC 32

// smem plan (floats): Ws[768][64] resident weights + Ar[2][32][128] A double buffer
#define WS_FLOATS (768 * 64)
#define AR_FLOATS (2 * KC * 128)
#define SMEM_BYTES ((WS_FLOATS + AR_FLOATS) * 4)

// ---------------- persistent device scratch ----------------
__device__ __align__(16) float g_W1h[UDIM * NG];           // tf32-rounded, [k][n]
__device__ __align__(16) float g_W1x[EDIM * NG];           // fp32 exact, [k][n]
__device__ __align__(16) float g_W2 [2 * UDIM * NG];       // tf32-rounded, [k][n]
__device__ __align__(16) float g_b1[NG];
__device__ __align__(16) float g_b2[NG];
__device__ __align__(16) float g_embW[(size_t)VOCAB * NG]; // fp32 exact: emb@W1x + b1
// states transposed [unit][batch]
__device__ __align__(16) float g_h1[2][UDIM * BATCH];
__device__ __align__(16) float g_h2[2][UDIM * BATCH];
__device__ __align__(16) float g_c1[UDIM * BATCH];
__device__ __align__(16) float g_c2[UDIM * BATCH];
__device__ unsigned g_bar_count = 0;
__device__ volatile unsigned g_bar_gen = 0;

__device__ __forceinline__ float tanh_ap(float x) {
    float r; asm("tanh.approx.f32 %0, %1;" : "=f"(r) : "f"(x)); return r;
}
__device__ __forceinline__ float sigmoid_ap(float x) {
    return 0.5f * tanh_ap(0.5f * x) + 0.5f;
}
__device__ __forceinline__ uint32_t cvt_tf32(float f) {
    uint32_t r; asm("cvt.rna.tf32.f32 %0, %1;" : "=r"(r) : "f"(f)); return r;
}
__device__ __forceinline__ float tf32r(float f) { return __uint_as_float(cvt_tf32(f)); }

__device__ __forceinline__ uint32_t smem_u32(const void* p) {
    uint32_t a;
    asm("{ .reg .u64 t; cvta.to.shared.u64 t, %1; cvt.u32.u64 %0, t; }" : "=r"(a) : "l"(p));
    return a;
}
__device__ __forceinline__ void cp16(uint32_t dst, const void* src) {
    asm volatile("cp.async.cg.shared.global [%0], [%1], 16;" :: "r"(dst), "l"(src));
}
__device__ __forceinline__ void cp_commit() { asm volatile("cp.async.commit_group;"); }
__device__ __forceinline__ void cp_wait1()  { asm volatile("cp.async.wait_group 1;"); }
__device__ __forceinline__ void cp_wait0()  { asm volatile("cp.async.wait_group 0;"); }

__device__ __forceinline__ void mma_tf32(float* c, const uint32_t* a, const uint32_t* b) {
    asm volatile(
        "mma.sync.aligned.m16n8k8.row.col.f32.tf32.tf32.f32 "
        "{%0,%1,%2,%3}, {%4,%5,%6,%7}, {%8,%9}, {%0,%1,%2,%3};"
        : "+f"(c[0]), "+f"(c[1]), "+f"(c[2]), "+f"(c[3])
        : "r"(a[0]), "r"(a[1]), "r"(a[2]), "r"(a[3]), "r"(b[0]), "r"(b[1]));
}

// ---------------- software grid barrier ----------------
__device__ __forceinline__ void grid_barrier() {
    __syncthreads();
    if (threadIdx.x == 0) {
        __threadfence();
        unsigned gen = g_bar_gen;
        if (atomicAdd(&g_bar_count, 1u) == GRID_CTAS - 1) {
            g_bar_count = 0;
            __threadfence();
            g_bar_gen = gen + 1;
        } else {
            while (g_bar_gen == gen) { }
            __threadfence();
        }
    }
    __syncthreads();
}

// ---------------- weight repack: n = u*4 + g; W1h/W2 tf32-rounded ----------------
__global__ void pack_kernel(
    const float* wf1, const float* bf1, const float* wi1, const float* bi1,
    const float* wc1, const float* bc1, const float* wo1, const float* bo1,
    const float* wf2, const float* bf2, const float* wi2, const float* bi2,
    const float* wc2, const float* bc2, const float* wo2, const float* bo2)
{
    const int TOT_W = (UDIM + EDIM + 2 * UDIM) * NG;
    int id = blockIdx.x * blockDim.x + threadIdx.x;
    if (id < TOT_W) {
        int kk = id >> 10;
        int n  = id & 1023;
        int u  = n >> 2;
        int g  = n & 3;
        if (kk < UDIM) {
            const float* w = (g == 0) ? wf1 : (g == 1) ? wi1 : (g == 2) ? wc1 : wo1;
            g_W1h[kk * NG + n] = tf32r(w[kk * UDIM + u]);
        } else if (kk < UDIM + EDIM) {
            const float* w = (g == 0) ? wf1 : (g == 1) ? wi1 : (g == 2) ? wc1 : wo1;
            g_W1x[(kk - UDIM) * NG + n] = w[kk * UDIM + u];   // exact
        } else {
            int k2 = kk - (UDIM + EDIM);
            const float* w = (g == 0) ? wf2 : (g == 1) ? wi2 : (g == 2) ? wc2 : wo2;
            g_W2[k2 * NG + n] = tf32r(w[k2 * UDIM + u]);
        }
    } else if (id < TOT_W + 2 * NG) {
        int j = id - TOT_W;
        int n = j & 1023;
        int u = n >> 2;
        int g = n & 3;
        if (j < NG) g_b1[n] = ((g == 0) ? bf1 : (g == 1) ? bi1 : (g == 2) ? bc1 : bo1)[u];
        else        g_b2[n] = ((g == 0) ? bf2 : (g == 1) ? bi2 : (g == 2) ? bc2 : bo2)[u];
    }
}

__global__ void zero_kernel()
{
    int id = blockIdx.x * blockDim.x + threadIdx.x;
    if (id < UDIM * BATCH) {
        g_h1[0][id] = 0.0f;
        g_h2[0][id] = 0.0f;
        g_c1[id]    = 0.0f;
        g_c2[id]    = 0.0f;
    }
}

// ---------------- embW = emb @ W1x + b1 (fp32 exact) ----------------
__global__ __launch_bounds__(256) void embw_kernel(const float* __restrict__ emb)
{
    __shared__ __align__(16) float As[32][64];
    __shared__ __align__(16) float Bs[32][64];

    const int tid = threadIdx.x;
    const int m0  = blockIdx.y * 64;
    const int n0  = blockIdx.x * 64;
    const int tm  = tid >> 4;
    const int tn  = tid & 15;

    float acc[4][4] = {};

    for (int k0 = 0; k0 < 128; k0 += 32) {
        #pragma unroll
        for (int i = 0; i < 2; i++) {
            int f4 = tid + i * 256;
            int m  = f4 >> 3;
            int kq = f4 & 7;
            int k  = k0 + kq * 4;
            float4 v = make_float4(0.f, 0.f, 0.f, 0.f);
            int row = m0 + m;
            if (k < EDIM && row < VOCAB)
                v = *(const float4*)&emb[(size_t)row * EDIM + k];
            As[kq * 4 + 0][m] = v.x;
            As[kq * 4 + 1][m] = v.y;
            As[kq * 4 + 2][m] = v.z;
            As[kq * 4 + 3][m] = v.w;
        }
        #pragma unroll
        for (int i = 0; i < 2; i++) {
            int f4 = tid + i * 256;
            int kk = f4 >> 4;
            int c4 = f4 & 15;
            int k  = k0 + kk;
            float4 v = make_float4(0.f, 0.f, 0.f, 0.f);
            if (k < EDIM) v = *(const float4*)&g_W1x[k * NG + n0 + c4 * 4];
            *(float4*)&Bs[kk][c4 * 4] = v;
        }
        __syncthreads();

        #pragma unroll
        for (int k = 0; k < 32; k++) {
            float4 b = *(const float4*)&Bs[k][tn * 4];
            float4 a = *(const float4*)&As[k][tm * 4];
            float ar[4] = {a.x, a.y, a.z, a.w};
            float br[4] = {b.x, b.y, b.z, b.w};
            #pragma unroll
            for (int r = 0; r < 4; r++)
                #pragma unroll
                for (int c = 0; c < 4; c++)
                    acc[r][c] += ar[r] * br[c];
        }
        __syncthreads();
    }

    float4 bb = *(const float4*)&g_b1[n0 + tn * 4];
    #pragma unroll
    for (int r = 0; r < 4; r++) {
        int row = m0 + tm * 4 + r;
        if (row < VOCAB)
            *(float4*)&g_embW[(size_t)row * NG + n0 + tn * 4] =
                make_float4(acc[r][0] + bb.x, acc[r][1] + bb.y,
                            acc[r][2] + bb.z, acc[r][3] + bb.w);
    }
}

// ---------------- persistent kernel ----------------
// Grid 128 = 8 m-tiles x 16 n-tiles. CTA tile 128M x 64N, 8 warps (4m x 2n),
// warp tile 32M x 32N, mma m16n8k8: mt=2, nt=4.
// Ws resident in smem, packed: Ws[k][ ((wn*32 + g*4) ^ (8*(k&3))) + nt ],
//   where n_local = wn*32 + nt*8 + g  -> B frag = LDS.128 (conflict-free).
// A staged per chunk: Ar[buf][k][ (m) ^ (8*(k&3)) ]  -> LDS.32 conflict-free.

// stage one 32k x 128m A chunk via cp.async (1024 x 16B, 4 per thread)
__device__ __forceinline__ void stage_A(float* dst, const float* __restrict__ src, int tid)
{
    #pragma unroll
    for (int i = 0; i < 4; i++) {
        int f4 = tid + i * NTHR;        // 0..1023
        int kq = f4 >> 5;               // 0..31
        int c4 = f4 & 31;               // 0..31
        int col = (c4 * 4) ^ ((kq & 3) * 8);
        cp16(smem_u32(dst + kq * 128 + col), src + (size_t)kq * BATCH + c4 * 4);
    }
}

template <bool L1P, bool DUAL>
__device__ __forceinline__ void gemm_phase(
    float* __restrict__ Ws,        // + wrow0*64 already applied
    float* __restrict__ Ar,
    int K,
    const float* __restrict__ A0,  // first K-source (transposed [k][b]) + m0
    const float* __restrict__ A1,  // second source for DUAL (k >= 256) + m0
    float* __restrict__ cs, float* __restrict__ hout,
    const int* __restrict__ tokens, int t, int m0, int n0)
{
    const int tid  = threadIdx.x;
    const int lane = tid & 31;
    const int wid  = tid >> 5;
    const int s    = lane & 3;
    const int g    = lane >> 2;
    const int wm   = wid & 3;
    const int wn   = wid >> 2;

    // conflict-free swizzled column bases (constant per thread)
    const int cm0  = (wm * 32 + g) ^ (8 * s);   // A mt0, row-lo
    const int cb   = (wn * 32 + g * 4) ^ (8 * s);

    float acc[2][4][4];
    #pragma unroll
    for (int a = 0; a < 2; a++)
        #pragma unroll
        for (int b = 0; b < 4; b++)
            #pragma unroll
            for (int c = 0; c < 4; c++) acc[a][b][c] = 0.0f;

    const int C = K / KC;
    {
        const float* src0 = (DUAL && 0 >= 8) ? A1 : A0;   // chunk 0 source
        stage_A(Ar, src0, tid);
        cp_commit();
    }

    for (int c = 0; c < C; c++) {
        int cur = c & 1;
        if (c + 1 < C) {
            int k0n = (c + 1) * KC;
            const float* srcn = (DUAL && k0n >= 2 * UDIM / 2) ?
                                A1 + (size_t)(k0n - UDIM) * BATCH :
                                A0 + (size_t)k0n * BATCH;
            // note: DUAL split point is k = UDIM (=256); chunks are 32-aligned
            stage_A(Ar + (1 - cur) * (KC * 128), srcn, tid);
            cp_commit();
            cp_wait1();
        } else {
            cp_wait0();
        }
        __syncthreads();

        const float* Ab = Ar + cur * (KC * 128) + s * 128;       // + slab*1024, col
        const float* Bb = Ws + ((size_t)(c * KC) + s) * 64 + cb; // + slab*512

        #pragma unroll
        for (int sl = 0; sl < KC / 8; sl++) {
            const float* ap = Ab + sl * (8 * 128);
            const float* bp = Bb + sl * (8 * 64);
            float4 b0 = *(const float4*)bp;            // k = kr0
            float4 b1 = *(const float4*)(bp + 4 * 64); // k = kr1
            uint32_t bf[4][2] = {
                { __float_as_uint(b0.x), __float_as_uint(b1.x) },
                { __float_as_uint(b0.y), __float_as_uint(b1.y) },
                { __float_as_uint(b0.z), __float_as_uint(b1.z) },
                { __float_as_uint(b0.w), __float_as_uint(b1.w) }
            };
            #pragma unroll
            for (int mt = 0; mt < 2; mt++) {
                const int cc = cm0 ^ (mt * 16);
                uint32_t af[4];
                af[0] = __float_as_uint(ap[cc]);
                af[1] = __float_as_uint(ap[cc ^ 8]);
                af[2] = __float_as_uint(ap[4 * 128 + cc]);
                af[3] = __float_as_uint(ap[4 * 128 + (cc ^ 8)]);
                #pragma unroll
                for (int nt = 0; nt < 4; nt++)
                    mma_tf32(acc[mt][nt], af, bf[nt]);
            }
        }
        __syncthreads();
    }

    // ---- fused LSTM epilogue ----
    // acc[mt][nt]: c0=(row g, col 2s), c1=(g,2s+1), c2=(g+8,2s), c3=(g+8,2s+1)
    // even-s-lsb lane holds (f,i), odd holds (ctilde,o); shfl-xor-1 completes a cell.
    #pragma unroll
    for (int mt = 0; mt < 2; mt++) {
        const int m = m0 + wm * 32 + mt * 16 + g + ((lane & 1) << 3);
        int tok = 0;
        if (L1P) tok = tokens[m * TSTEPS + t];
        #pragma unroll
        for (int nt = 0; nt < 4; nt++) {
            float* a = acc[mt][nt];
            float v1 = __shfl_xor_sync(0xFFFFFFFFu, (lane & 1) ? a[0] : a[2], 1);
            float v2 = __shfl_xor_sync(0xFFFFFFFFu, (lane & 1) ? a[1] : a[3], 1);
            float pf, pi, pc, po;
            if (lane & 1) { pc = a[2]; po = a[3]; pf = v1; pi = v2; }
            else          { pf = a[0]; pi = a[1]; pc = v1; po = v2; }

            const int u = ((n0 + wn * 32 + nt * 8) >> 2) + (s >> 1);
            if (L1P) {
                float4 x = *(const float4*)&g_embW[(size_t)tok * NG + u * 4];
                pf += x.x; pi += x.y; pc += x.z; po += x.w;
            } else {
                float4 bv = *(const float4*)&g_b2[u * 4];
                pf += bv.x; pi += bv.y; pc += bv.z; po += bv.w;
            }
            float cold = cs[(size_t)u * BATCH + m];
            float cn = sigmoid_ap(pf) * cold + sigmoid_ap(pi) * tanh_ap(pc);
            cs[(size_t)u * BATCH + m] = cn;
            hout[(size_t)u * BATCH + m] = tf32r(sigmoid_ap(po) * tanh_ap(cn));
        }
    }
}

__global__ __launch_bounds__(NTHR, 1) void lstm_persistent(
    const int* __restrict__ tokens,
    const float* __restrict__ w_out, const float* __restrict__ b_out,
    float* __restrict__ out)
{
    extern __shared__ __align__(16) float smem[];
    float* Ws = smem;                 // [768][64]: rows 0-255 = W1h slice, 256-767 = W2 slice
    float* Ar = smem + WS_FLOATS;     // [2][32][128]

    const int cta = blockIdx.x;
    const int n0  = (cta & 15) * 64;      // 16 n-tiles
    const int m0  = (cta >> 4) * 128;     // 8 m-tiles
    const int tid = threadIdx.x;

    // ---- load resident weight slices (packed + swizzled) ----
    for (int idx = tid; idx < 768 * 64; idx += NTHR) {
        int k  = idx >> 6;
        int nl = idx & 63;
        int wn = nl >> 5, r = nl & 31, g = r & 7, nt = r >> 3;
        int dst = k * 64 + (((wn << 5) + (g << 2)) ^ ((k & 3) << 3)) + nt;
        float v = (k < UDIM) ? g_W1h[(size_t)k * NG + n0 + nl]
                             : g_W2[(size_t)(k - UDIM) * NG + n0 + nl];
        Ws[dst] = v;
    }
    __syncthreads();

    float* Ws2 = Ws + UDIM * 64;   // layer2 weight rows

    // prologue: layer1 t=0 (h1_init zeros in g_h1[0]) -> h1(0) into g_h1[1]
    gemm_phase<true, false>(Ws, Ar, UDIM, g_h1[0] + m0, g_h1[0] + m0,
                            g_c1, g_h1[1], tokens, 0, m0, n0);
    grid_barrier();

    for (int t = 0; t < TSTEPS; t++) {
        // layer2(t): A = [h2(t-1) | h1(t)]
        gemm_phase<false, true>(Ws2, Ar, 2 * UDIM,
                                g_h2[t & 1] + m0, g_h1[(t + 1) & 1] + m0,
                                g_c2, g_h2[(t + 1) & 1], tokens, t, m0, n0);
        // layer1(t+1): A = h1(t)
        if (t < TSTEPS - 1)
            gemm_phase<true, false>(Ws, Ar, UDIM,
                                    g_h1[(t + 1) & 1] + m0, g_h1[0] + m0,
                                    g_c1, g_h1[t & 1], tokens, t + 1, m0, n0);
        grid_barrier();
    }

    // final dense + sigmoid; h2(79) in g_h2[0]
    int gw   = cta * (NTHR / 32) + (tid >> 5);
    int lane = tid & 31;
    if (gw < BATCH / 32) {
        int bb = gw * 32 + lane;
        float s = 0.0f;
        const float* h = g_h2[0];
        #pragma unroll 8
        for (int u = 0; u < UDIM; u++)
            s += h[(size_t)u * BATCH + bb] * w_out[u];
        out[bb] = 1.0f / (1.0f + expf(-(s + b_out[0])));
    }
}

// ---------------- launch ----------------
extern "C" void kernel_launch(void* const* d_in, const int* in_sizes, int n_in,
                              void* d_out, int out_size)
{
    const int*   tokens = (const int*)  d_in[0];
    const float* emb    = (const float*)d_in[1];
    const float* wf1 = (const float*)d_in[2];  const float* bf1 = (const float*)d_in[3];
    const float* wi1 = (const float*)d_in[4];  const float* bi1 = (const float*)d_in[5];
    const float* wc1 = (const float*)d_in[6];  const float* bc1 = (const float*)d_in[7];
    const float* wo1 = (const float*)d_in[8];  const float* bo1 = (const float*)d_in[9];
    const float* wf2 = (const float*)d_in[10]; const float* bf2 = (const float*)d_in[11];
    const float* wi2 = (const float*)d_in[12]; const float* bi2 = (const float*)d_in[13];
    const float* wc2 = (const float*)d_in[14]; const float* bc2 = (const float*)d_in[15];
    const float* wo2 = (const float*)d_in[16]; const float* bo2 = (const float*)d_in[17];
    const float* w_out = (const float*)d_in[18];
    const float* b_out = (const float*)d_in[19];
    float* out = (float*)d_out;

    static int smem_set = 0;
    if (!smem_set) {
        cudaFuncSetAttribute(lstm_persistent,
                             cudaFuncAttributeMaxDynamicSharedMemorySize, SMEM_BYTES);
        smem_set = 1;
    }

    const int TOT = (UDIM + EDIM + 2 * UDIM) * NG + 2 * NG;
    pack_kernel<<<(TOT + 255) / 256, 256>>>(wf1, bf1, wi1, bi1, wc1, bc1, wo1, bo1,
                                            wf2, bf2, wi2, bi2, wc2, bc2, wo2, bo2);
    zero_kernel<<<(UDIM * BATCH + 255) / 256, 256>>>();

    embw_kernel<<<dim3(NG / 64, (VOCAB + 63) / 64), 256>>>(emb);

    lstm_persistent<<<GRID_CTAS, NTHR, SMEM_BYTES>>>(tokens, w_out, b_out, out);
}

// round 10
// speedup vs baseline: 4.7634x; 1.4300x over previous
#include <cuda_runtime.h>
#include <cuda_bf16.h>
#include <math.h>
#include <stdint.h>

#define BATCH 1024
#define TSTEPS 80
#define EDIM 100
#define UDIM 256
#define NG 1024       // 4 gates * U, packed n = u*4 + g
#define VOCAB 10000
#define GRID_CTAS 128
#define NTHR 256

// K2 = packed k-pair rows. Layer1: 128 rows, Layer2: 256 rows. Chunk = 32 rows (64 k).
#define KC2 32

// smem (uint32 units): Ws[384][64] packed bf16x2 weights + Ar[2][32][128] A buffer
#define WS_U32 (384 * 64)
#define AR_U32 (2 * KC2 * 128)
#define SMEM_BYTES ((WS_U32 + AR_U32) * 4)

// ---------------- persistent device scratch ----------------
__device__ __align__(16) uint32_t g_W1hp[128 * NG];        // bf16x2 [k2][n]
__device__ __align__(16) uint32_t g_W2p [256 * NG];        // bf16x2 [k2][n]
__device__ __align__(16) float g_W1x[EDIM * NG];           // fp32 exact, [k][n]
__device__ __align__(16) float g_b1[NG];
__device__ __align__(16) float g_b2[NG];
__device__ __align__(16) float g_embW[(size_t)VOCAB * NG]; // fp32 exact: emb@W1x + b1
// h states packed bf16x2 pairs of units: [u2][batch]
__device__ __align__(16) uint32_t g_h1p[2][(UDIM / 2) * BATCH];
__device__ __align__(16) uint32_t g_h2p[2][(UDIM / 2) * BATCH];
__device__ __align__(16) float g_c1[UDIM * BATCH];
__device__ __align__(16) float g_c2[UDIM * BATCH];
__device__ unsigned g_bar_count = 0;
__device__ volatile unsigned g_bar_gen = 0;

__device__ __forceinline__ float tanh_ap(float x) {
    float r; asm("tanh.approx.f32 %0, %1;" : "=f"(r) : "f"(x)); return r;
}
__device__ __forceinline__ float sigmoid_ap(float x) {
    return 0.5f * tanh_ap(0.5f * x) + 0.5f;
}
__device__ __forceinline__ uint32_t pack_bf2(float lo, float hi) {
    unsigned l = __bfloat16_as_ushort(__float2bfloat16_rn(lo));
    unsigned h = __bfloat16_as_ushort(__float2bfloat16_rn(hi));
    return l | (h << 16);
}
__device__ __forceinline__ uint32_t smem_u32(const void* p) {
    uint32_t a;
    asm("{ .reg .u64 t; cvta.to.shared.u64 t, %1; cvt.u32.u64 %0, t; }" : "=r"(a) : "l"(p));
    return a;
}
__device__ __forceinline__ void cp16(uint32_t dst, const void* src) {
    asm volatile("cp.async.cg.shared.global [%0], [%1], 16;" :: "r"(dst), "l"(src));
}
__device__ __forceinline__ void cp_commit() { asm volatile("cp.async.commit_group;"); }
__device__ __forceinline__ void cp_wait1()  { asm volatile("cp.async.wait_group 1;"); }
__device__ __forceinline__ void cp_wait0()  { asm volatile("cp.async.wait_group 0;"); }

// m16n8k16 bf16 MMA, fp32 accum
__device__ __forceinline__ void mma_bf16(float* c, const uint32_t* a, const uint32_t* b) {
    asm volatile(
        "mma.sync.aligned.m16n8k16.row.col.f32.bf16.bf16.f32 "
        "{%0,%1,%2,%3}, {%4,%5,%6,%7}, {%8,%9}, {%0,%1,%2,%3};"
        : "+f"(c[0]), "+f"(c[1]), "+f"(c[2]), "+f"(c[3])
        : "r"(a[0]), "r"(a[1]), "r"(a[2]), "r"(a[3]), "r"(b[0]), "r"(b[1]));
}

// ---------------- software grid barrier ----------------
__device__ __forceinline__ void grid_barrier() {
    __syncthreads();
    if (threadIdx.x == 0) {
        __threadfence();
        unsigned gen = g_bar_gen;
        if (atomicAdd(&g_bar_count, 1u) == GRID_CTAS - 1) {
            g_bar_count = 0;
            __threadfence();
            g_bar_gen = gen + 1;
        } else {
            while (g_bar_gen == gen) { }
            __threadfence();
        }
    }
    __syncthreads();
}

// ---------------- pack: n = u*4+g; recurrent W as bf16x2 k-pairs; W1x exact ----------------
__global__ void pack_kernel(
    const float* wf1, const float* bf1, const float* wi1, const float* bi1,
    const float* wc1, const float* bc1, const float* wo1, const float* bo1,
    const float* wf2, const float* bf2, const float* wi2, const float* bi2,
    const float* wc2, const float* bc2, const float* wo2, const float* bo2)
{
    const int TOT_P = 384 * NG;                 // packed recurrent rows
    const int TOT_X = EDIM * NG;                // exact W1x
    int id = blockIdx.x * blockDim.x + threadIdx.x;
    if (id < TOT_P) {
        int k2 = id >> 10;
        int n  = id & 1023;
        int u  = n >> 2;
        int g  = n & 3;
        if (k2 < 128) {
            const float* w = (g == 0) ? wf1 : (g == 1) ? wi1 : (g == 2) ? wc1 : wo1;
            g_W1hp[k2 * NG + n] = pack_bf2(w[(2 * k2) * UDIM + u],
                                           w[(2 * k2 + 1) * UDIM + u]);
        } else {
            int kk = k2 - 128;
            const float* w = (g == 0) ? wf2 : (g == 1) ? wi2 : (g == 2) ? wc2 : wo2;
            g_W2p[kk * NG + n] = pack_bf2(w[(2 * kk) * UDIM + u],
                                          w[(2 * kk + 1) * UDIM + u]);
        }
    } else if (id < TOT_P + TOT_X) {
        int j = id - TOT_P;
        int kk = j >> 10;
        int n  = j & 1023;
        int u  = n >> 2;
        int g  = n & 3;
        const float* w = (g == 0) ? wf1 : (g == 1) ? wi1 : (g == 2) ? wc1 : wo1;
        g_W1x[kk * NG + n] = w[(UDIM + kk) * UDIM + u];   // rows U..U+E of layer1 W
    } else if (id < TOT_P + TOT_X + 2 * NG) {
        int j = id - TOT_P - TOT_X;
        int n = j & 1023;
        int u = n >> 2;
        int g = n & 3;
        if (j < NG) g_b1[n] = ((g == 0) ? bf1 : (g == 1) ? bi1 : (g == 2) ? bc1 : bo1)[u];
        else        g_b2[n] = ((g == 0) ? bf2 : (g == 1) ? bi2 : (g == 2) ? bc2 : bo2)[u];
    }
}

__global__ void zero_kernel()
{
    int id = blockIdx.x * blockDim.x + threadIdx.x;
    if (id < UDIM * BATCH) {
        g_c1[id] = 0.0f;
        g_c2[id] = 0.0f;
    }
    if (id < (UDIM / 2) * BATCH) {
        g_h1p[0][id] = 0u;
        g_h2p[0][id] = 0u;
    }
}

// ---------------- embW = emb @ W1x + b1 (fp32 exact) ----------------
__global__ __launch_bounds__(256) void embw_kernel(const float* __restrict__ emb)
{
    __shared__ __align__(16) float As[32][64];
    __shared__ __align__(16) float Bs[32][64];

    const int tid = threadIdx.x;
    const int m0  = blockIdx.y * 64;
    const int n0  = blockIdx.x * 64;
    const int tm  = tid >> 4;
    const int tn  = tid & 15;

    float acc[4][4] = {};

    for (int k0 = 0; k0 < 128; k0 += 32) {
        #pragma unroll
        for (int i = 0; i < 2; i++) {
            int f4 = tid + i * 256;
            int m  = f4 >> 3;
            int kq = f4 & 7;
            int k  = k0 + kq * 4;
            float4 v = make_float4(0.f, 0.f, 0.f, 0.f);
            int row = m0 + m;
            if (k < EDIM && row < VOCAB)
                v = *(const float4*)&emb[(size_t)row * EDIM + k];
            As[kq * 4 + 0][m] = v.x;
            As[kq * 4 + 1][m] = v.y;
            As[kq * 4 + 2][m] = v.z;
            As[kq * 4 + 3][m] = v.w;
        }
        #pragma unroll
        for (int i = 0; i < 2; i++) {
            int f4 = tid + i * 256;
            int kk = f4 >> 4;
            int c4 = f4 & 15;
            int k  = k0 + kk;
            float4 v = make_float4(0.f, 0.f, 0.f, 0.f);
            if (k < EDIM) v = *(const float4*)&g_W1x[k * NG + n0 + c4 * 4];
            *(float4*)&Bs[kk][c4 * 4] = v;
        }
        __syncthreads();

        #pragma unroll
        for (int k = 0; k < 32; k++) {
            float4 b = *(const float4*)&Bs[k][tn * 4];
            float4 a = *(const float4*)&As[k][tm * 4];
            float ar[4] = {a.x, a.y, a.z, a.w};
            float br[4] = {b.x, b.y, b.z, b.w};
            #pragma unroll
            for (int r = 0; r < 4; r++)
                #pragma unroll
                for (int c = 0; c < 4; c++)
                    acc[r][c] += ar[r] * br[c];
        }
        __syncthreads();
    }

    float4 bb = *(const float4*)&g_b1[n0 + tn * 4];
    #pragma unroll
    for (int r = 0; r < 4; r++) {
        int row = m0 + tm * 4 + r;
        if (row < VOCAB)
            *(float4*)&g_embW[(size_t)row * NG + n0 + tn * 4] =
                make_float4(acc[r][0] + bb.x, acc[r][1] + bb.y,
                            acc[r][2] + bb.z, acc[r][3] + bb.w);
    }
}

// ---------------- persistent kernel ----------------
// Grid 128 = 8 m-tiles x 16 n-tiles. CTA tile 128M x 64N, 8 warps (4m x 2n),
// warp tile 32M x 32N, mma m16n8k16 bf16: mt=2, nt=4.
// Ws resident (bf16x2 rows k2): Ws[k2][ ((wn*32 + g*4) ^ (8*(k2&3))) + nt ].
// Ar staged per chunk (bf16x2): Ar[k2][ m ^ (8*(k2&3)) ].

// stage one 32-row (64k) x 128m packed A chunk: 1024 cp16 / 256 thr = 4 each
__device__ __forceinline__ void stage_A(uint32_t* dst, const uint32_t* __restrict__ src, int tid)
{
    #pragma unroll
    for (int i = 0; i < 4; i++) {
        int f4 = tid + i * NTHR;        // 0..1023
        int kq = f4 >> 5;               // 0..31 packed rows
        int c4 = f4 & 31;               // 0..31
        int col = (c4 * 4) ^ ((kq & 3) * 8);
        cp16(smem_u32(dst + kq * 128 + col), src + (size_t)kq * BATCH + c4 * 4);
    }
}

template <bool L1P, bool DUAL>
__device__ __forceinline__ void gemm_phase(
    const uint32_t* __restrict__ Ws,   // weight rows (k2-base applied)
    uint32_t* __restrict__ Ar,
    int K2,                            // packed k rows: 128 (L1) or 256 (L2)
    const uint32_t* __restrict__ A0,   // packed h [u2][b] + m0
    const uint32_t* __restrict__ A1,   // second source for DUAL (k2 >= 128) + m0
    float* __restrict__ cs, uint32_t* __restrict__ houtp,
    const int* __restrict__ tokens, int t, int m0, int n0)
{
    const int tid  = threadIdx.x;
    const int lane = tid & 31;
    const int wid  = tid >> 5;
    const int s    = lane & 3;
    const int g    = lane >> 2;
    const int wm   = wid & 3;
    const int wn   = wid >> 2;

    const int cm0  = (wm * 32 + g) ^ (8 * s);
    const int cb   = (wn * 32 + g * 4) ^ (8 * s);

    float acc[2][4][4];
    #pragma unroll
    for (int a = 0; a < 2; a++)
        #pragma unroll
        for (int b = 0; b < 4; b++)
            #pragma unroll
            for (int c = 0; c < 4; c++) acc[a][b][c] = 0.0f;

    stage_A(Ar, A0, tid);
    cp_commit();

    const int C = K2 / KC2;
    for (int c = 0; c < C; c++) {
        int cur = c & 1;
        if (c + 1 < C) {
            int r0 = (c + 1) * KC2;
            const uint32_t* srcn = (DUAL && r0 >= 128) ?
                                   A1 + (size_t)(r0 - 128) * BATCH :
                                   A0 + (size_t)r0 * BATCH;
            stage_A(Ar + (1 - cur) * (KC2 * 128), srcn, tid);
            cp_commit();
            cp_wait1();
        } else {
            cp_wait0();
        }
        __syncthreads();

        const uint32_t* Ab = Ar + cur * (KC2 * 128) + s * 128;
        const uint32_t* Bb = Ws + ((size_t)(c * KC2) + s) * 64 + cb;

        #pragma unroll
        for (int sl = 0; sl < KC2 / 8; sl++) {          // 4 slabs of k16
            const uint32_t* ap = Ab + sl * (8 * 128);
            const uint32_t* bp = Bb + sl * (8 * 64);
            uint4 b0 = *(const uint4*)bp;               // k2 = s
            uint4 b1 = *(const uint4*)(bp + 4 * 64);    // k2 = s+4
            uint32_t bf[4][2] = {
                { b0.x, b1.x }, { b0.y, b1.y }, { b0.z, b1.z }, { b0.w, b1.w }
            };
            #pragma unroll
            for (int mt = 0; mt < 2; mt++) {
                const int cc = cm0 ^ (mt * 16);
                uint32_t af[4];
                af[0] = ap[cc];
                af[1] = ap[cc ^ 8];
                af[2] = ap[4 * 128 + cc];
                af[3] = ap[4 * 128 + (cc ^ 8)];
                #pragma unroll
                for (int nt = 0; nt < 4; nt++)
                    mma_bf16(acc[mt][nt], af, bf[nt]);
            }
        }
        __syncthreads();
    }

    // ---- fused LSTM epilogue ----
    // acc[mt][nt]: c0=(row g, col 2s), c1=(g,2s+1), c2=(g+8,2s), c3=(g+8,2s+1)
    // shfl-xor-1: combine (f,i)/(ctilde,o); shfl-xor-2: pack h unit pairs.
    #pragma unroll
    for (int mt = 0; mt < 2; mt++) {
        const int m = m0 + wm * 32 + mt * 16 + g + ((lane & 1) << 3);
        int tok = 0;
        if (L1P) tok = tokens[m * TSTEPS + t];
        #pragma unroll
        for (int nt = 0; nt < 4; nt++) {
            float* a = acc[mt][nt];
            float v1 = __shfl_xor_sync(0xFFFFFFFFu, (lane & 1) ? a[0] : a[2], 1);
            float v2 = __shfl_xor_sync(0xFFFFFFFFu, (lane & 1) ? a[1] : a[3], 1);
            float pf, pi, pc, po;
            if (lane & 1) { pc = a[2]; po = a[3]; pf = v1; pi = v2; }
            else          { pf = a[0]; pi = a[1]; pc = v1; po = v2; }

            const int nb = n0 + wn * 32 + nt * 8;
            const int u  = (nb >> 2) + (s >> 1);
            if (L1P) {
                float4 x = *(const float4*)&g_embW[(size_t)tok * NG + u * 4];
                pf += x.x; pi += x.y; pc += x.z; po += x.w;
            } else {
                float4 bv = *(const float4*)&g_b2[u * 4];
                pf += bv.x; pi += bv.y; pc += bv.z; po += bv.w;
            }
            float cold = cs[(size_t)u * BATCH + m];
            float cn = sigmoid_ap(pf) * cold + sigmoid_ap(pi) * tanh_ap(pc);
            cs[(size_t)u * BATCH + m] = cn;
            float hn = sigmoid_ap(po) * tanh_ap(cn);
            // pack unit pair (u even in lanes s<2, u odd in lanes s>=2)
            float ho = __shfl_xor_sync(0xFFFFFFFFu, hn, 2);
            if ((lane & 2) == 0) {
                const int u2 = nb >> 3;
                houtp[(size_t)u2 * BATCH + m] = pack_bf2(hn, ho);
            }
        }
    }
}

__global__ __launch_bounds__(NTHR, 1) void lstm_persistent(
    const int* __restrict__ tokens,
    const float* __restrict__ w_out, const float* __restrict__ b_out,
    float* __restrict__ out)
{
    extern __shared__ __align__(16) uint32_t smem[];
    uint32_t* Ws = smem;                 // [384][64]: rows 0-127 W1h, 128-383 W2
    uint32_t* Ar = smem + WS_U32;        // [2][32][128]

    const int cta = blockIdx.x;
    const int n0  = (cta & 15) * 64;
    const int m0  = (cta >> 4) * 128;
    const int tid = threadIdx.x;

    // ---- load resident weight slices (packed + swizzled) ----
    for (int idx = tid; idx < 384 * 64; idx += NTHR) {
        int k2 = idx >> 6;
        int nl = idx & 63;
        int wn = nl >> 5, r = nl & 31, g = r & 7, nt = r >> 3;
        int dst = k2 * 64 + (((wn << 5) + (g << 2)) ^ ((k2 & 3) << 3)) + nt;
        uint32_t v = (k2 < 128) ? g_W1hp[(size_t)k2 * NG + n0 + nl]
                                : g_W2p[(size_t)(k2 - 128) * NG + n0 + nl];
        Ws[dst] = v;
    }
    __syncthreads();

    const uint32_t* Ws2 = Ws + 128 * 64;

    // prologue: layer1 t=0 (h1 zeros in g_h1p[0]) -> h1(0) into g_h1p[1]
    gemm_phase<true, false>(Ws, Ar, 128, g_h1p[0] + m0, g_h1p[0] + m0,
                            g_c1, g_h1p[1], tokens, 0, m0, n0);
    grid_barrier();

    for (int t = 0; t < TSTEPS; t++) {
        // layer2(t): A = [h2(t-1) | h1(t)]
        gemm_phase<false, true>(Ws2, Ar, 256,
                                g_h2p[t & 1] + m0, g_h1p[(t + 1) & 1] + m0,
                                g_c2, g_h2p[(t + 1) & 1], tokens, t, m0, n0);
        // layer1(t+1): A = h1(t)
        if (t < TSTEPS - 1)
            gemm_phase<true, false>(Ws, Ar, 128,
                                    g_h1p[(t + 1) & 1] + m0, g_h1p[0] + m0,
                                    g_c1, g_h1p[t & 1], tokens, t + 1, m0, n0);
        grid_barrier();
    }

    // final dense + sigmoid; h2(79) packed in g_h2p[0]
    int gw   = cta * (NTHR / 32) + (tid >> 5);
    int lane = tid & 31;
    if (gw < BATCH / 32) {
        int bb = gw * 32 + lane;
        float s = 0.0f;
        const uint32_t* h = g_h2p[0];
        #pragma unroll 8
        for (int u2 = 0; u2 < UDIM / 2; u2++) {
            uint32_t v = h[(size_t)u2 * BATCH + bb];
            float lo = __bfloat162float(__ushort_as_bfloat16((unsigned short)(v & 0xFFFF)));
            float hi = __bfloat162float(__ushort_as_bfloat16((unsigned short)(v >> 16)));
            s += lo * w_out[2 * u2] + hi * w_out[2 * u2 + 1];
        }
        out[bb] = 1.0f / (1.0f + expf(-(s + b_out[0])));
    }
}

// ---------------- launch ----------------
extern "C" void kernel_launch(void* const* d_in, const int* in_sizes, int n_in,
                              void* d_out, int out_size)
{
    const int*   tokens = (const int*)  d_in[0];
    const float* emb    = (const float*)d_in[1];
    const float* wf1 = (const float*)d_in[2];  const float* bf1 = (const float*)d_in[3];
    const float* wi1 = (const float*)d_in[4];  const float* bi1 = (const float*)d_in[5];
    const float* wc1 = (const float*)d_in[6];  const float* bc1 = (const float*)d_in[7];
    const float* wo1 = (const float*)d_in[8];  const float* bo1 = (const float*)d_in[9];
    const float* wf2 = (const float*)d_in[10]; const float* bf2 = (const float*)d_in[11];
    const float* wi2 = (const float*)d_in[12]; const float* bi2 = (const float*)d_in[13];
    const float* wc2 = (const float*)d_in[14]; const float* bc2 = (const float*)d_in[15];
    const float* wo2 = (const float*)d_in[16]; const float* bo2 = (const float*)d_in[17];
    const float* w_out = (const float*)d_in[18];
    const float* b_out = (const float*)d_in[19];
    float* out = (float*)d_out;

    static int smem_set = 0;
    if (!smem_set) {
        cudaFuncSetAttribute(lstm_persistent,
                             cudaFuncAttributeMaxDynamicSharedMemorySize, SMEM_BYTES);
        smem_set = 1;
    }

    const int TOT = 384 * NG + EDIM * NG + 2 * NG;
    pack_kernel<<<(TOT + 255) / 256, 256>>>(wf1, bf1, wi1, bi1, wc1, bc1, wo1, bo1,
                                            wf2, bf2, wi2, bi2, wc2, bc2, wo2, bo2);
    zero_kernel<<<(UDIM * BATCH + 255) / 256, 256>>>();

    embw_kernel<<<dim3(NG / 64, (VOCAB + 63) / 64), 256>>>(emb);

    lstm_persistent<<<GRID_CTAS, NTHR, SMEM_BYTES>>>(tokens, w_out, b_out, out);
}

// round 11
// speedup vs baseline: 5.1102x; 1.0728x over previous
#include <cuda_runtime.h>
#include <cuda_bf16.h>
#include <math.h>
#include <stdint.h>

#define BATCH 1024
#define TSTEPS 80
#define EDIM 100
#define UDIM 256
#define NG 1024       // 4 gates * U, packed n = u*4 + g
#define VOCAB 10000
#define GRID_CTAS 128
#define NTHR 256

// packed k-pair rows: Layer1 = 128, Layer2 = 256. Chunk = 64 rows (128 k).
#define KC2 64

// CTA tile: 64 M x 128 N. smem: Ws[384][128] bf16x2 (192KB) + Ar[2][64][64] (32KB)
#define WS_U32 (384 * 128)
#define AR_U32 (2 * KC2 * 64)
#define SMEM_BYTES ((WS_U32 + AR_U32) * 4)   // 229376 B

// ---------------- persistent device scratch ----------------
__device__ __align__(16) uint32_t g_W1hp[128 * NG];        // bf16x2 [k2][n]
__device__ __align__(16) uint32_t g_W2p [256 * NG];        // bf16x2 [k2][n]
__device__ __align__(16) float g_W1x[EDIM * NG];           // fp32 exact, [k][n]
__device__ __align__(16) float g_b1[NG];
__device__ __align__(16) float g_b2[NG];
__device__ __align__(16) float g_embW[(size_t)VOCAB * NG]; // fp32 exact: emb@W1x + b1
// h states packed bf16x2 unit pairs: [u2][batch]
__device__ __align__(16) uint32_t g_h1p[2][(UDIM / 2) * BATCH];
__device__ __align__(16) uint32_t g_h2p[2][(UDIM / 2) * BATCH];
__device__ __align__(16) float g_c1[UDIM * BATCH];
__device__ __align__(16) float g_c2[UDIM * BATCH];
__device__ unsigned g_bar_count = 0;
__device__ volatile unsigned g_bar_gen = 0;

__device__ __forceinline__ float tanh_ap(float x) {
    float r; asm("tanh.approx.f32 %0, %1;" : "=f"(r) : "f"(x)); return r;
}
__device__ __forceinline__ float sigmoid_ap(float x) {
    return 0.5f * tanh_ap(0.5f * x) + 0.5f;
}
__device__ __forceinline__ uint32_t pack_bf2(float lo, float hi) {
    unsigned l = __bfloat16_as_ushort(__float2bfloat16_rn(lo));
    unsigned h = __bfloat16_as_ushort(__float2bfloat16_rn(hi));
    return l | (h << 16);
}
__device__ __forceinline__ uint32_t smem_u32(const void* p) {
    uint32_t a;
    asm("{ .reg .u64 t; cvta.to.shared.u64 t, %1; cvt.u32.u64 %0, t; }" : "=r"(a) : "l"(p));
    return a;
}
__device__ __forceinline__ void cp16(uint32_t dst, const void* src) {
    asm volatile("cp.async.cg.shared.global [%0], [%1], 16;" :: "r"(dst), "l"(src));
}
__device__ __forceinline__ void cp_commit() { asm volatile("cp.async.commit_group;"); }
__device__ __forceinline__ void cp_wait1()  { asm volatile("cp.async.wait_group 1;"); }
__device__ __forceinline__ void cp_wait0()  { asm volatile("cp.async.wait_group 0;"); }

__device__ __forceinline__ void mma_bf16(float* c, const uint32_t* a, const uint32_t* b) {
    asm volatile(
        "mma.sync.aligned.m16n8k16.row.col.f32.bf16.bf16.f32 "
        "{%0,%1,%2,%3}, {%4,%5,%6,%7}, {%8,%9}, {%0,%1,%2,%3};"
        : "+f"(c[0]), "+f"(c[1]), "+f"(c[2]), "+f"(c[3])
        : "r"(a[0]), "r"(a[1]), "r"(a[2]), "r"(a[3]), "r"(b[0]), "r"(b[1]));
}

// ---------------- software grid barrier ----------------
__device__ __forceinline__ void grid_barrier() {
    __syncthreads();
    if (threadIdx.x == 0) {
        __threadfence();
        unsigned gen = g_bar_gen;
        if (atomicAdd(&g_bar_count, 1u) == GRID_CTAS - 1) {
            g_bar_count = 0;
            __threadfence();
            g_bar_gen = gen + 1;
        } else {
            while (g_bar_gen == gen) { }
            __threadfence();
        }
    }
    __syncthreads();
}

// ---------------- pack: n = u*4+g; recurrent W as bf16x2 k-pairs; W1x exact ----------------
__global__ void pack_kernel(
    const float* wf1, const float* bf1, const float* wi1, const float* bi1,
    const float* wc1, const float* bc1, const float* wo1, const float* bo1,
    const float* wf2, const float* bf2, const float* wi2, const float* bi2,
    const float* wc2, const float* bc2, const float* wo2, const float* bo2)
{
    const int TOT_P = 384 * NG;
    const int TOT_X = EDIM * NG;
    int id = blockIdx.x * blockDim.x + threadIdx.x;
    if (id < TOT_P) {
        int k2 = id >> 10;
        int n  = id & 1023;
        int u  = n >> 2;
        int g  = n & 3;
        if (k2 < 128) {
            const float* w = (g == 0) ? wf1 : (g == 1) ? wi1 : (g == 2) ? wc1 : wo1;
            g_W1hp[k2 * NG + n] = pack_bf2(w[(2 * k2) * UDIM + u],
                                           w[(2 * k2 + 1) * UDIM + u]);
        } else {
            int kk = k2 - 128;
            const float* w = (g == 0) ? wf2 : (g == 1) ? wi2 : (g == 2) ? wc2 : wo2;
            g_W2p[kk * NG + n] = pack_bf2(w[(2 * kk) * UDIM + u],
                                          w[(2 * kk + 1) * UDIM + u]);
        }
    } else if (id < TOT_P + TOT_X) {
        int j = id - TOT_P;
        int kk = j >> 10;
        int n  = j & 1023;
        int u  = n >> 2;
        int g  = n & 3;
        const float* w = (g == 0) ? wf1 : (g == 1) ? wi1 : (g == 2) ? wc1 : wo1;
        g_W1x[kk * NG + n] = w[(UDIM + kk) * UDIM + u];
    } else if (id < TOT_P + TOT_X + 2 * NG) {
        int j = id - TOT_P - TOT_X;
        int n = j & 1023;
        int u = n >> 2;
        int g = n & 3;
        if (j < NG) g_b1[n] = ((g == 0) ? bf1 : (g == 1) ? bi1 : (g == 2) ? bc1 : bo1)[u];
        else        g_b2[n] = ((g == 0) ? bf2 : (g == 1) ? bi2 : (g == 2) ? bc2 : bo2)[u];
    }
}

__global__ void zero_kernel()
{
    int id = blockIdx.x * blockDim.x + threadIdx.x;
    if (id < UDIM * BATCH) {
        g_c1[id] = 0.0f;
        g_c2[id] = 0.0f;
    }
    if (id < (UDIM / 2) * BATCH) {
        g_h1p[0][id] = 0u;
        g_h2p[0][id] = 0u;
    }
}

// ---------------- embW = emb @ W1x + b1 (fp32 exact) ----------------
__global__ __launch_bounds__(256) void embw_kernel(const float* __restrict__ emb)
{
    __shared__ __align__(16) float As[32][64];
    __shared__ __align__(16) float Bs[32][64];

    const int tid = threadIdx.x;
    const int m0  = blockIdx.y * 64;
    const int n0  = blockIdx.x * 64;
    const int tm  = tid >> 4;
    const int tn  = tid & 15;

    float acc[4][4] = {};

    for (int k0 = 0; k0 < 128; k0 += 32) {
        #pragma unroll
        for (int i = 0; i < 2; i++) {
            int f4 = tid + i * 256;
            int m  = f4 >> 3;
            int kq = f4 & 7;
            int k  = k0 + kq * 4;
            float4 v = make_float4(0.f, 0.f, 0.f, 0.f);
            int row = m0 + m;
            if (k < EDIM && row < VOCAB)
                v = *(const float4*)&emb[(size_t)row * EDIM + k];
            As[kq * 4 + 0][m] = v.x;
            As[kq * 4 + 1][m] = v.y;
            As[kq * 4 + 2][m] = v.z;
            As[kq * 4 + 3][m] = v.w;
        }
        #pragma unroll
        for (int i = 0; i < 2; i++) {
            int f4 = tid + i * 256;
            int kk = f4 >> 4;
            int c4 = f4 & 15;
            int k  = k0 + kk;
            float4 v = make_float4(0.f, 0.f, 0.f, 0.f);
            if (k < EDIM) v = *(const float4*)&g_W1x[k * NG + n0 + c4 * 4];
            *(float4*)&Bs[kk][c4 * 4] = v;
        }
        __syncthreads();

        #pragma unroll
        for (int k = 0; k < 32; k++) {
            float4 b = *(const float4*)&Bs[k][tn * 4];
            float4 a = *(const float4*)&As[k][tm * 4];
            float ar[4] = {a.x, a.y, a.z, a.w};
            float br[4] = {b.x, b.y, b.z, b.w};
            #pragma unroll
            for (int r = 0; r < 4; r++)
                #pragma unroll
                for (int c = 0; c < 4; c++)
                    acc[r][c] += ar[r] * br[c];
        }
        __syncthreads();
    }

    float4 bb = *(const float4*)&g_b1[n0 + tn * 4];
    #pragma unroll
    for (int r = 0; r < 4; r++) {
        int row = m0 + tm * 4 + r;
        if (row < VOCAB)
            *(float4*)&g_embW[(size_t)row * NG + n0 + tn * 4] =
                make_float4(acc[r][0] + bb.x, acc[r][1] + bb.y,
                            acc[r][2] + bb.z, acc[r][3] + bb.w);
    }
}

// ---------------- persistent kernel ----------------
// Grid 128 = 16 m-tiles x 8 n-tiles. CTA tile 64M x 128N, 8 warps (2m x 4n),
// warp tile 32M x 32N, mma m16n8k16 bf16: mt=2, nt=4.
// Ws resident: Ws[k2][ ((wn*32 + g*4) ^ (8*(k2&3))) + nt ], row stride 128.
// Ar staged per 64-row chunk: Ar[k2][ m ^ (8*(k2&3)) ], row stride 64.

// stage one 64-row x 64m packed A chunk: 1024 cp16 / 256 thr = 4 each
__device__ __forceinline__ void stage_A(uint32_t* dst, const uint32_t* __restrict__ src, int tid)
{
    #pragma unroll
    for (int i = 0; i < 4; i++) {
        int f4 = tid + i * NTHR;        // 0..1023
        int kq = f4 >> 4;               // 0..63 packed rows
        int c4 = f4 & 15;               // 0..15
        int col = (c4 * 4) ^ ((kq & 3) * 8);
        cp16(smem_u32(dst + kq * 64 + col), src + (size_t)kq * BATCH + c4 * 4);
    }
}

template <bool L1P, bool DUAL, bool ZERO>
__device__ __forceinline__ void gemm_phase(
    const uint32_t* __restrict__ Ws,   // weight rows (k2-base applied), stride 128
    uint32_t* __restrict__ Ar,
    int K2,                            // packed k rows: 128 (L1) or 256 (L2)
    const uint32_t* __restrict__ A0,   // packed h [u2][b] + m0
    const uint32_t* __restrict__ A1,   // second source for DUAL (k2 >= 128) + m0
    float* __restrict__ cs, uint32_t* __restrict__ houtp,
    const int* __restrict__ tokens, int t, int m0, int n0)
{
    const int tid  = threadIdx.x;
    const int lane = tid & 31;
    const int wid  = tid >> 5;
    const int s    = lane & 3;
    const int g    = lane >> 2;
    const int wm   = wid & 1;          // 2 m-warps
    const int wn   = wid >> 1;         // 4 n-warps

    const int cm0  = (wm * 32 + g) ^ (8 * s);
    const int cb   = (wn * 32 + g * 4) ^ (8 * s);

    float acc[2][4][4];
    #pragma unroll
    for (int a = 0; a < 2; a++)
        #pragma unroll
        for (int b = 0; b < 4; b++)
            #pragma unroll
            for (int c = 0; c < 4; c++) acc[a][b][c] = 0.0f;

    if (!ZERO) {
        stage_A(Ar, A0, tid);
        cp_commit();

        const int C = K2 / KC2;        // 2 (L1) or 4 (L2)
        for (int c = 0; c < C; c++) {
            int cur = c & 1;
            if (c + 1 < C) {
                int r0 = (c + 1) * KC2;
                const uint32_t* srcn = (DUAL && r0 >= 128) ?
                                       A1 + (size_t)(r0 - 128) * BATCH :
                                       A0 + (size_t)r0 * BATCH;
                stage_A(Ar + (1 - cur) * (KC2 * 64), srcn, tid);
                cp_commit();
                cp_wait1();
            } else {
                cp_wait0();
            }
            __syncthreads();

            const uint32_t* Ab = Ar + cur * (KC2 * 64) + s * 64;
            const uint32_t* Bb = Ws + ((size_t)(c * KC2) + s) * 128 + cb;

            #pragma unroll
            for (int sl = 0; sl < KC2 / 8; sl++) {       // 8 slabs of k16
                const uint32_t* ap = Ab + sl * (8 * 64);
                const uint32_t* bp = Bb + sl * (8 * 128);
                uint4 b0 = *(const uint4*)bp;            // k2 = s
                uint4 b1 = *(const uint4*)(bp + 4 * 128);// k2 = s+4
                uint32_t bf[4][2] = {
                    { b0.x, b1.x }, { b0.y, b1.y }, { b0.z, b1.z }, { b0.w, b1.w }
                };
                #pragma unroll
                for (int mt = 0; mt < 2; mt++) {
                    const int cc = cm0 ^ (mt * 16);
                    uint32_t af[4];
                    af[0] = ap[cc];
                    af[1] = ap[cc ^ 8];
                    af[2] = ap[4 * 64 + cc];
                    af[3] = ap[4 * 64 + (cc ^ 8)];
                    #pragma unroll
                    for (int nt = 0; nt < 4; nt++)
                        mma_bf16(acc[mt][nt], af, bf[nt]);
                }
            }
            __syncthreads();
        }
    }

    // ---- fused LSTM epilogue ----
    // acc[mt][nt]: c0=(row g, col 2s), c1=(g,2s+1), c2=(g+8,2s), c3=(g+8,2s+1)
    // shfl-xor-1 combines (f,i)/(ctilde,o); shfl-xor-2 packs unit pairs.
    #pragma unroll
    for (int mt = 0; mt < 2; mt++) {
        const int m = m0 + wm * 32 + mt * 16 + g + ((lane & 1) << 3);
        int tok = 0;
        if (L1P) tok = tokens[m * TSTEPS + t];
        #pragma unroll
        for (int nt = 0; nt < 4; nt++) {
            float* a = acc[mt][nt];
            float v1 = __shfl_xor_sync(0xFFFFFFFFu, (lane & 1) ? a[0] : a[2], 1);
            float v2 = __shfl_xor_sync(0xFFFFFFFFu, (lane & 1) ? a[1] : a[3], 1);
            float pf, pi, pc, po;
            if (lane & 1) { pc = a[2]; po = a[3]; pf = v1; pi = v2; }
            else          { pf = a[0]; pi = a[1]; pc = v1; po = v2; }

            const int nb = n0 + wn * 32 + nt * 8;
            const int u  = (nb >> 2) + (s >> 1);
            if (L1P) {
                float4 x = *(const float4*)&g_embW[(size_t)tok * NG + u * 4];
                pf += x.x; pi += x.y; pc += x.z; po += x.w;
            } else {
                float4 bv = *(const float4*)&g_b2[u * 4];
                pf += bv.x; pi += bv.y; pc += bv.z; po += bv.w;
            }
            float cold = cs[(size_t)u * BATCH + m];
            float cn = sigmoid_ap(pf) * cold + sigmoid_ap(pi) * tanh_ap(pc);
            cs[(size_t)u * BATCH + m] = cn;
            float hn = sigmoid_ap(po) * tanh_ap(cn);
            float ho = __shfl_xor_sync(0xFFFFFFFFu, hn, 2);
            if ((lane & 2) == 0) {
                const int u2 = nb >> 3;
                houtp[(size_t)u2 * BATCH + m] = pack_bf2(hn, ho);
            }
        }
    }
}

__global__ __launch_bounds__(NTHR, 1) void lstm_persistent(
    const int* __restrict__ tokens,
    const float* __restrict__ w_out, const float* __restrict__ b_out,
    float* __restrict__ out)
{
    extern __shared__ __align__(16) uint32_t smem[];
    uint32_t* Ws = smem;                 // [384][128]: rows 0-127 W1h, 128-383 W2
    uint32_t* Ar = smem + WS_U32;        // [2][64][64]

    const int cta = blockIdx.x;
    const int n0  = (cta & 7) * 128;     // 8 n-tiles
    const int m0  = (cta >> 3) * 64;     // 16 m-tiles
    const int tid = threadIdx.x;

    // ---- load resident weight slices (packed + swizzled), one time ----
    for (int idx = tid; idx < 384 * 128; idx += NTHR) {
        int k2 = idx >> 7;
        int nl = idx & 127;
        int wn = nl >> 5, r = nl & 31, g = r & 7, nt = r >> 3;
        int dst = k2 * 128 + (((wn << 5) + (g << 2)) ^ ((k2 & 3) << 3)) + nt;
        uint32_t v = (k2 < 128) ? g_W1hp[(size_t)k2 * NG + n0 + nl]
                                : g_W2p[(size_t)(k2 - 128) * NG + n0 + nl];
        Ws[dst] = v;
    }
    __syncthreads();

    const uint32_t* Ws2 = Ws + 128 * 128;

    // prologue: layer1 t=0 with h1 = 0  ->  gates = embW gather only (no GEMM)
    gemm_phase<true, false, true>(Ws, Ar, 128, g_h1p[0] + m0, g_h1p[0] + m0,
                                  g_c1, g_h1p[1], tokens, 0, m0, n0);
    grid_barrier();

    for (int t = 0; t < TSTEPS; t++) {
        // layer2(t): A = [h2(t-1) | h1(t)]
        gemm_phase<false, true, false>(Ws2, Ar, 256,
                                       g_h2p[t & 1] + m0, g_h1p[(t + 1) & 1] + m0,
                                       g_c2, g_h2p[(t + 1) & 1], tokens, t, m0, n0);
        // layer1(t+1): A = h1(t)
        if (t < TSTEPS - 1)
            gemm_phase<true, false, false>(Ws, Ar, 128,
                                           g_h1p[(t + 1) & 1] + m0, g_h1p[0] + m0,
                                           g_c1, g_h1p[t & 1], tokens, t + 1, m0, n0);
        grid_barrier();
    }

    // final dense + sigmoid; h2(79) packed in g_h2p[0]
    int gw   = cta * (NTHR / 32) + (tid >> 5);
    int lane = tid & 31;
    if (gw < BATCH / 32) {
        int bb = gw * 32 + lane;
        float s = 0.0f;
        const uint32_t* h = g_h2p[0];
        #pragma unroll 8
        for (int u2 = 0; u2 < UDIM / 2; u2++) {
            uint32_t v = h[(size_t)u2 * BATCH + bb];
            float lo = __bfloat162float(__ushort_as_bfloat16((unsigned short)(v & 0xFFFF)));
            float hi = __bfloat162float(__ushort_as_bfloat16((unsigned short)(v >> 16)));
            s += lo * w_out[2 * u2] + hi * w_out[2 * u2 + 1];
        }
        out[bb] = 1.0f / (1.0f + expf(-(s + b_out[0])));
    }
}

// ---------------- launch ----------------
extern "C" void kernel_launch(void* const* d_in, const int* in_sizes, int n_in,
                              void* d_out, int out_size)
{
    const int*   tokens = (const int*)  d_in[0];
    const float* emb    = (const float*)d_in[1];
    const float* wf1 = (const float*)d_in[2];  const float* bf1 = (const float*)d_in[3];
    const float* wi1 = (const float*)d_in[4];  const float* bi1 = (const float*)d_in[5];
    const float* wc1 = (const float*)d_in[6];  const float* bc1 = (const float*)d_in[7];
    const float* wo1 = (const float*)d_in[8];  const float* bo1 = (const float*)d_in[9];
    const float* wf2 = (const float*)d_in[10]; const float* bf2 = (const float*)d_in[11];
    const float* wi2 = (const float*)d_in[12]; const float* bi2 = (const float*)d_in[13];
    const float* wc2 = (const float*)d_in[14]; const float* bc2 = (const float*)d_in[15];
    const float* wo2 = (const float*)d_in[16]; const float* bo2 = (const float*)d_in[17];
    const float* w_out = (const float*)d_in[18];
    const float* b_out = (const float*)d_in[19];
    float* out = (float*)d_out;

    static int smem_set = 0;
    if (!smem_set) {
        cudaFuncSetAttribute(lstm_persistent,
                             cudaFuncAttributeMaxDynamicSharedMemorySize, SMEM_BYTES);
        smem_set = 1;
    }

    const int TOT = 384 * NG + EDIM * NG + 2 * NG;
    pack_kernel<<<(TOT + 255) / 256, 256>>>(wf1, bf1, wi1, bi1, wc1, bc1, wo1, bo1,
                                            wf2, bf2, wi2, bi2, wc2, bc2, wo2, bo2);
    zero_kernel<<<(UDIM * BATCH + 255) / 256, 256>>>();

    embw_kernel<<<dim3(NG / 64, (VOCAB + 63) / 64), 256>>>(emb);

    lstm_persistent<<<GRID_CTAS, NTHR, SMEM_BYTES>>>(tokens, w_out, b_out, out);
}

// round 12
// speedup vs baseline: 5.3841x; 1.0536x over previous
#include <cuda_runtime.h>
#include <cuda_bf16.h>
#include <math.h>
#include <stdint.h>

#define BATCH 1024
#define TSTEPS 80
#define EDIM 100
#define UDIM 256
#define NG 1024       // 4 gates * U, packed n = u*4 + g
#define VOCAB 10000
#define GRID_CTAS 128
#define NTHR 256

// packed k-pair rows: Layer1 = 128, Layer2 = 256. Chunk = 64 rows (128 k).
#define KC2 64

// CTA tile: 128 M x 128 N. smem: Ws[<=256][128] bf16x2 (<=128KB) + Ar[2][64][128] (64KB)
#define WS_U32_MAX (256 * 128)
#define AR_U32 (2 * KC2 * 128)
#define SMEM_BYTES ((WS_U32_MAX + AR_U32) * 4)   // 196608 B

// ---------------- persistent device scratch ----------------
__device__ __align__(16) uint32_t g_W1hp[128 * NG];        // bf16x2 [k2][n]
__device__ __align__(16) uint32_t g_W2p [256 * NG];        // bf16x2 [k2][n]
__device__ __align__(16) float g_W1x[EDIM * NG];           // fp32 exact, [k][n]
__device__ __align__(16) float g_b1[NG];
__device__ __align__(16) float g_b2[NG];
__device__ __align__(16) float g_embW[(size_t)VOCAB * NG]; // fp32 exact: emb@W1x + b1
// h states packed bf16x2 unit pairs: [u2][batch]
__device__ __align__(16) uint32_t g_h1p[2][(UDIM / 2) * BATCH];
__device__ __align__(16) uint32_t g_h2p[2][(UDIM / 2) * BATCH];
__device__ __align__(16) float g_c1[UDIM * BATCH];
__device__ __align__(16) float g_c2[UDIM * BATCH];
__device__ unsigned g_bar_count = 0;
__device__ volatile unsigned g_bar_gen = 0;

__device__ __forceinline__ float tanh_ap(float x) {
    float r; asm("tanh.approx.f32 %0, %1;" : "=f"(r) : "f"(x)); return r;
}
__device__ __forceinline__ float sigmoid_ap(float x) {
    return 0.5f * tanh_ap(0.5f * x) + 0.5f;
}
__device__ __forceinline__ uint32_t pack_bf2(float lo, float hi) {
    unsigned l = __bfloat16_as_ushort(__float2bfloat16_rn(lo));
    unsigned h = __bfloat16_as_ushort(__float2bfloat16_rn(hi));
    return l | (h << 16);
}
__device__ __forceinline__ uint32_t smem_u32(const void* p) {
    uint32_t a;
    asm("{ .reg .u64 t; cvta.to.shared.u64 t, %1; cvt.u32.u64 %0, t; }" : "=r"(a) : "l"(p));
    return a;
}
__device__ __forceinline__ void cp16(uint32_t dst, const void* src) {
    asm volatile("cp.async.cg.shared.global [%0], [%1], 16;" :: "r"(dst), "l"(src));
}
__device__ __forceinline__ void cp_commit() { asm volatile("cp.async.commit_group;"); }
__device__ __forceinline__ void cp_wait1()  { asm volatile("cp.async.wait_group 1;"); }
__device__ __forceinline__ void cp_wait0()  { asm volatile("cp.async.wait_group 0;"); }

__device__ __forceinline__ void mma_bf16(float* c, const uint32_t* a, const uint32_t* b) {
    asm volatile(
        "mma.sync.aligned.m16n8k16.row.col.f32.bf16.bf16.f32 "
        "{%0,%1,%2,%3}, {%4,%5,%6,%7}, {%8,%9}, {%0,%1,%2,%3};"
        : "+f"(c[0]), "+f"(c[1]), "+f"(c[2]), "+f"(c[3])
        : "r"(a[0]), "r"(a[1]), "r"(a[2]), "r"(a[3]), "r"(b[0]), "r"(b[1]));
}

// ---------------- software grid barrier ----------------
__device__ __forceinline__ void grid_barrier() {
    __syncthreads();
    if (threadIdx.x == 0) {
        __threadfence();
        unsigned gen = g_bar_gen;
        if (atomicAdd(&g_bar_count, 1u) == GRID_CTAS - 1) {
            g_bar_count = 0;
            __threadfence();
            g_bar_gen = gen + 1;
        } else {
            while (g_bar_gen == gen) { }
            __threadfence();
        }
    }
    __syncthreads();
}

// ---------------- pack: n = u*4+g; recurrent W as bf16x2 k-pairs; W1x exact ----------------
__global__ void pack_kernel(
    const float* wf1, const float* bf1, const float* wi1, const float* bi1,
    const float* wc1, const float* bc1, const float* wo1, const float* bo1,
    const float* wf2, const float* bf2, const float* wi2, const float* bi2,
    const float* wc2, const float* bc2, const float* wo2, const float* bo2)
{
    const int TOT_P = 384 * NG;
    const int TOT_X = EDIM * NG;
    int id = blockIdx.x * blockDim.x + threadIdx.x;
    if (id < TOT_P) {
        int k2 = id >> 10;
        int n  = id & 1023;
        int u  = n >> 2;
        int g  = n & 3;
        if (k2 < 128) {
            const float* w = (g == 0) ? wf1 : (g == 1) ? wi1 : (g == 2) ? wc1 : wo1;
            g_W1hp[k2 * NG + n] = pack_bf2(w[(2 * k2) * UDIM + u],
                                           w[(2 * k2 + 1) * UDIM + u]);
        } else {
            int kk = k2 - 128;
            const float* w = (g == 0) ? wf2 : (g == 1) ? wi2 : (g == 2) ? wc2 : wo2;
            g_W2p[kk * NG + n] = pack_bf2(w[(2 * kk) * UDIM + u],
                                          w[(2 * kk + 1) * UDIM + u]);
        }
    } else if (id < TOT_P + TOT_X) {
        int j = id - TOT_P;
        int kk = j >> 10;
        int n  = j & 1023;
        int u  = n >> 2;
        int g  = n & 3;
        const float* w = (g == 0) ? wf1 : (g == 1) ? wi1 : (g == 2) ? wc1 : wo1;
        g_W1x[kk * NG + n] = w[(UDIM + kk) * UDIM + u];
    } else if (id < TOT_P + TOT_X + 2 * NG) {
        int j = id - TOT_P - TOT_X;
        int n = j & 1023;
        int u = n >> 2;
        int g = n & 3;
        if (j < NG) g_b1[n] = ((g == 0) ? bf1 : (g == 1) ? bi1 : (g == 2) ? bc1 : bo1)[u];
        else        g_b2[n] = ((g == 0) ? bf2 : (g == 1) ? bi2 : (g == 2) ? bc2 : bo2)[u];
    }
}

__global__ void zero_kernel()
{
    int id = blockIdx.x * blockDim.x + threadIdx.x;
    if (id < UDIM * BATCH) {
        g_c1[id] = 0.0f;
        g_c2[id] = 0.0f;
    }
    if (id < (UDIM / 2) * BATCH) {
        g_h1p[0][id] = 0u;
        g_h1p[1][id] = 0u;
        g_h2p[0][id] = 0u;
        g_h2p[1][id] = 0u;
    }
}

// ---------------- embW = emb @ W1x + b1 (fp32 exact) ----------------
__global__ __launch_bounds__(256) void embw_kernel(const float* __restrict__ emb)
{
    __shared__ __align__(16) float As[32][64];
    __shared__ __align__(16) float Bs[32][64];

    const int tid = threadIdx.x;
    const int m0  = blockIdx.y * 64;
    const int n0  = blockIdx.x * 64;
    const int tm  = tid >> 4;
    const int tn  = tid & 15;

    float acc[4][4] = {};

    for (int k0 = 0; k0 < 128; k0 += 32) {
        #pragma unroll
        for (int i = 0; i < 2; i++) {
            int f4 = tid + i * 256;
            int m  = f4 >> 3;
            int kq = f4 & 7;
            int k  = k0 + kq * 4;
            float4 v = make_float4(0.f, 0.f, 0.f, 0.f);
            int row = m0 + m;
            if (k < EDIM && row < VOCAB)
                v = *(const float4*)&emb[(size_t)row * EDIM + k];
            As[kq * 4 + 0][m] = v.x;
            As[kq * 4 + 1][m] = v.y;
            As[kq * 4 + 2][m] = v.z;
            As[kq * 4 + 3][m] = v.w;
        }
        #pragma unroll
        for (int i = 0; i < 2; i++) {
            int f4 = tid + i * 256;
            int kk = f4 >> 4;
            int c4 = f4 & 15;
            int k  = k0 + kk;
            float4 v = make_float4(0.f, 0.f, 0.f, 0.f);
            if (k < EDIM) v = *(const float4*)&g_W1x[k * NG + n0 + c4 * 4];
            *(float4*)&Bs[kk][c4 * 4] = v;
        }
        __syncthreads();

        #pragma unroll
        for (int k = 0; k < 32; k++) {
            float4 b = *(const float4*)&Bs[k][tn * 4];
            float4 a = *(const float4*)&As[k][tm * 4];
            float ar[4] = {a.x, a.y, a.z, a.w};
            float br[4] = {b.x, b.y, b.z, b.w};
            #pragma unroll
            for (int r = 0; r < 4; r++)
                #pragma unroll
                for (int c = 0; c < 4; c++)
                    acc[r][c] += ar[r] * br[c];
        }
        __syncthreads();
    }

    float4 bb = *(const float4*)&g_b1[n0 + tn * 4];
    #pragma unroll
    for (int r = 0; r < 4; r++) {
        int row = m0 + tm * 4 + r;
        if (row < VOCAB)
            *(float4*)&g_embW[(size_t)row * NG + n0 + tn * 4] =
                make_float4(acc[r][0] + bb.x, acc[r][1] + bb.y,
                            acc[r][2] + bb.z, acc[r][3] + bb.w);
    }
}

// ---------------- persistent kernel, split-layer CTA groups ----------------
// CTAs 0-63: layer2 (K2=256). CTAs 64-127: layer1 (K2=128). Both run every step
// concurrently; one grid barrier per step.
// CTA tile 128M x 128N; 8 warps (4m x 2n); warp tile 32M x 64N; mma m16n8k16:
// mt=2, nt=8. Ws row stride 128 u32; A chunk [64 rows][128 m-cols].
// Ws pack: n_local = wn*64 + h*32 + q*8 + g -> dst col ((wn*64+h*32+g*4)^sw)+q.
// Ar: col = m ^ sw, sw = 8*(k2&3).

// stage one 64-row x 128m packed A chunk: 2048 cp16 / 256 thr = 8 each
__device__ __forceinline__ void stage_A(uint32_t* dst, const uint32_t* __restrict__ src, int tid)
{
    #pragma unroll
    for (int i = 0; i < 8; i++) {
        int f4 = tid + i * NTHR;        // 0..2047
        int kq = f4 >> 5;               // 0..63 packed rows
        int c4 = f4 & 31;               // 0..31 (x4 cols = 128)
        int col = (c4 * 4) ^ ((kq & 3) * 8);
        cp16(smem_u32(dst + kq * 128 + col), src + (size_t)kq * BATCH + c4 * 4);
    }
}

template <bool L1P, bool DUAL, bool ZERO>
__device__ __forceinline__ void gemm_phase(
    const uint32_t* __restrict__ Ws,   // resident weights, row stride 128
    uint32_t* __restrict__ Ar,
    int K2,                            // packed k rows: 128 (L1) or 256 (L2)
    const uint32_t* __restrict__ A0,   // packed h [u2][b] + m0 (h2 for DUAL)
    const uint32_t* __restrict__ A1,   // h1 source for DUAL (k2 >= 128) + m0
    float* __restrict__ cs, uint32_t* __restrict__ houtp,
    const int* __restrict__ tokens, int t, int m0, int n0)
{
    const int tid  = threadIdx.x;
    const int lane = tid & 31;
    const int wid  = tid >> 5;
    const int s    = lane & 3;
    const int g    = lane >> 2;
    const int wm   = wid & 3;          // 4 m-warps
    const int wn   = wid >> 2;         // 2 n-warps

    const int cm0  = (wm * 32 + g) ^ (8 * s);
    const int cb   = (wn * 64 + g * 4) ^ (8 * s);

    float acc[2][8][4];
    #pragma unroll
    for (int a = 0; a < 2; a++)
        #pragma unroll
        for (int b = 0; b < 8; b++)
            #pragma unroll
            for (int c = 0; c < 4; c++) acc[a][b][c] = 0.0f;

    if (!ZERO) {
        stage_A(Ar, A0, tid);
        cp_commit();

        const int C = K2 / KC2;        // 2 (L1) or 4 (L2)
        for (int c = 0; c < C; c++) {
            int cur = c & 1;
            if (c + 1 < C) {
                int r0 = (c + 1) * KC2;
                const uint32_t* srcn = (DUAL && r0 >= 128) ?
                                       A1 + (size_t)(r0 - 128) * BATCH :
                                       A0 + (size_t)r0 * BATCH;
                stage_A(Ar + (1 - cur) * (KC2 * 128), srcn, tid);
                cp_commit();
                cp_wait1();
            } else {
                cp_wait0();
            }
            __syncthreads();

            const uint32_t* Ab = Ar + cur * (KC2 * 128) + s * 128;
            const uint32_t* Bb = Ws + ((size_t)(c * KC2) + s) * 128 + cb;

            #pragma unroll
            for (int sl = 0; sl < KC2 / 8; sl++) {       // 8 slabs of k16
                const uint32_t* ap = Ab + sl * (8 * 128);
                const uint32_t* bp = Bb + sl * (8 * 128);
                uint32_t bf[8][2];
                #pragma unroll
                for (int hh = 0; hh < 2; hh++) {
                    uint4 b0 = *(const uint4*)(bp + hh * 32);            // k2 = s
                    uint4 b1 = *(const uint4*)(bp + hh * 32 + 4 * 128);  // k2 = s+4
                    bf[hh * 4 + 0][0] = b0.x; bf[hh * 4 + 0][1] = b1.x;
                    bf[hh * 4 + 1][0] = b0.y; bf[hh * 4 + 1][1] = b1.y;
                    bf[hh * 4 + 2][0] = b0.z; bf[hh * 4 + 2][1] = b1.z;
                    bf[hh * 4 + 3][0] = b0.w; bf[hh * 4 + 3][1] = b1.w;
                }
                #pragma unroll
                for (int mt = 0; mt < 2; mt++) {
                    const int cc = cm0 ^ (mt * 16);
                    uint32_t af[4];
                    af[0] = ap[cc];
                    af[1] = ap[cc ^ 8];
                    af[2] = ap[4 * 128 + cc];
                    af[3] = ap[4 * 128 + (cc ^ 8)];
                    #pragma unroll
                    for (int nt = 0; nt < 8; nt++)
                        mma_bf16(acc[mt][nt], af, bf[nt]);
                }
            }
            __syncthreads();
        }
    }

    // ---- fused LSTM epilogue ----
    // acc[mt][nt]: c0=(row g, col 2s), c1=(g,2s+1), c2=(g+8,2s), c3=(g+8,2s+1)
    // shfl-xor-1 combines (f,i)/(ctilde,o); shfl-xor-2 packs unit pairs.
    #pragma unroll
    for (int mt = 0; mt < 2; mt++) {
        const int m = m0 + wm * 32 + mt * 16 + g + ((lane & 1) << 3);
        int tok = 0;
        if (L1P) tok = tokens[m * TSTEPS + t];
        #pragma unroll
        for (int nt = 0; nt < 8; nt++) {
            float* a = acc[mt][nt];
            float v1 = __shfl_xor_sync(0xFFFFFFFFu, (lane & 1) ? a[0] : a[2], 1);
            float v2 = __shfl_xor_sync(0xFFFFFFFFu, (lane & 1) ? a[1] : a[3], 1);
            float pf, pi, pc, po;
            if (lane & 1) { pc = a[2]; po = a[3]; pf = v1; pi = v2; }
            else          { pf = a[0]; pi = a[1]; pc = v1; po = v2; }

            const int nb = n0 + wn * 64 + nt * 8;
            const int u  = (nb >> 2) + (s >> 1);
            if (L1P) {
                float4 x = *(const float4*)&g_embW[(size_t)tok * NG + u * 4];
                pf += x.x; pi += x.y; pc += x.z; po += x.w;
            } else {
                float4 bv = *(const float4*)&g_b2[u * 4];
                pf += bv.x; pi += bv.y; pc += bv.z; po += bv.w;
            }
            float cold = cs[(size_t)u * BATCH + m];
            float cn = sigmoid_ap(pf) * cold + sigmoid_ap(pi) * tanh_ap(pc);
            cs[(size_t)u * BATCH + m] = cn;
            float hn = sigmoid_ap(po) * tanh_ap(cn);
            float ho = __shfl_xor_sync(0xFFFFFFFFu, hn, 2);
            if ((lane & 2) == 0) {
                const int u2 = nb >> 3;
                houtp[(size_t)u2 * BATCH + m] = pack_bf2(hn, ho);
            }
        }
    }
}

__global__ __launch_bounds__(NTHR, 1) void lstm_persistent(
    const int* __restrict__ tokens,
    const float* __restrict__ w_out, const float* __restrict__ b_out,
    float* __restrict__ out)
{
    extern __shared__ __align__(16) uint32_t smem[];
    uint32_t* Ws = smem;                 // L2 group: [256][128]; L1 group: [128][128]
    uint32_t* Ar;                        // set per group below

    const int cta  = blockIdx.x;
    const bool L2G = (cta < 64);
    const int n0   = (cta & 7) * 128;        // 8 n-tiles within the group's gate space
    const int m0   = ((cta >> 3) & 7) * 128; // 8 m-tiles
    const int tid  = threadIdx.x;

    const int wrows = L2G ? 256 : 128;
    Ar = smem + wrows * 128;

    // ---- one-time: load resident weight slice (packed + swizzled) ----
    for (int idx = tid; idx < wrows * 128; idx += NTHR) {
        int k2 = idx >> 7;
        int nl = idx & 127;
        int wn = nl >> 6;
        int h  = (nl >> 5) & 1;
        int r  = nl & 31;
        int g  = r & 7;
        int q  = r >> 3;
        int dst = k2 * 128 + (((wn << 6) + (h << 5) + (g << 2)) ^ ((k2 & 3) << 3)) + q;
        uint32_t v = L2G ? g_W2p[(size_t)k2 * NG + n0 + nl]
                         : g_W1hp[(size_t)k2 * NG + n0 + nl];
        Ws[dst] = v;
    }
    __syncthreads();

    // prologue: L1 group computes h1(0) = gates(embW) with h1(-1)=0 (no GEMM)
    if (!L2G)
        gemm_phase<true, false, true>(Ws, Ar, 128, g_h1p[0] + m0, g_h1p[0] + m0,
                                      g_c1, g_h1p[1], tokens, 0, m0, n0);
    grid_barrier();

    for (int t = 0; t < TSTEPS; t++) {
        if (L2G) {
            // layer2(t): A = [h2(t-1) | h1(t)]
            gemm_phase<false, true, false>(Ws, Ar, 256,
                                           g_h2p[t & 1] + m0, g_h1p[(t + 1) & 1] + m0,
                                           g_c2, g_h2p[(t + 1) & 1], tokens, t, m0, n0);
        } else if (t < TSTEPS - 1) {
            // layer1(t+1): A = h1(t)
            gemm_phase<true, false, false>(Ws, Ar, 128,
                                           g_h1p[(t + 1) & 1] + m0, g_h1p[0] + m0,
                                           g_c1, g_h1p[t & 1], tokens, t + 1, m0, n0);
        }
        grid_barrier();
    }

    // final dense + sigmoid; h2(79) packed in g_h2p[0]
    int gw   = cta * (NTHR / 32) + (tid >> 5);
    int lane = tid & 31;
    if (gw < BATCH / 32) {
        int bb = gw * 32 + lane;
        float s = 0.0f;
        const uint32_t* h = g_h2p[0];
        #pragma unroll 8
        for (int u2 = 0; u2 < UDIM / 2; u2++) {
            uint32_t v = h[(size_t)u2 * BATCH + bb];
            float lo = __bfloat162float(__ushort_as_bfloat16((unsigned short)(v & 0xFFFF)));
            float hi = __bfloat162float(__ushort_as_bfloat16((unsigned short)(v >> 16)));
            s += lo * w_out[2 * u2] + hi * w_out[2 * u2 + 1];
        }
        out[bb] = 1.0f / (1.0f + expf(-(s + b_out[0])));
    }
}

// ---------------- launch ----------------
extern "C" void kernel_launch(void* const* d_in, const int* in_sizes, int n_in,
                              void* d_out, int out_size)
{
    const int*   tokens = (const int*)  d_in[0];
    const float* emb    = (const float*)d_in[1];
    const float* wf1 = (const float*)d_in[2];  const float* bf1 = (const float*)d_in[3];
    const float* wi1 = (const float*)d_in[4];  const float* bi1 = (const float*)d_in[5];
    const float* wc1 = (const float*)d_in[6];  const float* bc1 = (const float*)d_in[7];
    const float* wo1 = (const float*)d_in[8];  const float* bo1 = (const float*)d_in[9];
    const float* wf2 = (const float*)d_in[10]; const float* bf2 = (const float*)d_in[11];
    const float* wi2 = (const float*)d_in[12]; const float* bi2 = (const float*)d_in[13];
    const float* wc2 = (const float*)d_in[14]; const float* bc2 = (const float*)d_in[15];
    const float* wo2 = (const float*)d_in[16]; const float* bo2 = (const float*)d_in[17];
    const float* w_out = (const float*)d_in[18];
    const float* b_out = (const float*)d_in[19];
    float* out = (float*)d_out;

    static int smem_set = 0;
    if (!smem_set) {
        cudaFuncSetAttribute(lstm_persistent,
                             cudaFuncAttributeMaxDynamicSharedMemorySize, SMEM_BYTES);
        smem_set = 1;
    }

    const int TOT = 384 * NG + EDIM * NG + 2 * NG;
    pack_kernel<<<(TOT + 255) / 256, 256>>>(wf1, bf1, wi1, bi1, wc1, bc1, wo1, bo1,
                                            wf2, bf2, wi2, bi2, wc2, bc2, wo2, bo2);
    zero_kernel<<<(UDIM * BATCH + 255) / 256, 256>>>();

    embw_kernel<<<dim3(NG / 64, (VOCAB + 63) / 64), 256>>>(emb);

    lstm_persistent<<<GRID_CTAS, NTHR, SMEM_BYTES>>>(tokens, w_out, b_out, out);
}

// round 14
// speedup vs baseline: 5.7700x; 1.0717x over previous
#include <cuda_runtime.h>
#include <cuda_bf16.h>
#include <math.h>
#include <stdint.h>

#define BATCH 1024
#define TSTEPS 80
#define EDIM 100
#define UDIM 256
#define NG 1024       // 4 gates * U, packed n = u*4 + g
#define VOCAB 10000
#define GRID_CTAS 128
#define NTHR 512

// packed k-pair rows: Layer1 = 128, Layer2 = 256. Chunk = 64 rows (128 k).
#define KC2 64

// CTA tile: 128 M x 128 N. smem: Ws[<=256][128] bf16x2 (<=128KB) + Ar[2][64][128] (64KB)
#define WS_U32_MAX (256 * 128)
#define AR_U32 (2 * KC2 * 128)
#define SMEM_BYTES ((WS_U32_MAX + AR_U32) * 4)   // 196608 B

// ---------------- persistent device scratch ----------------
__device__ __align__(16) uint32_t g_W1hp[128 * NG];        // bf16x2 [k2][n]
__device__ __align__(16) uint32_t g_W2p [256 * NG];        // bf16x2 [k2][n]
__device__ __align__(16) float g_W1x[EDIM * NG];           // fp32 exact, [k][n]
__device__ __align__(16) float g_b1[NG];
__device__ __align__(16) float g_b2[NG];
__device__ __align__(16) float g_embW[(size_t)VOCAB * NG]; // fp32 exact: emb@W1x + b1
// h states packed bf16x2 unit pairs: [u2][batch]
__device__ __align__(16) uint32_t g_h1p[2][(UDIM / 2) * BATCH];
__device__ __align__(16) uint32_t g_h2p[2][(UDIM / 2) * BATCH];
__device__ __align__(16) float g_c1[UDIM * BATCH];
__device__ __align__(16) float g_c2[UDIM * BATCH];
__device__ unsigned g_bar_count = 0;
__device__ unsigned g_bar_gen = 0;

__device__ __forceinline__ float tanh_ap(float x) {
    float r; asm("tanh.approx.f32 %0, %1;" : "=f"(r) : "f"(x)); return r;
}
__device__ __forceinline__ float sigmoid_ap(float x) {
    return 0.5f * tanh_ap(0.5f * x) + 0.5f;
}
__device__ __forceinline__ uint32_t pack_bf2(float lo, float hi) {
    unsigned l = __bfloat16_as_ushort(__float2bfloat16_rn(lo));
    unsigned h = __bfloat16_as_ushort(__float2bfloat16_rn(hi));
    return l | (h << 16);
}
__device__ __forceinline__ uint32_t smem_u32(const void* p) {
    uint32_t a;
    asm("{ .reg .u64 t; cvta.to.shared.u64 t, %1; cvt.u32.u64 %0, t; }" : "=r"(a) : "l"(p));
    return a;
}
__device__ __forceinline__ void cp16(uint32_t dst, const void* src) {
    asm volatile("cp.async.cg.shared.global [%0], [%1], 16;" :: "r"(dst), "l"(src));
}
__device__ __forceinline__ void cp_commit() { asm volatile("cp.async.commit_group;"); }
__device__ __forceinline__ void cp_wait1()  { asm volatile("cp.async.wait_group 1;"); }
__device__ __forceinline__ void cp_wait0()  { asm volatile("cp.async.wait_group 0;"); }

__device__ __forceinline__ void mma_bf16(float* c, const uint32_t* a, const uint32_t* b) {
    asm volatile(
        "mma.sync.aligned.m16n8k16.row.col.f32.bf16.bf16.f32 "
        "{%0,%1,%2,%3}, {%4,%5,%6,%7}, {%8,%9}, {%0,%1,%2,%3};"
        : "+f"(c[0]), "+f"(c[1]), "+f"(c[2]), "+f"(c[3])
        : "r"(a[0]), "r"(a[1]), "r"(a[2]), "r"(a[3]), "r"(b[0]), "r"(b[1]));
}

// ---------------- software grid barrier (release/acquire, no MEMBAR) ----------------
__device__ __forceinline__ void grid_barrier() {
    __syncthreads();
    if (threadIdx.x == 0) {
        unsigned gen;
        asm volatile("ld.relaxed.gpu.global.u32 %0, [%1];"
                     : "=r"(gen) : "l"(&g_bar_gen));
        unsigned old;
        asm volatile("atom.release.gpu.global.add.u32 %0, [%1], 1;"
                     : "=r"(old) : "l"(&g_bar_count) : "memory");
        if (old == GRID_CTAS - 1) {
            asm volatile("st.relaxed.gpu.global.u32 [%0], %1;"
                         :: "l"(&g_bar_count), "r"(0u) : "memory");
            asm volatile("st.release.gpu.global.u32 [%0], %1;"
                         :: "l"(&g_bar_gen), "r"(gen + 1) : "memory");
        } else {
            unsigned cur;
            do {
                asm volatile("ld.acquire.gpu.global.u32 %0, [%1];"
                             : "=r"(cur) : "l"(&g_bar_gen) : "memory");
            } while (cur == gen);
        }
    }
    __syncthreads();
}

// ---------------- pack: n = u*4+g; recurrent W as bf16x2 k-pairs; W1x exact ----------------
__global__ void pack_kernel(
    const float* wf1, const float* bf1, const float* wi1, const float* bi1,
    const float* wc1, const float* bc1, const float* wo1, const float* bo1,
    const float* wf2, const float* bf2, const float* wi2, const float* bi2,
    const float* wc2, const float* bc2, const float* wo2, const float* bo2)
{
    const int TOT_P = 384 * NG;
    const int TOT_X = EDIM * NG;
    int id = blockIdx.x * blockDim.x + threadIdx.x;
    if (id < TOT_P) {
        int k2 = id >> 10;
        int n  = id & 1023;
        int u  = n >> 2;
        int g  = n & 3;
        if (k2 < 128) {
            const float* w = (g == 0) ? wf1 : (g == 1) ? wi1 : (g == 2) ? wc1 : wo1;
            g_W1hp[k2 * NG + n] = pack_bf2(w[(2 * k2) * UDIM + u],
                                           w[(2 * k2 + 1) * UDIM + u]);
        } else {
            int kk = k2 - 128;
            const float* w = (g == 0) ? wf2 : (g == 1) ? wi2 : (g == 2) ? wc2 : wo2;
            g_W2p[kk * NG + n] = pack_bf2(w[(2 * kk) * UDIM + u],
                                          w[(2 * kk + 1) * UDIM + u]);
        }
    } else if (id < TOT_P + TOT_X) {
        int j = id - TOT_P;
        int kk = j >> 10;
        int n  = j & 1023;
        int u  = n >> 2;
        int g  = n & 3;
        const float* w = (g == 0) ? wf1 : (g == 1) ? wi1 : (g == 2) ? wc1 : wo1;
        g_W1x[kk * NG + n] = w[(UDIM + kk) * UDIM + u];
    } else if (id < TOT_P + TOT_X + 2 * NG) {
        int j = id - TOT_P - TOT_X;
        int n = j & 1023;
        int u = n >> 2;
        int g = n & 3;
        if (j < NG) g_b1[n] = ((g == 0) ? bf1 : (g == 1) ? bi1 : (g == 2) ? bc1 : bo1)[u];
        else        g_b2[n] = ((g == 0) ? bf2 : (g == 1) ? bi2 : (g == 2) ? bc2 : bo2)[u];
    }
}

__global__ void zero_kernel()
{
    int id = blockIdx.x * blockDim.x + threadIdx.x;
    if (id < UDIM * BATCH) {
        g_c1[id] = 0.0f;
        g_c2[id] = 0.0f;
    }
    if (id < (UDIM / 2) * BATCH) {
        g_h1p[0][id] = 0u;
        g_h1p[1][id] = 0u;
        g_h2p[0][id] = 0u;
        g_h2p[1][id] = 0u;
    }
}

// ---------------- embW = emb @ W1x + b1 (fp32 exact) ----------------
__global__ __launch_bounds__(256) void embw_kernel(const float* __restrict__ emb)
{
    __shared__ __align__(16) float As[32][64];
    __shared__ __align__(16) float Bs[32][64];

    const int tid = threadIdx.x;
    const int m0  = blockIdx.y * 64;
    const int n0  = blockIdx.x * 64;
    const int tm  = tid >> 4;
    const int tn  = tid & 15;

    float acc[4][4] = {};

    for (int k0 = 0; k0 < 128; k0 += 32) {
        #pragma unroll
        for (int i = 0; i < 2; i++) {
            int f4 = tid + i * 256;
            int m  = f4 >> 3;
            int kq = f4 & 7;
            int k  = k0 + kq * 4;
            float4 v = make_float4(0.f, 0.f, 0.f, 0.f);
            int row = m0 + m;
            if (k < EDIM && row < VOCAB)
                v = *(const float4*)&emb[(size_t)row * EDIM + k];
            As[kq * 4 + 0][m] = v.x;
            As[kq * 4 + 1][m] = v.y;
            As[kq * 4 + 2][m] = v.z;
            As[kq * 4 + 3][m] = v.w;
        }
        #pragma unroll
        for (int i = 0; i < 2; i++) {
            int f4 = tid + i * 256;
            int kk = f4 >> 4;
            int c4 = f4 & 15;
            int k  = k0 + kk;
            float4 v = make_float4(0.f, 0.f, 0.f, 0.f);
            if (k < EDIM) v = *(const float4*)&g_W1x[k * NG + n0 + c4 * 4];
            *(float4*)&Bs[kk][c4 * 4] = v;
        }
        __syncthreads();

        #pragma unroll
        for (int k = 0; k < 32; k++) {
            float4 b = *(const float4*)&Bs[k][tn * 4];
            float4 a = *(const float4*)&As[k][tm * 4];
            float ar[4] = {a.x, a.y, a.z, a.w};
            float br[4] = {b.x, b.y, b.z, b.w};
            #pragma unroll
            for (int r = 0; r < 4; r++)
                #pragma unroll
                for (int c = 0; c < 4; c++)
                    acc[r][c] += ar[r] * br[c];
        }
        __syncthreads();
    }

    float4 bb = *(const float4*)&g_b1[n0 + tn * 4];
    #pragma unroll
    for (int r = 0; r < 4; r++) {
        int row = m0 + tm * 4 + r;
        if (row < VOCAB)
            *(float4*)&g_embW[(size_t)row * NG + n0 + tn * 4] =
                make_float4(acc[r][0] + bb.x, acc[r][1] + bb.y,
                            acc[r][2] + bb.z, acc[r][3] + bb.w);
    }
}

// ---------------- persistent kernel, split-layer CTA groups ----------------
// CTAs 0-63: layer2 (K2=256). CTAs 64-127: layer1 (K2=128). One barrier/step.
// CTA tile 128M x 128N; 16 warps (4m x 4n); warp tile 32M x 32N; mma m16n8k16:
// mt=2, nt=4. Ws row stride 128 u32; A chunk [64 rows][128 m-cols].
// Ws pack: n_local = wn*32 + q*8 + g -> dst col ((wn*32+g*4)^sw)+q, sw=8*(k2&3).
// Ar: col = m ^ sw.

// stage one 64-row x 128m packed A chunk: 2048 cp16 / 512 thr = 4 each
__device__ __forceinline__ void stage_A(uint32_t* dst, const uint32_t* __restrict__ src, int tid)
{
    #pragma unroll
    for (int i = 0; i < 4; i++) {
        int f4 = tid + i * NTHR;        // 0..2047
        int kq = f4 >> 5;               // 0..63 packed rows
        int c4 = f4 & 31;               // 0..31 (x4 cols = 128)
        int col = (c4 * 4) ^ ((kq & 3) * 8);
        cp16(smem_u32(dst + kq * 128 + col), src + (size_t)kq * BATCH + c4 * 4);
    }
}

template <bool L1P, bool DUAL, bool ZERO>
__device__ __forceinline__ void gemm_phase(
    const uint32_t* __restrict__ Ws,   // resident weights, row stride 128
    uint32_t* __restrict__ Ar,
    int K2,                            // packed k rows: 128 (L1) or 256 (L2)
    const uint32_t* __restrict__ A0,   // packed h [u2][b] + m0 (h2 for DUAL)
    const uint32_t* __restrict__ A1,   // h1 source for DUAL (k2 >= 128) + m0
    float* __restrict__ cs, uint32_t* __restrict__ houtp,
    const int* __restrict__ tokens, int t, int m0, int n0)
{
    const int tid  = threadIdx.x;
    const int lane = tid & 31;
    const int wid  = tid >> 5;
    const int s    = lane & 3;
    const int g    = lane >> 2;
    const int wm   = wid & 3;          // 4 m-warps
    const int wn   = wid >> 2;         // 4 n-warps

    const int cm0  = (wm * 32 + g) ^ (8 * s);
    const int cb   = (wn * 32 + g * 4) ^ (8 * s);

    float acc[2][4][4];
    #pragma unroll
    for (int a = 0; a < 2; a++)
        #pragma unroll
        for (int b = 0; b < 4; b++)
            #pragma unroll
            for (int c = 0; c < 4; c++) acc[a][b][c] = 0.0f;

    if (!ZERO) {
        stage_A(Ar, A0, tid);
        cp_commit();

        const int C = K2 / KC2;        // 2 (L1) or 4 (L2)
        for (int c = 0; c < C; c++) {
            int cur = c & 1;
            if (c + 1 < C) {
                int r0 = (c + 1) * KC2;
                const uint32_t* srcn = (DUAL && r0 >= 128) ?
                                       A1 + (size_t)(r0 - 128) * BATCH :
                                       A0 + (size_t)r0 * BATCH;
                stage_A(Ar + (1 - cur) * (KC2 * 128), srcn, tid);
                cp_commit();
                cp_wait1();
            } else {
                cp_wait0();
            }
            __syncthreads();

            const uint32_t* Ab = Ar + cur * (KC2 * 128) + s * 128;
            const uint32_t* Bb = Ws + ((size_t)(c * KC2) + s) * 128 + cb;

            #pragma unroll
            for (int sl = 0; sl < KC2 / 8; sl++) {       // 8 slabs of k16
                const uint32_t* ap = Ab + sl * (8 * 128);
                const uint32_t* bp = Bb + sl * (8 * 128);
                uint4 b0 = *(const uint4*)bp;            // k2 = s
                uint4 b1 = *(const uint4*)(bp + 4 * 128);// k2 = s+4
                uint32_t bf[4][2] = {
                    { b0.x, b1.x }, { b0.y, b1.y }, { b0.z, b1.z }, { b0.w, b1.w }
                };
                #pragma unroll
                for (int mt = 0; mt < 2; mt++) {
                    const int cc = cm0 ^ (mt * 16);
                    uint32_t af[4];
                    af[0] = ap[cc];
                    af[1] = ap[cc ^ 8];
                    af[2] = ap[4 * 128 + cc];
                    af[3] = ap[4 * 128 + (cc ^ 8)];
                    #pragma unroll
                    for (int nt = 0; nt < 4; nt++)
                        mma_bf16(acc[mt][nt], af, bf[nt]);
                }
            }
            __syncthreads();
        }
    }

    // ---- fused LSTM epilogue ----
    // acc[mt][nt]: c0=(row g, col 2s), c1=(g,2s+1), c2=(g+8,2s), c3=(g+8,2s+1)
    // shfl-xor-1 combines (f,i)/(ctilde,o); shfl-xor-2 packs unit pairs.
    #pragma unroll
    for (int mt = 0; mt < 2; mt++) {
        const int m = m0 + wm * 32 + mt * 16 + g + ((lane & 1) << 3);
        int tok = 0;
        if (L1P) tok = tokens[m * TSTEPS + t];
        #pragma unroll
        for (int nt = 0; nt < 4; nt++) {
            float* a = acc[mt][nt];
            float v1 = __shfl_xor_sync(0xFFFFFFFFu, (lane & 1) ? a[0] : a[2], 1);
            float v2 = __shfl_xor_sync(0xFFFFFFFFu, (lane & 1) ? a[1] : a[3], 1);
            float pf, pi, pc, po;
            if (lane & 1) { pc = a[2]; po = a[3]; pf = v1; pi = v2; }
            else          { pf = a[0]; pi = a[1]; pc = v1; po = v2; }

            const int nb = n0 + wn * 32 + nt * 8;
            const int u  = (nb >> 2) + (s >> 1);
            if (L1P) {
                float4 x = *(const float4*)&g_embW[(size_t)tok * NG + u * 4];
                pf += x.x; pi += x.y; pc += x.z; po += x.w;
            } else {
                float4 bv = *(const float4*)&g_b2[u * 4];
                pf += bv.x; pi += bv.y; pc += bv.z; po += bv.w;
            }
            float cold = cs[(size_t)u * BATCH + m];
            float cn = sigmoid_ap(pf) * cold + sigmoid_ap(pi) * tanh_ap(pc);
            cs[(size_t)u * BATCH + m] = cn;
            float hn = sigmoid_ap(po) * tanh_ap(cn);
            float ho = __shfl_xor_sync(0xFFFFFFFFu, hn, 2);
            if ((lane & 2) == 0) {
                const int u2 = nb >> 3;
                houtp[(size_t)u2 * BATCH + m] = pack_bf2(hn, ho);
            }
        }
    }
}

__global__ __launch_bounds__(NTHR, 1) void lstm_persistent(
    const int* __restrict__ tokens,
    const float* __restrict__ w_out, const float* __restrict__ b_out,
    float* __restrict__ out)
{
    extern __shared__ __align__(16) uint32_t smem[];
    uint32_t* Ws = smem;                 // L2 group: [256][128]; L1 group: [128][128]
    uint32_t* Ar;

    const int cta  = blockIdx.x;
    const bool L2G = (cta < 64);
    const int n0   = (cta & 7) * 128;        // 8 n-tiles
    const int m0   = ((cta >> 3) & 7) * 128; // 8 m-tiles
    const int tid  = threadIdx.x;

    const int wrows = L2G ? 256 : 128;
    Ar = smem + wrows * 128;

    // ---- one-time: load resident weight slice (packed + swizzled) ----
    for (int idx = tid; idx < wrows * 128; idx += NTHR) {
        int k2 = idx >> 7;
        int nl = idx & 127;
        int wn = nl >> 5;
        int r  = nl & 31;
        int g  = r & 7;
        int q  = r >> 3;
        int dst = k2 * 128 + (((wn << 5) + (g << 2)) ^ ((k2 & 3) << 3)) + q;
        uint32_t v = L2G ? g_W2p[(size_t)k2 * NG + n0 + nl]
                         : g_W1hp[(size_t)k2 * NG + n0 + nl];
        Ws[dst] = v;
    }
    __syncthreads();

    // prologue: L1 group computes h1(0) = gates(embW) with h1(-1)=0 (no GEMM)
    if (!L2G)
        gemm_phase<true, false, true>(Ws, Ar, 128, g_h1p[0] + m0, g_h1p[0] + m0,
                                      g_c1, g_h1p[1], tokens, 0, m0, n0);
    grid_barrier();

    for (int t = 0; t < TSTEPS; t++) {
        if (L2G) {
            // layer2(t): A = [h2(t-1) | h1(t)]
            gemm_phase<false, true, false>(Ws, Ar, 256,
                                           g_h2p[t & 1] + m0, g_h1p[(t + 1) & 1] + m0,
                                           g_c2, g_h2p[(t + 1) & 1], tokens, t, m0, n0);
        } else if (t < TSTEPS - 1) {
            // layer1(t+1): A = h1(t)
            gemm_phase<true, false, false>(Ws, Ar, 128,
                                           g_h1p[(t + 1) & 1] + m0, g_h1p[0] + m0,
                                           g_c1, g_h1p[t & 1], tokens, t + 1, m0, n0);
        }
        grid_barrier();
    }

    // final dense + sigmoid; h2(79) packed in g_h2p[0]
    int gw   = cta * (NTHR / 32) + (tid >> 5);
    int lane = tid & 31;
    if (gw < BATCH / 32) {
        int bb = gw * 32 + lane;
        float s = 0.0f;
        const uint32_t* h = g_h2p[0];
        #pragma unroll 8
        for (int u2 = 0; u2 < UDIM / 2; u2++) {
            uint32_t v = h[(size_t)u2 * BATCH + bb];
            float lo = __bfloat162float(__ushort_as_bfloat16((unsigned short)(v & 0xFFFF)));
            float hi = __bfloat162float(__ushort_as_bfloat16((unsigned short)(v >> 16)));
            s += lo * w_out[2 * u2] + hi * w_out[2 * u2 + 1];
        }
        out[bb] = 1.0f / (1.0f + expf(-(s + b_out[0])));
    }
}

// ---------------- launch ----------------
extern "C" void kernel_launch(void* const* d_in, const int* in_sizes, int n_in,
                              void* d_out, int out_size)
{
    const int*   tokens = (const int*)  d_in[0];
    const float* emb    = (const float*)d_in[1];
    const float* wf1 = (const float*)d_in[2];  const float* bf1 = (const float*)d_in[3];
    const float* wi1 = (const float*)d_in[4];  const float* bi1 = (const float*)d_in[5];
    const float* wc1 = (const float*)d_in[6];  const float* bc1 = (const float*)d_in[7];
    const float* wo1 = (const float*)d_in[8];  const float* bo1 = (const float*)d_in[9];
    const float* wf2 = (const float*)d_in[10]; const float* bf2 = (const float*)d_in[11];
    const float* wi2 = (const float*)d_in[12]; const float* bi2 = (const float*)d_in[13];
    const float* wc2 = (const float*)d_in[14]; const float* bc2 = (const float*)d_in[15];
    const float* wo2 = (const float*)d_in[16]; const float* bo2 = (const float*)d_in[17];
    const float* w_out = (const float*)d_in[18];
    const float* b_out = (const float*)d_in[19];
    float* out = (float*)d_out;

    static int smem_set = 0;
    if (!smem_set) {
        cudaFuncSetAttribute(lstm_persistent,
                             cudaFuncAttributeMaxDynamicSharedMemorySize, SMEM_BYTES);
        smem_set = 1;
    }

    const int TOT = 384 * NG + EDIM * NG + 2 * NG;
    pack_kernel<<<(TOT + 255) / 256, 256>>>(wf1, bf1, wi1, bi1, wc1, bc1, wo1, bo1,
                                            wf2, bf2, wi2, bi2, wc2, bc2, wo2, bo2);
    zero_kernel<<<(UDIM * BATCH + 255) / 256, 256>>>();

    embw_kernel<<<dim3(NG / 64, (VOCAB + 63) / 64), 256>>>(emb);

    lstm_persistent<<<GRID_CTAS, NTHR, SMEM_BYTES>>>(tokens, w_out, b_out, out);
}

// round 15
// speedup vs baseline: 6.5729x; 1.1392x over previous
#include <cuda_runtime.h>
#include <cuda_bf16.h>
#include <math.h>
#include <stdint.h>

#define BATCH 1024
#define TSTEPS 80
#define EDIM 100
#define UDIM 256
#define NG 1024       // 4 gates * U, packed n = u*4 + g
#define VOCAB 10000
#define GRID_CTAS 128
#define NTHR 512

// packed k-pair rows: Layer1 = 128, Layer2 = 256. Chunk = 64 rows (128 k).
#define KC2 64

// smem (u32): Ws[<=256][128] + Ar[2][64][128] + csm[4096] + bsm[128]
#define WS_U32_MAX (256 * 128)
#define AR_U32 (2 * KC2 * 128)
#define CS_U32 (32 * 128)
#define SMEM_BYTES ((WS_U32_MAX + AR_U32 + CS_U32 + 128) * 4)   // 213504 B

// ---------------- persistent device scratch ----------------
__device__ __align__(16) uint32_t g_W1hp[128 * NG];        // bf16x2 [k2][n]
__device__ __align__(16) uint32_t g_W2p [256 * NG];        // bf16x2 [k2][n]
__device__ __align__(16) float g_W1x[EDIM * NG];           // fp32 exact, [k][n]
__device__ __align__(16) float g_b1[NG];
__device__ __align__(16) float g_b2[NG];
__device__ __align__(16) float g_embW[(size_t)VOCAB * NG]; // fp32 exact: emb@W1x + b1
// h states packed bf16x2 unit pairs: [u2][batch]
__device__ __align__(16) uint32_t g_h1p[2][(UDIM / 2) * BATCH];
__device__ __align__(16) uint32_t g_h2p[2][(UDIM / 2) * BATCH];
__device__ unsigned g_bar_count = 0;
__device__ unsigned g_bar_gen = 0;
__device__ unsigned g_cls_cnt[8 * 32];   // per-m0-class monotonic counters (padded)

__device__ __forceinline__ float tanh_ap(float x) {
    float r; asm("tanh.approx.f32 %0, %1;" : "=f"(r) : "f"(x)); return r;
}
__device__ __forceinline__ float sigmoid_ap(float x) {
    return 0.5f * tanh_ap(0.5f * x) + 0.5f;
}
__device__ __forceinline__ uint32_t pack_bf2(float lo, float hi) {
    unsigned l = __bfloat16_as_ushort(__float2bfloat16_rn(lo));
    unsigned h = __bfloat16_as_ushort(__float2bfloat16_rn(hi));
    return l | (h << 16);
}
__device__ __forceinline__ uint32_t smem_u32(const void* p) {
    uint32_t a;
    asm("{ .reg .u64 t; cvta.to.shared.u64 t, %1; cvt.u32.u64 %0, t; }" : "=r"(a) : "l"(p));
    return a;
}
__device__ __forceinline__ void cp16(uint32_t dst, const void* src) {
    asm volatile("cp.async.cg.shared.global [%0], [%1], 16;" :: "r"(dst), "l"(src));
}
__device__ __forceinline__ void cp_commit() { asm volatile("cp.async.commit_group;"); }
__device__ __forceinline__ void cp_wait1()  { asm volatile("cp.async.wait_group 1;"); }
__device__ __forceinline__ void cp_wait0()  { asm volatile("cp.async.wait_group 0;"); }

__device__ __forceinline__ void mma_bf16(float* c, const uint32_t* a, const uint32_t* b) {
    asm volatile(
        "mma.sync.aligned.m16n8k16.row.col.f32.bf16.bf16.f32 "
        "{%0,%1,%2,%3}, {%4,%5,%6,%7}, {%8,%9}, {%0,%1,%2,%3};"
        : "+f"(c[0]), "+f"(c[1]), "+f"(c[2]), "+f"(c[3])
        : "r"(a[0]), "r"(a[1]), "r"(a[2]), "r"(a[3]), "r"(b[0]), "r"(b[1]));
}

// ---------------- barriers ----------------
// class barrier: 16 CTAs of one m0 class, monotonic counter, target = 16*call#
__device__ __forceinline__ void class_barrier(unsigned* cnt, unsigned target) {
    __syncthreads();
    if (threadIdx.x == 0) {
        unsigned old;
        asm volatile("atom.release.gpu.global.add.u32 %0, [%1], 1;"
                     : "=r"(old) : "l"(cnt) : "memory");
        unsigned cur = old + 1;
        while (cur < target) {
            asm volatile("ld.acquire.gpu.global.u32 %0, [%1];"
                         : "=r"(cur) : "l"(cnt) : "memory");
        }
    }
    __syncthreads();
}

// full-grid barrier (used once, before the output stage)
__device__ __forceinline__ void grid_barrier() {
    __syncthreads();
    if (threadIdx.x == 0) {
        unsigned gen;
        asm volatile("ld.relaxed.gpu.global.u32 %0, [%1];"
                     : "=r"(gen) : "l"(&g_bar_gen));
        unsigned old;
        asm volatile("atom.release.gpu.global.add.u32 %0, [%1], 1;"
                     : "=r"(old) : "l"(&g_bar_count) : "memory");
        if (old == GRID_CTAS - 1) {
            asm volatile("st.relaxed.gpu.global.u32 [%0], %1;"
                         :: "l"(&g_bar_count), "r"(0u) : "memory");
            asm volatile("st.release.gpu.global.u32 [%0], %1;"
                         :: "l"(&g_bar_gen), "r"(gen + 1) : "memory");
        } else {
            unsigned cur;
            do {
                asm volatile("ld.acquire.gpu.global.u32 %0, [%1];"
                             : "=r"(cur) : "l"(&g_bar_gen) : "memory");
            } while (cur == gen);
        }
    }
    __syncthreads();
}

// ---------------- pack: n = u*4+g; recurrent W as bf16x2 k-pairs; W1x exact ----------------
__global__ void pack_kernel(
    const float* wf1, const float* bf1, const float* wi1, const float* bi1,
    const float* wc1, const float* bc1, const float* wo1, const float* bo1,
    const float* wf2, const float* bf2, const float* wi2, const float* bi2,
    const float* wc2, const float* bc2, const float* wo2, const float* bo2)
{
    const int TOT_P = 384 * NG;
    const int TOT_X = EDIM * NG;
    int id = blockIdx.x * blockDim.x + threadIdx.x;
    if (id < TOT_P) {
        int k2 = id >> 10;
        int n  = id & 1023;
        int u  = n >> 2;
        int g  = n & 3;
        if (k2 < 128) {
            const float* w = (g == 0) ? wf1 : (g == 1) ? wi1 : (g == 2) ? wc1 : wo1;
            g_W1hp[k2 * NG + n] = pack_bf2(w[(2 * k2) * UDIM + u],
                                           w[(2 * k2 + 1) * UDIM + u]);
        } else {
            int kk = k2 - 128;
            const float* w = (g == 0) ? wf2 : (g == 1) ? wi2 : (g == 2) ? wc2 : wo2;
            g_W2p[kk * NG + n] = pack_bf2(w[(2 * kk) * UDIM + u],
                                          w[(2 * kk + 1) * UDIM + u]);
        }
    } else if (id < TOT_P + TOT_X) {
        int j = id - TOT_P;
        int kk = j >> 10;
        int n  = j & 1023;
        int u  = n >> 2;
        int g  = n & 3;
        const float* w = (g == 0) ? wf1 : (g == 1) ? wi1 : (g == 2) ? wc1 : wo1;
        g_W1x[kk * NG + n] = w[(UDIM + kk) * UDIM + u];
    } else if (id < TOT_P + TOT_X + 2 * NG) {
        int j = id - TOT_P - TOT_X;
        int n = j & 1023;
        int u = n >> 2;
        int g = n & 3;
        if (j < NG) g_b1[n] = ((g == 0) ? bf1 : (g == 1) ? bi1 : (g == 2) ? bc1 : bo1)[u];
        else        g_b2[n] = ((g == 0) ? bf2 : (g == 1) ? bi2 : (g == 2) ? bc2 : bo2)[u];
    }
}

__global__ void zero_kernel()
{
    int id = blockIdx.x * blockDim.x + threadIdx.x;
    if (id < 8 * 32) g_cls_cnt[id] = 0;
    if (id < (UDIM / 2) * BATCH) {
        g_h1p[0][id] = 0u;
        g_h1p[1][id] = 0u;
        g_h2p[0][id] = 0u;
        g_h2p[1][id] = 0u;
    }
}

// ---------------- embW = emb @ W1x + b1 (fp32 exact) ----------------
__global__ __launch_bounds__(256) void embw_kernel(const float* __restrict__ emb)
{
    __shared__ __align__(16) float As[32][64];
    __shared__ __align__(16) float Bs[32][64];

    const int tid = threadIdx.x;
    const int m0  = blockIdx.y * 64;
    const int n0  = blockIdx.x * 64;
    const int tm  = tid >> 4;
    const int tn  = tid & 15;

    float acc[4][4] = {};

    for (int k0 = 0; k0 < 128; k0 += 32) {
        #pragma unroll
        for (int i = 0; i < 2; i++) {
            int f4 = tid + i * 256;
            int m  = f4 >> 3;
            int kq = f4 & 7;
            int k  = k0 + kq * 4;
            float4 v = make_float4(0.f, 0.f, 0.f, 0.f);
            int row = m0 + m;
            if (k < EDIM && row < VOCAB)
                v = *(const float4*)&emb[(size_t)row * EDIM + k];
            As[kq * 4 + 0][m] = v.x;
            As[kq * 4 + 1][m] = v.y;
            As[kq * 4 + 2][m] = v.z;
            As[kq * 4 + 3][m] = v.w;
        }
        #pragma unroll
        for (int i = 0; i < 2; i++) {
            int f4 = tid + i * 256;
            int kk = f4 >> 4;
            int c4 = f4 & 15;
            int k  = k0 + kk;
            float4 v = make_float4(0.f, 0.f, 0.f, 0.f);
            if (k < EDIM) v = *(const float4*)&g_W1x[k * NG + n0 + c4 * 4];
            *(float4*)&Bs[kk][c4 * 4] = v;
        }
        __syncthreads();

        #pragma unroll
        for (int k = 0; k < 32; k++) {
            float4 b = *(const float4*)&Bs[k][tn * 4];
            float4 a = *(const float4*)&As[k][tm * 4];
            float ar[4] = {a.x, a.y, a.z, a.w};
            float br[4] = {b.x, b.y, b.z, b.w};
            #pragma unroll
            for (int r = 0; r < 4; r++)
                #pragma unroll
                for (int c = 0; c < 4; c++)
                    acc[r][c] += ar[r] * br[c];
        }
        __syncthreads();
    }

    float4 bb = *(const float4*)&g_b1[n0 + tn * 4];
    #pragma unroll
    for (int r = 0; r < 4; r++) {
        int row = m0 + tm * 4 + r;
        if (row < VOCAB)
            *(float4*)&g_embW[(size_t)row * NG + n0 + tn * 4] =
                make_float4(acc[r][0] + bb.x, acc[r][1] + bb.y,
                            acc[r][2] + bb.z, acc[r][3] + bb.w);
    }
}

// ---------------- persistent kernel, split-layer CTA groups + m0 classes ----------------
// CTAs 0-63: layer2 (K2=256). CTAs 64-127: layer1 (K2=128).
// m0 class = 8 L2 + 8 L1 CTAs sharing one m0; per-step sync is class-local.
// CTA tile 128M x 128N; 16 warps (4m x 4n); warp tile 32M x 32N; mma m16n8k16.
// c state lives in per-CTA smem (unique owner). b2 slice cached in smem.

__device__ __forceinline__ void stage_A(uint32_t* dst, const uint32_t* __restrict__ src, int tid)
{
    #pragma unroll
    for (int i = 0; i < 4; i++) {
        int f4 = tid + i * NTHR;        // 0..2047
        int kq = f4 >> 5;               // 0..63 packed rows
        int c4 = f4 & 31;               // 0..31 (x4 cols = 128)
        int col = (c4 * 4) ^ ((kq & 3) * 8);
        cp16(smem_u32(dst + kq * 128 + col), src + (size_t)kq * BATCH + c4 * 4);
    }
}

template <bool L1P, bool DUAL, bool ZERO>
__device__ __forceinline__ void gemm_phase(
    const uint32_t* __restrict__ Ws,   // resident weights, row stride 128
    uint32_t* __restrict__ Ar,
    float* __restrict__ csm,           // smem c state [u_local(32)][m_local(128)]
    const float* __restrict__ bsm,     // smem b2 slice (L2 only)
    int K2,
    const uint32_t* __restrict__ A0,   // packed h [u2][b] + m0 (h2 for DUAL)
    const uint32_t* __restrict__ A1,   // h1 source for DUAL (k2 >= 128) + m0
    uint32_t* __restrict__ houtp,
    const int* __restrict__ tokens, int t, int m0, int n0)
{
    const int tid  = threadIdx.x;
    const int lane = tid & 31;
    const int wid  = tid >> 5;
    const int s    = lane & 3;
    const int g    = lane >> 2;
    const int wm   = wid & 3;          // 4 m-warps
    const int wn   = wid >> 2;         // 4 n-warps

    const int cm0  = (wm * 32 + g) ^ (8 * s);
    const int cb   = (wn * 32 + g * 4) ^ (8 * s);

    float acc[2][4][4];
    #pragma unroll
    for (int a = 0; a < 2; a++)
        #pragma unroll
        for (int b = 0; b < 4; b++)
            #pragma unroll
            for (int c = 0; c < 4; c++) acc[a][b][c] = 0.0f;

    if (!ZERO) {
        stage_A(Ar, A0, tid);
        cp_commit();

        const int C = K2 / KC2;        // 2 (L1) or 4 (L2)
        for (int c = 0; c < C; c++) {
            int cur = c & 1;
            if (c + 1 < C) {
                int r0 = (c + 1) * KC2;
                const uint32_t* srcn = (DUAL && r0 >= 128) ?
                                       A1 + (size_t)(r0 - 128) * BATCH :
                                       A0 + (size_t)r0 * BATCH;
                stage_A(Ar + (1 - cur) * (KC2 * 128), srcn, tid);
                cp_commit();
                cp_wait1();
            } else {
                cp_wait0();
            }
            __syncthreads();

            const uint32_t* Ab = Ar + cur * (KC2 * 128) + s * 128;
            const uint32_t* Bb = Ws + ((size_t)(c * KC2) + s) * 128 + cb;

            #pragma unroll
            for (int sl = 0; sl < KC2 / 8; sl++) {       // 8 slabs of k16
                const uint32_t* ap = Ab + sl * (8 * 128);
                const uint32_t* bp = Bb + sl * (8 * 128);
                uint4 b0 = *(const uint4*)bp;            // k2 = s
                uint4 b1 = *(const uint4*)(bp + 4 * 128);// k2 = s+4
                uint32_t bf[4][2] = {
                    { b0.x, b1.x }, { b0.y, b1.y }, { b0.z, b1.z }, { b0.w, b1.w }
                };
                #pragma unroll
                for (int mt = 0; mt < 2; mt++) {
                    const int cc = cm0 ^ (mt * 16);
                    uint32_t af[4];
                    af[0] = ap[cc];
                    af[1] = ap[cc ^ 8];
                    af[2] = ap[4 * 128 + cc];
                    af[3] = ap[4 * 128 + (cc ^ 8)];
                    #pragma unroll
                    for (int nt = 0; nt < 4; nt++)
                        mma_bf16(acc[mt][nt], af, bf[nt]);
                }
            }
            __syncthreads();
        }
    }

    // ---- fused LSTM epilogue (c in smem; bias from smem for L2) ----
    #pragma unroll
    for (int mt = 0; mt < 2; mt++) {
        const int mloc = wm * 32 + mt * 16 + g + ((lane & 1) << 3);
        const int m = m0 + mloc;
        int tok = 0;
        if (L1P) tok = tokens[m * TSTEPS + t];
        #pragma unroll
        for (int nt = 0; nt < 4; nt++) {
            float* a = acc[mt][nt];
            float v1 = __shfl_xor_sync(0xFFFFFFFFu, (lane & 1) ? a[0] : a[2], 1);
            float v2 = __shfl_xor_sync(0xFFFFFFFFu, (lane & 1) ? a[1] : a[3], 1);
            float pf, pi, pc, po;
            if (lane & 1) { pc = a[2]; po = a[3]; pf = v1; pi = v2; }
            else          { pf = a[0]; pi = a[1]; pc = v1; po = v2; }

            const int uloc = wn * 8 + nt * 2 + (s >> 1);   // 0..31
            float4 x;
            if (L1P) {
                const int u = (n0 >> 2) + uloc;
                x = *(const float4*)&g_embW[(size_t)tok * NG + u * 4];
            } else {
                x = *(const float4*)&bsm[uloc * 4];
            }
            pf += x.x; pi += x.y; pc += x.z; po += x.w;
            float cold = csm[uloc * 128 + mloc];
            float cn = sigmoid_ap(pf) * cold + sigmoid_ap(pi) * tanh_ap(pc);
            csm[uloc * 128 + mloc] = cn;
            float hn = sigmoid_ap(po) * tanh_ap(cn);
            float ho = __shfl_xor_sync(0xFFFFFFFFu, hn, 2);
            if ((lane & 2) == 0) {
                const int nb = n0 + wn * 32 + nt * 8;
                const int u2 = nb >> 3;
                houtp[(size_t)u2 * BATCH + m] = pack_bf2(hn, ho);
            }
        }
    }
}

__global__ __launch_bounds__(NTHR, 1) void lstm_persistent(
    const int* __restrict__ tokens,
    const float* __restrict__ w_out, const float* __restrict__ b_out,
    float* __restrict__ out)
{
    extern __shared__ __align__(16) uint32_t smem[];

    const int cta  = blockIdx.x;
    const bool L2G = (cta < 64);
    const int n0   = (cta & 7) * 128;        // 8 n-tiles
    const int mcls = (cta >> 3) & 7;         // m0 class 0..7
    const int m0   = mcls * 128;
    const int tid  = threadIdx.x;

    const int wrows = L2G ? 256 : 128;
    uint32_t* Ws  = smem;
    uint32_t* Ar  = smem + wrows * 128;
    float*    csm = (float*)(Ar + AR_U32);
    float*    bsm = csm + CS_U32;
    unsigned* cnt = &g_cls_cnt[mcls * 32];

    // ---- one-time: resident weights (packed + swizzled), c zero, b2 slice ----
    for (int idx = tid; idx < wrows * 128; idx += NTHR) {
        int k2 = idx >> 7;
        int nl = idx & 127;
        int wn = nl >> 5;
        int r  = nl & 31;
        int g  = r & 7;
        int q  = r >> 3;
        int dst = k2 * 128 + (((wn << 5) + (g << 2)) ^ ((k2 & 3) << 3)) + q;
        uint32_t v = L2G ? g_W2p[(size_t)k2 * NG + n0 + nl]
                         : g_W1hp[(size_t)k2 * NG + n0 + nl];
        Ws[dst] = v;
    }
    for (int idx = tid; idx < CS_U32; idx += NTHR) csm[idx] = 0.0f;
    if (tid < 128) bsm[tid] = g_b2[n0 + tid];
    __syncthreads();

    unsigned bar_n = 0;

    // prologue: L1 group computes h1(0) = gates(embW) with h1(-1)=0 (no GEMM)
    if (!L2G)
        gemm_phase<true, false, true>(Ws, Ar, csm, bsm, 128,
                                      g_h1p[0] + m0, g_h1p[0] + m0,
                                      g_h1p[1], tokens, 0, m0, n0);
    class_barrier(cnt, 16 * ++bar_n);

    for (int t = 0; t < TSTEPS; t++) {
        if (L2G) {
            // layer2(t): A = [h2(t-1) | h1(t)]
            gemm_phase<false, true, false>(Ws, Ar, csm, bsm, 256,
                                           g_h2p[t & 1] + m0, g_h1p[(t + 1) & 1] + m0,
                                           g_h2p[(t + 1) & 1], tokens, t, m0, n0);
        } else if (t < TSTEPS - 1) {
            // layer1(t+1): A = h1(t)
            gemm_phase<true, false, false>(Ws, Ar, csm, bsm, 128,
                                           g_h1p[(t + 1) & 1] + m0, g_h1p[0] + m0,
                                           g_h1p[t & 1], tokens, t + 1, m0, n0);
        }
        class_barrier(cnt, 16 * ++bar_n);
    }

    grid_barrier();   // all classes done before output

    // final dense + sigmoid; h2(79) packed in g_h2p[0]
    int gw   = cta * (NTHR / 32) + (tid >> 5);
    int lane = tid & 31;
    if (gw < BATCH / 32) {
        int bb = gw * 32 + lane;
        float s = 0.0f;
        const uint32_t* h = g_h2p[0];
        #pragma unroll 8
        for (int u2 = 0; u2 < UDIM / 2; u2++) {
            uint32_t v = h[(size_t)u2 * BATCH + bb];
            float lo = __bfloat162float(__ushort_as_bfloat16((unsigned short)(v & 0xFFFF)));
            float hi = __bfloat162float(__ushort_as_bfloat16((unsigned short)(v >> 16)));
            s += lo * w_out[2 * u2] + hi * w_out[2 * u2 + 1];
        }
        out[bb] = 1.0f / (1.0f + expf(-(s + b_out[0])));
    }
}

// ---------------- launch ----------------
extern "C" void kernel_launch(void* const* d_in, const int* in_sizes, int n_in,
                              void* d_out, int out_size)
{
    const int*   tokens = (const int*)  d_in[0];
    const float* emb    = (const float*)d_in[1];
    const float* wf1 = (const float*)d_in[2];  const float* bf1 = (const float*)d_in[3];
    const float* wi1 = (const float*)d_in[4];  const float* bi1 = (const float*)d_in[5];
    const float* wc1 = (const float*)d_in[6];  const float* bc1 = (const float*)d_in[7];
    const float* wo1 = (const float*)d_in[8];  const float* bo1 = (const float*)d_in[9];
    const float* wf2 = (const float*)d_in[10]; const float* bf2 = (const float*)d_in[11];
    const float* wi2 = (const float*)d_in[12]; const float* bi2 = (const float*)d_in[13];
    const float* wc2 = (const float*)d_in[14]; const float* bc2 = (const float*)d_in[15];
    const float* wo2 = (const float*)d_in[16]; const float* bo2 = (const float*)d_in[17];
    const float* w_out = (const float*)d_in[18];
    const float* b_out = (const float*)d_in[19];
    float* out = (float*)d_out;

    static int smem_set = 0;
    if (!smem_set) {
        cudaFuncSetAttribute(lstm_persistent,
                             cudaFuncAttributeMaxDynamicSharedMemorySize, SMEM_BYTES);
        smem_set = 1;
    }

    const int TOT = 384 * NG + EDIM * NG + 2 * NG;
    pack_kernel<<<(TOT + 255) / 256, 256>>>(wf1, bf1, wi1, bi1, wc1, bc1, wo1, bo1,
                                            wf2, bf2, wi2, bi2, wc2, bc2, wo2, bo2);
    zero_kernel<<<(UDIM / 2 * BATCH + 255) / 256, 256>>>();

    embw_kernel<<<dim3(NG / 64, (VOCAB + 63) / 64), 256>>>(emb);

    lstm_persistent<<<GRID_CTAS, NTHR, SMEM_BYTES>>>(tokens, w_out, b_out, out);
}

// round 16
// speedup vs baseline: 6.6002x; 1.0042x over previous
#include <cuda_runtime.h>
#include <cuda_bf16.h>
#include <math.h>
#include <stdint.h>

#define BATCH 1024
#define TSTEPS 80
#define EDIM 100
#define UDIM 256
#define NG 1024       // 4 gates * U, packed n = u*4 + g
#define VOCAB 10000
#define GRID_CTAS 128
#define NTHR 512

// packed k-pair rows: Layer1 = 128, Layer2 = 256. Chunk = 64 rows (128 k).
#define KC2 64

// smem (u32): Ws[<=256][128] + Ar[2][64][128] + csm[4096] + bsm[128]
#define WS_U32_MAX (256 * 128)
#define AR_U32 (2 * KC2 * 128)
#define CS_U32 (32 * 128)
#define SMEM_BYTES ((WS_U32_MAX + AR_U32 + CS_U32 + 128) * 4)   // 213504 B

// ---------------- persistent device scratch ----------------
__device__ __align__(16) uint32_t g_W1hp[128 * NG];        // bf16x2 [k2][n]
__device__ __align__(16) uint32_t g_W2p [256 * NG];        // bf16x2 [k2][n]
__device__ __align__(16) float g_W1x[EDIM * NG];           // fp32 exact, [k][n]
__device__ __align__(16) float g_b1[NG];
__device__ __align__(16) float g_b2[NG];
__device__ __align__(16) float g_embW[(size_t)VOCAB * NG]; // fp32 exact: emb@W1x + b1
// h1: ring of 4 (L1 may run ahead of L2 by <=3 steps); h2: double buffer
__device__ __align__(16) uint32_t g_h1p[4][(UDIM / 2) * BATCH];
__device__ __align__(16) uint32_t g_h2p[2][(UDIM / 2) * BATCH];
__device__ unsigned g_bar_count = 0;
__device__ unsigned g_bar_gen = 0;
__device__ unsigned g_l1_done[8 * 32];   // per-class monotonic phase counters
__device__ unsigned g_l2_done[8 * 32];

__device__ __forceinline__ float tanh_ap(float x) {
    float r; asm("tanh.approx.f32 %0, %1;" : "=f"(r) : "f"(x)); return r;
}
__device__ __forceinline__ float sigmoid_ap(float x) {
    return 0.5f * tanh_ap(0.5f * x) + 0.5f;
}
__device__ __forceinline__ uint32_t pack_bf2(float lo, float hi) {
    unsigned l = __bfloat16_as_ushort(__float2bfloat16_rn(lo));
    unsigned h = __bfloat16_as_ushort(__float2bfloat16_rn(hi));
    return l | (h << 16);
}
__device__ __forceinline__ uint32_t smem_u32(const void* p) {
    uint32_t a;
    asm("{ .reg .u64 t; cvta.to.shared.u64 t, %1; cvt.u32.u64 %0, t; }" : "=r"(a) : "l"(p));
    return a;
}
__device__ __forceinline__ void cp16(uint32_t dst, const void* src) {
    asm volatile("cp.async.cg.shared.global [%0], [%1], 16;" :: "r"(dst), "l"(src));
}
__device__ __forceinline__ void cp_commit() { asm volatile("cp.async.commit_group;"); }
__device__ __forceinline__ void cp_wait1()  { asm volatile("cp.async.wait_group 1;"); }
__device__ __forceinline__ void cp_wait0()  { asm volatile("cp.async.wait_group 0;"); }

__device__ __forceinline__ void mma_bf16(float* c, const uint32_t* a, const uint32_t* b) {
    asm volatile(
        "mma.sync.aligned.m16n8k16.row.col.f32.bf16.bf16.f32 "
        "{%0,%1,%2,%3}, {%4,%5,%6,%7}, {%8,%9}, {%0,%1,%2,%3};"
        : "+f"(c[0]), "+f"(c[1]), "+f"(c[2]), "+f"(c[3])
        : "r"(a[0]), "r"(a[1]), "r"(a[2]), "r"(a[3]), "r"(b[0]), "r"(b[1]));
}

// ---------------- producer/consumer sync ----------------
// signal: all CTA stores done -> one release-add on a class counter
__device__ __forceinline__ void cls_signal(unsigned* cnt) {
    __syncthreads();
    if (threadIdx.x == 0) {
        unsigned old;
        asm volatile("atom.release.gpu.global.add.u32 %0, [%1], 1;"
                     : "=r"(old) : "l"(cnt) : "memory");
    }
}
// wait: spin until counter >= target, then publish to whole CTA
__device__ __forceinline__ void cls_wait(const unsigned* cnt, unsigned target) {
    if (threadIdx.x == 0) {
        unsigned cur;
        do {
            asm volatile("ld.acquire.gpu.global.u32 %0, [%1];"
                         : "=r"(cur) : "l"(cnt) : "memory");
        } while (cur < target);
    }
    __syncthreads();
}

// full-grid barrier (used once, before the output stage)
__device__ __forceinline__ void grid_barrier() {
    __syncthreads();
    if (threadIdx.x == 0) {
        unsigned gen;
        asm volatile("ld.relaxed.gpu.global.u32 %0, [%1];"
                     : "=r"(gen) : "l"(&g_bar_gen));
        unsigned old;
        asm volatile("atom.release.gpu.global.add.u32 %0, [%1], 1;"
                     : "=r"(old) : "l"(&g_bar_count) : "memory");
        if (old == GRID_CTAS - 1) {
            asm volatile("st.relaxed.gpu.global.u32 [%0], %1;"
                         :: "l"(&g_bar_count), "r"(0u) : "memory");
            asm volatile("st.release.gpu.global.u32 [%0], %1;"
                         :: "l"(&g_bar_gen), "r"(gen + 1) : "memory");
        } else {
            unsigned cur;
            do {
                asm volatile("ld.acquire.gpu.global.u32 %0, [%1];"
                             : "=r"(cur) : "l"(&g_bar_gen) : "memory");
            } while (cur == gen);
        }
    }
    __syncthreads();
}

// ---------------- pack: n = u*4+g; recurrent W as bf16x2 k-pairs; W1x exact ----------------
__global__ void pack_kernel(
    const float* wf1, const float* bf1, const float* wi1, const float* bi1,
    const float* wc1, const float* bc1, const float* wo1, const float* bo1,
    const float* wf2, const float* bf2, const float* wi2, const float* bi2,
    const float* wc2, const float* bc2, const float* wo2, const float* bo2)
{
    const int TOT_P = 384 * NG;
    const int TOT_X = EDIM * NG;
    int id = blockIdx.x * blockDim.x + threadIdx.x;
    if (id < TOT_P) {
        int k2 = id >> 10;
        int n  = id & 1023;
        int u  = n >> 2;
        int g  = n & 3;
        if (k2 < 128) {
            const float* w = (g == 0) ? wf1 : (g == 1) ? wi1 : (g == 2) ? wc1 : wo1;
            g_W1hp[k2 * NG + n] = pack_bf2(w[(2 * k2) * UDIM + u],
                                           w[(2 * k2 + 1) * UDIM + u]);
        } else {
            int kk = k2 - 128;
            const float* w = (g == 0) ? wf2 : (g == 1) ? wi2 : (g == 2) ? wc2 : wo2;
            g_W2p[kk * NG + n] = pack_bf2(w[(2 * kk) * UDIM + u],
                                          w[(2 * kk + 1) * UDIM + u]);
        }
    } else if (id < TOT_P + TOT_X) {
        int j = id - TOT_P;
        int kk = j >> 10;
        int n  = j & 1023;
        int u  = n >> 2;
        int g  = n & 3;
        const float* w = (g == 0) ? wf1 : (g == 1) ? wi1 : (g == 2) ? wc1 : wo1;
        g_W1x[kk * NG + n] = w[(UDIM + kk) * UDIM + u];
    } else if (id < TOT_P + TOT_X + 2 * NG) {
        int j = id - TOT_P - TOT_X;
        int n = j & 1023;
        int u = n >> 2;
        int g = n & 3;
        if (j < NG) g_b1[n] = ((g == 0) ? bf1 : (g == 1) ? bi1 : (g == 2) ? bc1 : bo1)[u];
        else        g_b2[n] = ((g == 0) ? bf2 : (g == 1) ? bi2 : (g == 2) ? bc2 : bo2)[u];
    }
}

__global__ void zero_kernel()
{
    int id = blockIdx.x * blockDim.x + threadIdx.x;
    if (id < 8 * 32) { g_l1_done[id] = 0; g_l2_done[id] = 0; }
    if (id < (UDIM / 2) * BATCH) g_h2p[0][id] = 0u;   // h2(-1) = 0
}

// ---------------- embW = emb @ W1x + b1 (fp32 exact) ----------------
__global__ __launch_bounds__(256) void embw_kernel(const float* __restrict__ emb)
{
    __shared__ __align__(16) float As[32][64];
    __shared__ __align__(16) float Bs[32][64];

    const int tid = threadIdx.x;
    const int m0  = blockIdx.y * 64;
    const int n0  = blockIdx.x * 64;
    const int tm  = tid >> 4;
    const int tn  = tid & 15;

    float acc[4][4] = {};

    for (int k0 = 0; k0 < 128; k0 += 32) {
        #pragma unroll
        for (int i = 0; i < 2; i++) {
            int f4 = tid + i * 256;
            int m  = f4 >> 3;
            int kq = f4 & 7;
            int k  = k0 + kq * 4;
            float4 v = make_float4(0.f, 0.f, 0.f, 0.f);
            int row = m0 + m;
            if (k < EDIM && row < VOCAB)
                v = *(const float4*)&emb[(size_t)row * EDIM + k];
            As[kq * 4 + 0][m] = v.x;
            As[kq * 4 + 1][m] = v.y;
            As[kq * 4 + 2][m] = v.z;
            As[kq * 4 + 3][m] = v.w;
        }
        #pragma unroll
        for (int i = 0; i < 2; i++) {
            int f4 = tid + i * 256;
            int kk = f4 >> 4;
            int c4 = f4 & 15;
            int k  = k0 + kk;
            float4 v = make_float4(0.f, 0.f, 0.f, 0.f);
            if (k < EDIM) v = *(const float4*)&g_W1x[k * NG + n0 + c4 * 4];
            *(float4*)&Bs[kk][c4 * 4] = v;
        }
        __syncthreads();

        #pragma unroll
        for (int k = 0; k < 32; k++) {
            float4 b = *(const float4*)&Bs[k][tn * 4];
            float4 a = *(const float4*)&As[k][tm * 4];
            float ar[4] = {a.x, a.y, a.z, a.w};
            float br[4] = {b.x, b.y, b.z, b.w};
            #pragma unroll
            for (int r = 0; r < 4; r++)
                #pragma unroll
                for (int c = 0; c < 4; c++)
                    acc[r][c] += ar[r] * br[c];
        }
        __syncthreads();
    }

    float4 bb = *(const float4*)&g_b1[n0 + tn * 4];
    #pragma unroll
    for (int r = 0; r < 4; r++) {
        int row = m0 + tm * 4 + r;
        if (row < VOCAB)
            *(float4*)&g_embW[(size_t)row * NG + n0 + tn * 4] =
                make_float4(acc[r][0] + bb.x, acc[r][1] + bb.y,
                            acc[r][2] + bb.z, acc[r][3] + bb.w);
    }
}

// ---------------- persistent kernel: decoupled L1/L2 chains ----------------
// CTAs 0-63: layer2 (K2=256). CTAs 64-127: layer1 (K2=128).
// L1 free-runs its recurrence (h1 ring of 4), L2 consumes via counters.
// CTA tile 128M x 128N; 16 warps (4m x 4n); warp tile 32M x 32N; mma m16n8k16.
// c state in per-CTA smem; b2 slice cached in smem.

__device__ __forceinline__ void stage_A(uint32_t* dst, const uint32_t* __restrict__ src, int tid)
{
    #pragma unroll
    for (int i = 0; i < 4; i++) {
        int f4 = tid + i * NTHR;        // 0..2047
        int kq = f4 >> 5;               // 0..63 packed rows
        int c4 = f4 & 31;               // 0..31 (x4 cols = 128)
        int col = (c4 * 4) ^ ((kq & 3) * 8);
        cp16(smem_u32(dst + kq * 128 + col), src + (size_t)kq * BATCH + c4 * 4);
    }
}

template <bool L1P, bool DUAL, bool ZERO>
__device__ __forceinline__ void gemm_phase(
    const uint32_t* __restrict__ Ws,   // resident weights, row stride 128
    uint32_t* __restrict__ Ar,
    float* __restrict__ csm,           // smem c state [u_local(32)][m_local(128)]
    const float* __restrict__ bsm,     // smem b2 slice (L2 only)
    int K2,
    const uint32_t* __restrict__ A0,   // packed h [u2][b] + m0 (h2 for DUAL)
    const uint32_t* __restrict__ A1,   // h1 source for DUAL (k2 >= 128) + m0
    uint32_t* __restrict__ houtp,
    const int* __restrict__ tokens, int t, int m0, int n0)
{
    const int tid  = threadIdx.x;
    const int lane = tid & 31;
    const int wid  = tid >> 5;
    const int s    = lane & 3;
    const int g    = lane >> 2;
    const int wm   = wid & 3;          // 4 m-warps
    const int wn   = wid >> 2;         // 4 n-warps

    const int cm0  = (wm * 32 + g) ^ (8 * s);
    const int cb   = (wn * 32 + g * 4) ^ (8 * s);

    float acc[2][4][4];
    #pragma unroll
    for (int a = 0; a < 2; a++)
        #pragma unroll
        for (int b = 0; b < 4; b++)
            #pragma unroll
            for (int c = 0; c < 4; c++) acc[a][b][c] = 0.0f;

    if (!ZERO) {
        stage_A(Ar, A0, tid);
        cp_commit();

        const int C = K2 / KC2;        // 2 (L1) or 4 (L2)
        for (int c = 0; c < C; c++) {
            int cur = c & 1;
            if (c + 1 < C) {
                int r0 = (c + 1) * KC2;
                const uint32_t* srcn = (DUAL && r0 >= 128) ?
                                       A1 + (size_t)(r0 - 128) * BATCH :
                                       A0 + (size_t)r0 * BATCH;
                stage_A(Ar + (1 - cur) * (KC2 * 128), srcn, tid);
                cp_commit();
                cp_wait1();
            } else {
                cp_wait0();
            }
            __syncthreads();

            const uint32_t* Ab = Ar + cur * (KC2 * 128) + s * 128;
            const uint32_t* Bb = Ws + ((size_t)(c * KC2) + s) * 128 + cb;

            #pragma unroll
            for (int sl = 0; sl < KC2 / 8; sl++) {       // 8 slabs of k16
                const uint32_t* ap = Ab + sl * (8 * 128);
                const uint32_t* bp = Bb + sl * (8 * 128);
                uint4 b0 = *(const uint4*)bp;            // k2 = s
                uint4 b1 = *(const uint4*)(bp + 4 * 128);// k2 = s+4
                uint32_t bf[4][2] = {
                    { b0.x, b1.x }, { b0.y, b1.y }, { b0.z, b1.z }, { b0.w, b1.w }
                };
                #pragma unroll
                for (int mt = 0; mt < 2; mt++) {
                    const int cc = cm0 ^ (mt * 16);
                    uint32_t af[4];
                    af[0] = ap[cc];
                    af[1] = ap[cc ^ 8];
                    af[2] = ap[4 * 128 + cc];
                    af[3] = ap[4 * 128 + (cc ^ 8)];
                    #pragma unroll
                    for (int nt = 0; nt < 4; nt++)
                        mma_bf16(acc[mt][nt], af, bf[nt]);
                }
            }
            __syncthreads();
        }
    }

    // ---- fused LSTM epilogue (c in smem; bias from smem for L2) ----
    #pragma unroll
    for (int mt = 0; mt < 2; mt++) {
        const int mloc = wm * 32 + mt * 16 + g + ((lane & 1) << 3);
        const int m = m0 + mloc;
        int tok = 0;
        if (L1P) tok = tokens[m * TSTEPS + t];
        #pragma unroll
        for (int nt = 0; nt < 4; nt++) {
            float* a = acc[mt][nt];
            float v1 = __shfl_xor_sync(0xFFFFFFFFu, (lane & 1) ? a[0] : a[2], 1);
            float v2 = __shfl_xor_sync(0xFFFFFFFFu, (lane & 1) ? a[1] : a[3], 1);
            float pf, pi, pc, po;
            if (lane & 1) { pc = a[2]; po = a[3]; pf = v1; pi = v2; }
            else          { pf = a[0]; pi = a[1]; pc = v1; po = v2; }

            const int uloc = wn * 8 + nt * 2 + (s >> 1);   // 0..31
            float4 x;
            if (L1P) {
                const int u = (n0 >> 2) + uloc;
                x = *(const float4*)&g_embW[(size_t)tok * NG + u * 4];
            } else {
                x = *(const float4*)&bsm[uloc * 4];
            }
            pf += x.x; pi += x.y; pc += x.z; po += x.w;
            float cold = csm[uloc * 128 + mloc];
            float cn = sigmoid_ap(pf) * cold + sigmoid_ap(pi) * tanh_ap(pc);
            csm[uloc * 128 + mloc] = cn;
            float hn = sigmoid_ap(po) * tanh_ap(cn);
            float ho = __shfl_xor_sync(0xFFFFFFFFu, hn, 2);
            if ((lane & 2) == 0) {
                const int nb = n0 + wn * 32 + nt * 8;
                const int u2 = nb >> 3;
                houtp[(size_t)u2 * BATCH + m] = pack_bf2(hn, ho);
            }
        }
    }
}

__global__ __launch_bounds__(NTHR, 1) void lstm_persistent(
    const int* __restrict__ tokens,
    const float* __restrict__ w_out, const float* __restrict__ b_out,
    float* __restrict__ out)
{
    extern __shared__ __align__(16) uint32_t smem[];

    const int cta  = blockIdx.x;
    const bool L2G = (cta < 64);
    const int n0   = (cta & 7) * 128;        // 8 n-tiles
    const int mcls = (cta >> 3) & 7;         // m0 class 0..7
    const int m0   = mcls * 128;
    const int tid  = threadIdx.x;

    const int wrows = L2G ? 256 : 128;
    uint32_t* Ws  = smem;
    uint32_t* Ar  = smem + wrows * 128;
    float*    csm = (float*)(Ar + AR_U32);
    float*    bsm = csm + CS_U32;
    unsigned* l1c = &g_l1_done[mcls * 32];
    unsigned* l2c = &g_l2_done[mcls * 32];

    // ---- one-time: resident weights (packed + swizzled), c zero, b2 slice ----
    for (int idx = tid; idx < wrows * 128; idx += NTHR) {
        int k2 = idx >> 7;
        int nl = idx & 127;
        int wn = nl >> 5;
        int r  = nl & 31;
        int g  = r & 7;
        int q  = r >> 3;
        int dst = k2 * 128 + (((wn << 5) + (g << 2)) ^ ((k2 & 3) << 3)) + q;
        uint32_t v = L2G ? g_W2p[(size_t)k2 * NG + n0 + nl]
                         : g_W1hp[(size_t)k2 * NG + n0 + nl];
        Ws[dst] = v;
    }
    for (int idx = tid; idx < CS_U32; idx += NTHR) csm[idx] = 0.0f;
    if (tid < 128) bsm[tid] = g_b2[n0 + tid];
    __syncthreads();

    if (!L2G) {
        // ---------------- L1 chain: free-running recurrence ----------------
        // t=0: h1(0) = gates(embW), h1(-1)=0 (no GEMM)
        gemm_phase<true, false, true>(Ws, Ar, csm, bsm, 128,
                                      g_h1p[0] + m0, g_h1p[0] + m0,
                                      g_h1p[0], tokens, 0, m0, n0);
        cls_signal(l1c);
        for (int t = 1; t < TSTEPS; t++) {
            cls_wait(l1c, 8u * t);                    // peers' h1(t-1)
            if (t >= 4) cls_wait(l2c, 8u * (t - 3));  // ring anti-overwrite
            gemm_phase<true, false, false>(Ws, Ar, csm, bsm, 128,
                                           g_h1p[(t - 1) & 3] + m0, g_h1p[0] + m0,
                                           g_h1p[t & 3], tokens, t, m0, n0);
            cls_signal(l1c);
        }
    } else {
        // ---------------- L2 chain: the critical path ----------------
        for (int t = 0; t < TSTEPS; t++) {
            if (t > 0) cls_wait(l2c, 8u * t);         // peers' h2(t-1)
            cls_wait(l1c, 8u * (t + 1));              // h1(t) ready
            gemm_phase<false, true, false>(Ws, Ar, csm, bsm, 256,
                                           g_h2p[t & 1] + m0, g_h1p[t & 3] + m0,
                                           g_h2p[(t + 1) & 1], tokens, t, m0, n0);
            cls_signal(l2c);
        }
    }

    grid_barrier();   // all chains done before output

    // final dense + sigmoid; h2(79) packed in g_h2p[0]
    int gw   = cta * (NTHR / 32) + (tid >> 5);
    int lane = tid & 31;
    if (gw < BATCH / 32) {
        int bb = gw * 32 + lane;
        float s = 0.0f;
        const uint32_t* h = g_h2p[0];
        #pragma unroll 8
        for (int u2 = 0; u2 < UDIM / 2; u2++) {
            uint32_t v = h[(size_t)u2 * BATCH + bb];
            float lo = __bfloat162float(__ushort_as_bfloat16((unsigned short)(v & 0xFFFF)));
            float hi = __bfloat162float(__ushort_as_bfloat16((unsigned short)(v >> 16)));
            s += lo * w_out[2 * u2] + hi * w_out[2 * u2 + 1];
        }
        out[bb] = 1.0f / (1.0f + expf(-(s + b_out[0])));
    }
}

// ---------------- launch ----------------
extern "C" void kernel_launch(void* const* d_in, const int* in_sizes, int n_in,
                              void* d_out, int out_size)
{
    const int*   tokens = (const int*)  d_in[0];
    const float* emb    = (const float*)d_in[1];
    const float* wf1 = (const float*)d_in[2];  const float* bf1 = (const float*)d_in[3];
    const float* wi1 = (const float*)d_in[4];  const float* bi1 = (const float*)d_in[5];
    const float* wc1 = (const float*)d_in[6];  const float* bc1 = (const float*)d_in[7];
    const float* wo1 = (const float*)d_in[8];  const float* bo1 = (const float*)d_in[9];
    const float* wf2 = (const float*)d_in[10]; const float* bf2 = (const float*)d_in[11];
    const float* wi2 = (const float*)d_in[12]; const float* bi2 = (const float*)d_in[13];
    const float* wc2 = (const float*)d_in[14]; const float* bc2 = (const float*)d_in[15];
    const float* wo2 = (const float*)d_in[16]; const float* bo2 = (const float*)d_in[17];
    const float* w_out = (const float*)d_in[18];
    const float* b_out = (const float*)d_in[19];
    float* out = (float*)d_out;

    static int smem_set = 0;
    if (!smem_set) {
        cudaFuncSetAttribute(lstm_persistent,
                             cudaFuncAttributeMaxDynamicSharedMemorySize, SMEM_BYTES);
        smem_set = 1;
    }

    const int TOT = 384 * NG + EDIM * NG + 2 * NG;
    pack_kernel<<<(TOT + 255) / 256, 256>>>(wf1, bf1, wi1, bi1, wc1, bc1, wo1, bo1,
                                            wf2, bf2, wi2, bi2, wc2, bc2, wo2, bo2);
    zero_kernel<<<(UDIM / 2 * BATCH + 255) / 256, 256>>>();

    embw_kernel<<<dim3(NG / 64, (VOCAB + 63) / 64), 256>>>(emb);

    lstm_persistent<<<GRID_CTAS, NTHR, SMEM_BYTES>>>(tokens, w_out, b_out, out);
}

// round 17
// speedup vs baseline: 6.6903x; 1.0136x over previous
#include <cuda_runtime.h>
#include <cuda_bf16.h>
#include <math.h>
#include <stdint.h>

#define BATCH 1024
#define TSTEPS 80
#define EDIM 100
#define UDIM 256
#define NG 1024       // 4 gates * U, packed n = u*4 + g
#define VOCAB 10000
#define GRID_CTAS 128
#define NTHR 512

#define KC2 64        // packed k2 rows per chunk (128 k)

// smem (u32): Ws[<=256][128] | Ar[2][64][128] | csm[4096] | bsm[128] | esm[128*132]
#define AR_U32  (2 * KC2 * 128)
#define CS_U32  (32 * 128)
#define ESM_STRIDE 132
#define ESM_U32 (128 * ESM_STRIDE)
// L1: 128*128 + AR + CS + 128 + ESM = 53888 u32 ; L2: 256*128 + AR + CS + 128 = 53376
#define SMEM_BYTES (53888 * 4)   // 215552 B

// ---------------- persistent device scratch ----------------
__device__ __align__(16) uint32_t g_W1hp[128 * NG];        // bf16x2 [k2][n]
__device__ __align__(16) uint32_t g_W2p [256 * NG];        // bf16x2 [k2][n]
__device__ __align__(16) float g_W1x[EDIM * NG];           // fp32 exact, [k][n]
__device__ __align__(16) float g_b1[NG];
__device__ __align__(16) float g_b2[NG];
__device__ __align__(16) float g_embW[(size_t)VOCAB * NG]; // fp32 exact: emb@W1x + b1
__device__ __align__(16) uint32_t g_h1p[4][(UDIM / 2) * BATCH];  // ring of 4
__device__ __align__(16) uint32_t g_h2p[2][(UDIM / 2) * BATCH];
__device__ unsigned g_bar_count = 0;
__device__ unsigned g_bar_gen = 0;
__device__ unsigned g_l1_done[8 * 32];
__device__ unsigned g_l2_done[8 * 32];

__device__ __forceinline__ float tanh_ap(float x) {
    float r; asm("tanh.approx.f32 %0, %1;" : "=f"(r) : "f"(x)); return r;
}
__device__ __forceinline__ float sigmoid_ap(float x) {
    return 0.5f * tanh_ap(0.5f * x) + 0.5f;
}
__device__ __forceinline__ uint32_t pack_bf2(float lo, float hi) {
    unsigned l = __bfloat16_as_ushort(__float2bfloat16_rn(lo));
    unsigned h = __bfloat16_as_ushort(__float2bfloat16_rn(hi));
    return l | (h << 16);
}
__device__ __forceinline__ uint32_t smem_u32(const void* p) {
    uint32_t a;
    asm("{ .reg .u64 t; cvta.to.shared.u64 t, %1; cvt.u32.u64 %0, t; }" : "=r"(a) : "l"(p));
    return a;
}
__device__ __forceinline__ void cp16(uint32_t dst, const void* src) {
    asm volatile("cp.async.cg.shared.global [%0], [%1], 16;" :: "r"(dst), "l"(src));
}
__device__ __forceinline__ void cp_commit() { asm volatile("cp.async.commit_group;"); }
__device__ __forceinline__ void cp_wait2()  { asm volatile("cp.async.wait_group 2;"); }
__device__ __forceinline__ void cp_wait1()  { asm volatile("cp.async.wait_group 1;"); }
__device__ __forceinline__ void cp_wait0()  { asm volatile("cp.async.wait_group 0;"); }

__device__ __forceinline__ void mma_bf16(float* c, const uint32_t* a, const uint32_t* b) {
    asm volatile(
        "mma.sync.aligned.m16n8k16.row.col.f32.bf16.bf16.f32 "
        "{%0,%1,%2,%3}, {%4,%5,%6,%7}, {%8,%9}, {%0,%1,%2,%3};"
        : "+f"(c[0]), "+f"(c[1]), "+f"(c[2]), "+f"(c[3])
        : "r"(a[0]), "r"(a[1]), "r"(a[2]), "r"(a[3]), "r"(b[0]), "r"(b[1]));
}

// ---------------- producer/consumer sync ----------------
__device__ __forceinline__ void cls_signal(unsigned* cnt) {
    __syncthreads();
    if (threadIdx.x == 0) {
        unsigned old;
        asm volatile("atom.release.gpu.global.add.u32 %0, [%1], 1;"
                     : "=r"(old) : "l"(cnt) : "memory");
    }
}
__device__ __forceinline__ void cls_wait(const unsigned* cnt, unsigned target) {
    if (threadIdx.x == 0) {
        unsigned cur;
        do {
            asm volatile("ld.acquire.gpu.global.u32 %0, [%1];"
                         : "=r"(cur) : "l"(cnt) : "memory");
        } while (cur < target);
    }
    __syncthreads();
}
__device__ __forceinline__ void grid_barrier() {
    __syncthreads();
    if (threadIdx.x == 0) {
        unsigned gen;
        asm volatile("ld.relaxed.gpu.global.u32 %0, [%1];"
                     : "=r"(gen) : "l"(&g_bar_gen));
        unsigned old;
        asm volatile("atom.release.gpu.global.add.u32 %0, [%1], 1;"
                     : "=r"(old) : "l"(&g_bar_count) : "memory");
        if (old == GRID_CTAS - 1) {
            asm volatile("st.relaxed.gpu.global.u32 [%0], %1;"
                         :: "l"(&g_bar_count), "r"(0u) : "memory");
            asm volatile("st.release.gpu.global.u32 [%0], %1;"
                         :: "l"(&g_bar_gen), "r"(gen + 1) : "memory");
        } else {
            unsigned cur;
            do {
                asm volatile("ld.acquire.gpu.global.u32 %0, [%1];"
                             : "=r"(cur) : "l"(&g_bar_gen) : "memory");
            } while (cur == gen);
        }
    }
    __syncthreads();
}

// ---------------- pack: n = u*4+g; recurrent W as bf16x2 k-pairs; W1x exact ----------------
__global__ void pack_kernel(
    const float* wf1, const float* bf1, const float* wi1, const float* bi1,
    const float* wc1, const float* bc1, const float* wo1, const float* bo1,
    const float* wf2, const float* bf2, const float* wi2, const float* bi2,
    const float* wc2, const float* bc2, const float* wo2, const float* bo2)
{
    const int TOT_P = 384 * NG;
    const int TOT_X = EDIM * NG;
    int id = blockIdx.x * blockDim.x + threadIdx.x;
    if (id < TOT_P) {
        int k2 = id >> 10;
        int n  = id & 1023;
        int u  = n >> 2;
        int g  = n & 3;
        if (k2 < 128) {
            const float* w = (g == 0) ? wf1 : (g == 1) ? wi1 : (g == 2) ? wc1 : wo1;
            g_W1hp[k2 * NG + n] = pack_bf2(w[(2 * k2) * UDIM + u],
                                           w[(2 * k2 + 1) * UDIM + u]);
        } else {
            int kk = k2 - 128;
            const float* w = (g == 0) ? wf2 : (g == 1) ? wi2 : (g == 2) ? wc2 : wo2;
            g_W2p[kk * NG + n] = pack_bf2(w[(2 * kk) * UDIM + u],
                                          w[(2 * kk + 1) * UDIM + u]);
        }
    } else if (id < TOT_P + TOT_X) {
        int j = id - TOT_P;
        int kk = j >> 10;
        int n  = j & 1023;
        int u  = n >> 2;
        int g  = n & 3;
        const float* w = (g == 0) ? wf1 : (g == 1) ? wi1 : (g == 2) ? wc1 : wo1;
        g_W1x[kk * NG + n] = w[(UDIM + kk) * UDIM + u];
    } else if (id < TOT_P + TOT_X + 2 * NG) {
        int j = id - TOT_P - TOT_X;
        int n = j & 1023;
        int u = n >> 2;
        int g = n & 3;
        if (j < NG) g_b1[n] = ((g == 0) ? bf1 : (g == 1) ? bi1 : (g == 2) ? bc1 : bo1)[u];
        else        g_b2[n] = ((g == 0) ? bf2 : (g == 1) ? bi2 : (g == 2) ? bc2 : bo2)[u];
    }
}

__global__ void zero_kernel()
{
    int id = blockIdx.x * blockDim.x + threadIdx.x;
    if (id < 8 * 32) { g_l1_done[id] = 0; g_l2_done[id] = 0; }
    if (id < (UDIM / 2) * BATCH) g_h2p[0][id] = 0u;   // h2(-1) = 0
}

// ---------------- embW = emb @ W1x + b1 (fp32 exact) ----------------
__global__ __launch_bounds__(256) void embw_kernel(const float* __restrict__ emb)
{
    __shared__ __align__(16) float As[32][64];
    __shared__ __align__(16) float Bs[32][64];

    const int tid = threadIdx.x;
    const int m0  = blockIdx.y * 64;
    const int n0  = blockIdx.x * 64;
    const int tm  = tid >> 4;
    const int tn  = tid & 15;

    float acc[4][4] = {};

    for (int k0 = 0; k0 < 128; k0 += 32) {
        #pragma unroll
        for (int i = 0; i < 2; i++) {
            int f4 = tid + i * 256;
            int m  = f4 >> 3;
            int kq = f4 & 7;
            int k  = k0 + kq * 4;
            float4 v = make_float4(0.f, 0.f, 0.f, 0.f);
            int row = m0 + m;
            if (k < EDIM && row < VOCAB)
                v = *(const float4*)&emb[(size_t)row * EDIM + k];
            As[kq * 4 + 0][m] = v.x;
            As[kq * 4 + 1][m] = v.y;
            As[kq * 4 + 2][m] = v.z;
            As[kq * 4 + 3][m] = v.w;
        }
        #pragma unroll
        for (int i = 0; i < 2; i++) {
            int f4 = tid + i * 256;
            int kk = f4 >> 4;
            int c4 = f4 & 15;
            int k  = k0 + kk;
            float4 v = make_float4(0.f, 0.f, 0.f, 0.f);
            if (k < EDIM) v = *(const float4*)&g_W1x[k * NG + n0 + c4 * 4];
            *(float4*)&Bs[kk][c4 * 4] = v;
        }
        __syncthreads();

        #pragma unroll
        for (int k = 0; k < 32; k++) {
            float4 b = *(const float4*)&Bs[k][tn * 4];
            float4 a = *(const float4*)&As[k][tm * 4];
            float ar[4] = {a.x, a.y, a.z, a.w};
            float br[4] = {b.x, b.y, b.z, b.w};
            #pragma unroll
            for (int r = 0; r < 4; r++)
                #pragma unroll
                for (int c = 0; c < 4; c++)
                    acc[r][c] += ar[r] * br[c];
        }
        __syncthreads();
    }

    float4 bb = *(const float4*)&g_b1[n0 + tn * 4];
    #pragma unroll
    for (int r = 0; r < 4; r++) {
        int row = m0 + tm * 4 + r;
        if (row < VOCAB)
            *(float4*)&g_embW[(size_t)row * NG + n0 + tn * 4] =
                make_float4(acc[r][0] + bb.x, acc[r][1] + bb.y,
                            acc[r][2] + bb.z, acc[r][3] + bb.w);
    }
}

// ---------------- staging ----------------
__device__ __forceinline__ void stage_A(uint32_t* dst, const uint32_t* __restrict__ src, int tid)
{
    #pragma unroll
    for (int i = 0; i < 4; i++) {
        int f4 = tid + i * NTHR;        // 0..2047
        int kq = f4 >> 5;               // 0..63 packed rows
        int c4 = f4 & 31;               // 0..31 (x4 cols = 128)
        int col = (c4 * 4) ^ ((kq & 3) * 8);
        cp16(smem_u32(dst + kq * 128 + col), src + (size_t)kq * BATCH + c4 * 4);
    }
}

// embW prefetch: thread tid>>2 owns m-row, tid&3 owns a 128B quarter of the 512B row
__device__ __forceinline__ void stage_emb(float* esm, const int* __restrict__ tokens,
                                          int t, int m0, int n0, int tid)
{
    int row  = tid >> 2;                // 0..127
    int part = tid & 3;                 // 0..3
    int tok  = tokens[(m0 + row) * TSTEPS + t];
    const float* src = g_embW + (size_t)tok * NG + n0 + part * 32;
    float* dst = esm + row * ESM_STRIDE + part * 32;
    #pragma unroll
    for (int i = 0; i < 8; i++)
        cp16(smem_u32(dst + i * 4), src + i * 4);
}

// ---------------- one K=128 chunk of MMA ----------------
__device__ __forceinline__ void compute_chunk(
    const uint32_t* __restrict__ Abuf,   // Ar + buf*(KC2*128)
    const uint32_t* __restrict__ Brows,  // Ws + c*KC2*128
    int s, int cb, int cm0, float acc[2][4][4])
{
    const uint32_t* Ab = Abuf + s * 128;
    const uint32_t* Bb = Brows + s * 128 + cb;
    #pragma unroll
    for (int sl = 0; sl < KC2 / 8; sl++) {
        const uint32_t* ap = Ab + sl * (8 * 128);
        const uint32_t* bp = Bb + sl * (8 * 128);
        uint4 b0 = *(const uint4*)bp;
        uint4 b1 = *(const uint4*)(bp + 4 * 128);
        uint32_t bf[4][2] = {
            { b0.x, b1.x }, { b0.y, b1.y }, { b0.z, b1.z }, { b0.w, b1.w }
        };
        #pragma unroll
        for (int mt = 0; mt < 2; mt++) {
            const int cc = cm0 ^ (mt * 16);
            uint32_t af[4];
            af[0] = ap[cc];
            af[1] = ap[cc ^ 8];
            af[2] = ap[4 * 128 + cc];
            af[3] = ap[4 * 128 + (cc ^ 8)];
            #pragma unroll
            for (int nt = 0; nt < 4; nt++)
                mma_bf16(acc[mt][nt], af, bf[nt]);
        }
    }
}

// ---------------- fused LSTM epilogue ----------------
template <bool L1P>
__device__ __forceinline__ void epilogue(
    float acc[2][4][4], float* __restrict__ csm,
    const float* __restrict__ xs,       // L1: esm (stride 132); L2: bsm
    uint32_t* __restrict__ houtp, int m0, int n0)
{
    const int lane = threadIdx.x & 31;
    const int wid  = threadIdx.x >> 5;
    const int s    = lane & 3;
    const int g    = lane >> 2;
    const int wm   = wid & 3;
    const int wn   = wid >> 2;

    #pragma unroll
    for (int mt = 0; mt < 2; mt++) {
        const int mloc = wm * 32 + mt * 16 + g + ((lane & 1) << 3);
        const int m = m0 + mloc;
        #pragma unroll
        for (int nt = 0; nt < 4; nt++) {
            float* a = acc[mt][nt];
            float v1 = __shfl_xor_sync(0xFFFFFFFFu, (lane & 1) ? a[0] : a[2], 1);
            float v2 = __shfl_xor_sync(0xFFFFFFFFu, (lane & 1) ? a[1] : a[3], 1);
            float pf, pi, pc, po;
            if (lane & 1) { pc = a[2]; po = a[3]; pf = v1; pi = v2; }
            else          { pf = a[0]; pi = a[1]; pc = v1; po = v2; }

            const int uloc = wn * 8 + nt * 2 + (s >> 1);   // 0..31
            float4 x = L1P ? *(const float4*)&xs[mloc * ESM_STRIDE + uloc * 4]
                           : *(const float4*)&xs[uloc * 4];
            pf += x.x; pi += x.y; pc += x.z; po += x.w;
            float cold = csm[uloc * 128 + mloc];
            float cn = sigmoid_ap(pf) * cold + sigmoid_ap(pi) * tanh_ap(pc);
            csm[uloc * 128 + mloc] = cn;
            float hn = sigmoid_ap(po) * tanh_ap(cn);
            float ho = __shfl_xor_sync(0xFFFFFFFFu, hn, 2);
            if ((lane & 2) == 0) {
                const int nb = n0 + wn * 32 + nt * 8;
                houtp[(size_t)(nb >> 3) * BATCH + m] = pack_bf2(hn, ho);
            }
        }
    }
}

// ---------------- L1 phase: K2=128 (2 chunks) + embW prefetch ----------------
template <bool ZERO>
__device__ __forceinline__ void phase_L1(
    const uint32_t* __restrict__ Ws, uint32_t* __restrict__ Ar,
    float* __restrict__ csm, float* __restrict__ esm,
    const uint32_t* __restrict__ A0,     // h1(t-1) + m0
    uint32_t* __restrict__ houtp,
    const int* __restrict__ tokens, int t, int m0, int n0)
{
    const int tid  = threadIdx.x;
    const int lane = tid & 31;
    const int wid  = tid >> 5;
    const int s    = lane & 3;
    const int g    = lane >> 2;
    const int cm0  = ((wid & 3) * 32 + g) ^ (8 * s);
    const int cb   = ((wid >> 2) * 32 + g * 4) ^ (8 * s);

    float acc[2][4][4] = {};

    if (ZERO) {
        stage_emb(esm, tokens, t, m0, n0, tid);
        cp_commit();
        cp_wait0();
        __syncthreads();
    } else {
        stage_A(Ar, A0, tid);                                   cp_commit();   // g1
        stage_A(Ar + KC2 * 128, A0 + (size_t)64 * BATCH, tid);  cp_commit();   // g2
        stage_emb(esm, tokens, t, m0, n0, tid);                 cp_commit();   // g3
        cp_wait2();  __syncthreads();          // g1 done
        compute_chunk(Ar, Ws, s, cb, cm0, acc);
        cp_wait1();  __syncthreads();          // g2 done
        compute_chunk(Ar + KC2 * 128, Ws + KC2 * 128, s, cb, cm0, acc);
        cp_wait0();  __syncthreads();          // emb done
    }
    epilogue<true>(acc, csm, esm, houtp, m0, n0);
}

// ---------------- L2 phase: h1-half first, peer wait hidden after chunk 0 ----------------
__device__ __forceinline__ void phase_L2(
    const uint32_t* __restrict__ Ws,     // rows permuted: 0..127 = W2 h1-part
    uint32_t* __restrict__ Ar,
    float* __restrict__ csm, const float* __restrict__ bsm,
    const uint32_t* __restrict__ H2,     // h2(t-1) + m0
    const uint32_t* __restrict__ H1,     // h1(t) + m0
    uint32_t* __restrict__ houtp,
    unsigned* __restrict__ l2c, int t, int m0, int n0)
{
    const int tid  = threadIdx.x;
    const int lane = tid & 31;
    const int wid  = tid >> 5;
    const int s    = lane & 3;
    const int g    = lane >> 2;
    const int cm0  = ((wid & 3) * 32 + g) ^ (8 * s);
    const int cb   = ((wid >> 2) * 32 + g * 4) ^ (8 * s);

    uint32_t* Ar1 = Ar + KC2 * 128;

    float acc[2][4][4] = {};

    stage_A(Ar,  H1, tid);                            cp_commit();  // g1: h1 rows 0..63
    stage_A(Ar1, H1 + (size_t)64 * BATCH, tid);       cp_commit();  // g2: h1 rows 64..127
    cp_wait1();  __syncthreads();                     // g1 done
    compute_chunk(Ar, Ws, s, cb, cm0, acc);           // h1 chunk 0

    // peer h2(t-1) wait — overlapped with the h1 compute above
    if (t > 0) cls_wait(l2c, 8u * t);
    else       __syncthreads();

    stage_A(Ar, H2, tid);                             cp_commit();  // g3: h2 rows 0..63
    cp_wait1();  __syncthreads();                     // g2 done
    compute_chunk(Ar1, Ws + KC2 * 128, s, cb, cm0, acc);  // h1 chunk 1
    __syncthreads();                                  // protect Ar1 overwrite
    stage_A(Ar1, H2 + (size_t)64 * BATCH, tid);       cp_commit();  // g4: h2 rows 64..127
    cp_wait1();  __syncthreads();                     // g3 done
    compute_chunk(Ar, Ws + 2 * KC2 * 128, s, cb, cm0, acc);   // h2 chunk 0
    cp_wait0();  __syncthreads();                     // g4 done
    compute_chunk(Ar1, Ws + 3 * KC2 * 128, s, cb, cm0, acc);  // h2 chunk 1

    epilogue<false>(acc, csm, bsm, houtp, m0, n0);
}

// ---------------- persistent kernel ----------------
__global__ __launch_bounds__(NTHR, 1) void lstm_persistent(
    const int* __restrict__ tokens,
    const float* __restrict__ w_out, const float* __restrict__ b_out,
    float* __restrict__ out)
{
    extern __shared__ __align__(16) uint32_t smem[];

    const int cta  = blockIdx.x;
    const bool L2G = (cta < 64);
    const int n0   = (cta & 7) * 128;
    const int mcls = (cta >> 3) & 7;
    const int m0   = mcls * 128;
    const int tid  = threadIdx.x;

    const int wrows = L2G ? 256 : 128;
    uint32_t* Ws  = smem;
    uint32_t* Ar  = smem + wrows * 128;
    float*    csm = (float*)(Ar + AR_U32);
    float*    bsm = csm + CS_U32;
    float*    esm = bsm + 128;
    unsigned* l1c = &g_l1_done[mcls * 32];
    unsigned* l2c = &g_l2_done[mcls * 32];

    // one-time: resident weights (packed + swizzled; L2 rows rotated by 128)
    for (int idx = tid; idx < wrows * 128; idx += NTHR) {
        int k2 = idx >> 7;
        int nl = idx & 127;
        int wn = nl >> 5;
        int r  = nl & 31;
        int g  = r & 7;
        int q  = r >> 3;
        int dst = k2 * 128 + (((wn << 5) + (g << 2)) ^ ((k2 & 3) << 3)) + q;
        uint32_t v = L2G ? g_W2p[(size_t)((k2 + 128) & 255) * NG + n0 + nl]
                         : g_W1hp[(size_t)k2 * NG + n0 + nl];
        Ws[dst] = v;
    }
    for (int idx = tid; idx < CS_U32; idx += NTHR) csm[idx] = 0.0f;
    if (tid < 128) bsm[tid] = g_b2[n0 + tid];
    __syncthreads();

    if (!L2G) {
        // L1 chain: free-running (h1 ring of 4)
        phase_L1<true>(Ws, Ar, csm, esm, g_h1p[0] + m0, g_h1p[0], tokens, 0, m0, n0);
        cls_signal(l1c);
        for (int t = 1; t < TSTEPS; t++) {
            cls_wait(l1c, 8u * t);                    // peers' h1(t-1)
            if (t >= 4) cls_wait(l2c, 8u * (t - 3));  // ring anti-overwrite
            phase_L1<false>(Ws, Ar, csm, esm, g_h1p[(t - 1) & 3] + m0,
                            g_h1p[t & 3], tokens, t, m0, n0);
            cls_signal(l1c);
        }
    } else {
        // L2 chain: the critical path
        for (int t = 0; t < TSTEPS; t++) {
            cls_wait(l1c, 8u * (t + 1));              // h1(t) ready
            phase_L2(Ws, Ar, csm, bsm,
                     g_h2p[t & 1] + m0, g_h1p[t & 3] + m0,
                     g_h2p[(t + 1) & 1], l2c, t, m0, n0);
            cls_signal(l2c);
        }
    }

    grid_barrier();

    // final dense + sigmoid; h2(79) packed in g_h2p[0]
    int gw   = cta * (NTHR / 32) + (tid >> 5);
    int lane = tid & 31;
    if (gw < BATCH / 32) {
        int bb = gw * 32 + lane;
        float s = 0.0f;
        const uint32_t* h = g_h2p[0];
        #pragma unroll 8
        for (int u2 = 0; u2 < UDIM / 2; u2++) {
            uint32_t v = h[(size_t)u2 * BATCH + bb];
            float lo = __bfloat162float(__ushort_as_bfloat16((unsigned short)(v & 0xFFFF)));
            float hi = __bfloat162float(__ushort_as_bfloat16((unsigned short)(v >> 16)));
            s += lo * w_out[2 * u2] + hi * w_out[2 * u2 + 1];
        }
        out[bb] = 1.0f / (1.0f + expf(-(s + b_out[0])));
    }
}

// ---------------- launch ----------------
extern "C" void kernel_launch(void* const* d_in, const int* in_sizes, int n_in,
                              void* d_out, int out_size)
{
    const int*   tokens = (const int*)  d_in[0];
    const float* emb    = (const float*)d_in[1];
    const float* wf1 = (const float*)d_in[2];  const float* bf1 = (const float*)d_in[3];
    const float* wi1 = (const float*)d_in[4];  const float* bi1 = (const float*)d_in[5];
    const float* wc1 = (const float*)d_in[6];  const float* bc1 = (const float*)d_in[7];
    const float* wo1 = (const float*)d_in[8];  const float* bo1 = (const float*)d_in[9];
    const float* wf2 = (const float*)d_in[10]; const float* bf2 = (const float*)d_in[11];
    const float* wi2 = (const float*)d_in[12]; const float* bi2 = (const float*)d_in[13];
    const float* wc2 = (const float*)d_in[14]; const float* bc2 = (const float*)d_in[15];
    const float* wo2 = (const float*)d_in[16]; const float* bo2 = (const float*)d_in[17];
    const float* w_out = (const float*)d_in[18];
    const float* b_out = (const float*)d_in[19];
    float* out = (float*)d_out;

    static int smem_set = 0;
    if (!smem_set) {
        cudaFuncSetAttribute(lstm_persistent,
                             cudaFuncAttributeMaxDynamicSharedMemorySize, SMEM_BYTES);
        smem_set = 1;
    }

    const int TOT = 384 * NG + EDIM * NG + 2 * NG;
    pack_kernel<<<(TOT + 255) / 256, 256>>>(wf1, bf1, wi1, bi1, wc1, bc1, wo1, bo1,
                                            wf2, bf2, wi2, bi2, wc2, bc2, wo2, bo2);
    zero_kernel<<<(UDIM / 2 * BATCH + 255) / 256, 256>>>();

    embw_kernel<<<dim3(NG / 64, (VOCAB + 63) / 64), 256>>>(emb);

    lstm_persistent<<<GRID_CTAS, NTHR, SMEM_BYTES>>>(tokens, w_out, b_out, out);
}